// round 8
// baseline (speedup 1.0000x reference)
#include <cuda_runtime.h>
#include <cuda_fp16.h>
#include <math.h>
#include <stdint.h>

#define BB 64
#define SQ 320
#define NCV 256
#define DM 256
#define HIDN 1024
#define NHEADS 8
#define NDEPTH 6
#define WSQ 1089

// ---------------- device scratch ----------------
__device__ float g_x[(size_t)BB * SQ * DM];
__device__ float g_ln[(size_t)BB * SQ * DM];     // final LN fp32 (gate 'extra')
__device__ float g_hcv[(size_t)BB * NCV * DM];

// fp16 activation buffers
__device__ __half g_lnh[(size_t)BB * SQ * DM];
__device__ __half g_qkvh[(size_t)BB * SQ * 3 * DM];
__device__ __half g_ath[(size_t)BB * SQ * DM];
__device__ __half g_h1h[(size_t)BB * SQ * HIDN];
__device__ __half g_cth[(size_t)BB * NCV * 2 * DM];
__device__ __half g_pth[(size_t)BB * 64 * 768];

// fp16 weights (one pool, fixed offsets)
#define WOFF_QKV   0u
#define WOFF_WO    1179648u
#define WOFF_W1    1572864u
#define WOFF_W2    3145728u
#define WOFF_PW    4718592u
#define WOFF_GW    4915200u
#define WPOOL_N    5046272u
__device__ __half g_wh[WPOOL_N];

// ---------------- helpers ----------------
__device__ __forceinline__ float pos2d_val(int yy, int xx, int d) {
    int dd = d & 127;
    int i = dd >> 1;
    float freq = expf((float)(2 * i) * (-0.07195578415606394f));
    float coord = (d < 128) ? (float)yy : (float)xx;
    float ang = coord * freq;
    return (d & 1) ? cosf(ang) : sinf(ang);
}

__device__ __forceinline__ float gelu_exact(float v) {
    return 0.5f * v * (1.0f + erff(v * 0.70710678118654752f));
}

__device__ __forceinline__ uint32_t smem_u32(const void* p) {
    uint32_t a;
    asm("{ .reg .u64 t; cvta.to.shared.u64 t, %1; cvt.u32.u64 %0, t; }" : "=r"(a) : "l"(p));
    return a;
}

__device__ __forceinline__ void cp16(uint32_t dst, const void* src) {
    asm volatile("cp.async.cg.shared.global [%0], [%1], 16;" :: "r"(dst), "l"(src));
}

__device__ __forceinline__ void ldsm4(uint32_t* r, uint32_t addr) {
    asm volatile("ldmatrix.sync.aligned.m8n8.x4.shared.b16 {%0,%1,%2,%3}, [%4];"
                 : "=r"(r[0]), "=r"(r[1]), "=r"(r[2]), "=r"(r[3]) : "r"(addr));
}

__device__ __forceinline__ void ldsm4t(uint32_t* r, uint32_t addr) {
    asm volatile("ldmatrix.sync.aligned.m8n8.x4.trans.shared.b16 {%0,%1,%2,%3}, [%4];"
                 : "=r"(r[0]), "=r"(r[1]), "=r"(r[2]), "=r"(r[3]) : "r"(addr));
}

__device__ __forceinline__ void mma16816(float* c, const uint32_t* a, const uint32_t* b) {
    asm volatile(
        "mma.sync.aligned.m16n8k16.row.col.f32.f16.f16.f32 "
        "{%0,%1,%2,%3}, {%4,%5,%6,%7}, {%8,%9}, {%0,%1,%2,%3};\n"
        : "+f"(c[0]), "+f"(c[1]), "+f"(c[2]), "+f"(c[3])
        : "r"(a[0]), "r"(a[1]), "r"(a[2]), "r"(a[3]), "r"(b[0]), "r"(b[1]));
}

// ---------------- weight fp32 -> fp16 ----------------
__global__ void __launch_bounds__(256) wcvt_k(const float* __restrict__ in,
                                              __half* __restrict__ h) {
    int i = blockIdx.x * 256 + threadIdx.x;
    float4 v = ((const float4*)in)[i];
    __half2* hp = (__half2*)(h + (size_t)i * 4);
    hp[0] = __floats2half2_rn(v.x, v.y);
    hp[1] = __floats2half2_rn(v.z, v.w);
}

// ---------------- embed (also fills cth low half) / im2col ----------------
__global__ void __launch_bounds__(256) embed_k(const float* __restrict__ h_map,
                                               const int* __restrict__ idx,
                                               float* __restrict__ hcv,
                                               __half* __restrict__ cth,
                                               float* __restrict__ x) {
    int gid = blockIdx.x * 256 + threadIdx.x;
    int d = gid & 255;
    int n = (gid >> 8) & 255;
    int b = gid >> 16;
    int p = idx[n];
    float h = h_map[((size_t)b * WSQ + p) * DM + d];
    hcv[gid] = h;
    cth[((size_t)(b * 256 + n)) * 512 + d] = __float2half_rn(h);
    x[((size_t)(b * SQ + n)) * DM + d] = h + pos2d_val(p / 33, p % 33, d);
}

__global__ void __launch_bounds__(256) im2col_k(const float* __restrict__ frame,
                                                __half* __restrict__ ph) {
    int gid = blockIdx.x * 256 + threadIdx.x;
    int k = gid % 768;
    int m = gid / 768;
    int c = k >> 8;
    int r = (k >> 4) & 15;
    int q = k & 15;
    int t = m & 63, b = m >> 6;
    int yy = (t >> 3) * 16 + r;
    int xx = (t & 7) * 16 + q;
    ph[gid] = __float2half_rn(frame[(((size_t)b * 3 + c) * 128 + yy) * 128 + xx]);
}

// ---------------- LayerNorm (entry only): x -> lnh ----------------
__global__ void __launch_bounds__(256) ln_k(const float* __restrict__ x,
                                            __half* __restrict__ yh,
                                            const float* __restrict__ gam,
                                            const float* __restrict__ bet) {
    int warp = threadIdx.x >> 5;
    int lane = threadIdx.x & 31;
    int tok = blockIdx.x * 8 + warp;
    const float* xp = x + (size_t)tok * DM;
    float v[8];
    float sum = 0.f, sq = 0.f;
#pragma unroll
    for (int i = 0; i < 8; i++) {
        v[i] = xp[lane + 32 * i];
        sum += v[i];
        sq += v[i] * v[i];
    }
#pragma unroll
    for (int off = 16; off; off >>= 1) {
        sum += __shfl_xor_sync(0xffffffffu, sum, off);
        sq  += __shfl_xor_sync(0xffffffffu, sq, off);
    }
    float mu = sum * (1.0f / 256.0f);
    float var = sq * (1.0f / 256.0f) - mu * mu;
    float inv = rsqrtf(var + 1e-5f);
#pragma unroll
    for (int i = 0; i < 8; i++) {
        int d = lane + 32 * i;
        yh[(size_t)tok * DM + d] = __float2half_rn((v[i] - mu) * inv * gam[d] + bet[d]);
    }
}

// ================= fused flash attention (mma.sync fp16) =================
#define ATT_RS 80u
#define ATT_TEN (320u * ATT_RS)
#define ATT_SMEM (3u * ATT_TEN)

__global__ void __launch_bounds__(320) attn_fa_k(const __half* __restrict__ qkvh,
                                                 __half* __restrict__ oh) {
    extern __shared__ char sm[];
    const uint32_t smb = smem_u32(sm);
    const int b = blockIdx.x >> 3;
    const int h = blockIdx.x & 7;
    const int tid = threadIdx.x;
    const int l = tid & 31;
    const int w = tid >> 5;

#pragma unroll
    for (int j = 0; j < 12; j++) {
        int c = j * 320 + tid;
        int tz = c / 1280;
        int rem = c - tz * 1280;
        int r = rem >> 2;
        int ch = rem & 3;
        const __half* src = qkvh + (size_t)(b * SQ + r) * 768 + tz * 256 + h * 32 + ch * 8;
        cp16(smb + (uint32_t)tz * ATT_TEN + (uint32_t)r * ATT_RS + (uint32_t)ch * 16u, src);
    }
    asm volatile("cp.async.commit_group;" ::: "memory");
    asm volatile("cp.async.wait_group 0;" ::: "memory");
    __syncthreads();

    const uint32_t smQ = smb, smK = smb + ATT_TEN, smV = smb + 2 * ATT_TEN;
    const int q0 = w * 32;

    uint32_t aq[2][2][4];
#pragma unroll
    for (int mf = 0; mf < 2; mf++)
#pragma unroll
        for (int kc = 0; kc < 2; kc++) {
            uint32_t addr = smQ +
                (uint32_t)(q0 + mf * 16 + (l & 7) + ((l >> 3) & 1) * 8) * ATT_RS +
                (uint32_t)(kc * 2 + (l >> 4)) * 16u;
            ldsm4(aq[mf][kc], addr);
        }

    float mrow[2][2] = {{-1e30f, -1e30f}, {-1e30f, -1e30f}};
    float lrow[2][2] = {{0.f, 0.f}, {0.f, 0.f}};
    float acc_o[2][4][4];
#pragma unroll
    for (int mf = 0; mf < 2; mf++)
#pragma unroll
        for (int db = 0; db < 4; db++)
#pragma unroll
            for (int q = 0; q < 4; q++) acc_o[mf][db][q] = 0.f;

    for (int ck = 0; ck < 320; ck += 64) {
        float s[2][8][4];
#pragma unroll
        for (int mf = 0; mf < 2; mf++)
#pragma unroll
            for (int nb = 0; nb < 8; nb++)
#pragma unroll
                for (int q = 0; q < 4; q++) s[mf][nb][q] = 0.f;

#pragma unroll
        for (int g = 0; g < 4; g++) {
#pragma unroll
            for (int ks = 0; ks < 2; ks++) {
                uint32_t bk[4];
                uint32_t addr = smK +
                    (uint32_t)(ck + g * 16 + ((l >> 4) << 3) + (l & 7)) * ATT_RS +
                    (uint32_t)(ks * 2 + ((l >> 3) & 1)) * 16u;
                ldsm4(bk, addr);
#pragma unroll
                for (int mf = 0; mf < 2; mf++) {
                    mma16816(s[mf][2 * g],     aq[mf][ks], bk);
                    mma16816(s[mf][2 * g + 1], aq[mf][ks], bk + 2);
                }
            }
        }

        uint32_t ap[2][4][4];
#pragma unroll
        for (int mf = 0; mf < 2; mf++) {
#pragma unroll
            for (int hh = 0; hh < 2; hh++) {
                float mx = -1e30f;
#pragma unroll
                for (int nb = 0; nb < 8; nb++) {
                    mx = fmaxf(mx, fmaxf(s[mf][nb][hh * 2], s[mf][nb][hh * 2 + 1]));
                }
                mx = fmaxf(mx, __shfl_xor_sync(0xffffffffu, mx, 1));
                mx = fmaxf(mx, __shfl_xor_sync(0xffffffffu, mx, 2));
                float mnew = fmaxf(mrow[mf][hh], mx);
                float corr = __expf(mrow[mf][hh] - mnew);
                mrow[mf][hh] = mnew;
                float lsum = 0.f;
#pragma unroll
                for (int nb = 0; nb < 8; nb++) {
                    float p0 = __expf(s[mf][nb][hh * 2]     - mnew);
                    float p1 = __expf(s[mf][nb][hh * 2 + 1] - mnew);
                    s[mf][nb][hh * 2] = p0;
                    s[mf][nb][hh * 2 + 1] = p1;
                    lsum += p0 + p1;
                }
                lsum += __shfl_xor_sync(0xffffffffu, lsum, 1);
                lsum += __shfl_xor_sync(0xffffffffu, lsum, 2);
                lrow[mf][hh] = lrow[mf][hh] * corr + lsum;
#pragma unroll
                for (int db = 0; db < 4; db++) {
                    acc_o[mf][db][hh * 2]     *= corr;
                    acc_o[mf][db][hh * 2 + 1] *= corr;
                }
            }
#pragma unroll
            for (int g = 0; g < 4; g++) {
                __half2 h0 = __floats2half2_rn(s[mf][2 * g][0],     s[mf][2 * g][1]);
                __half2 h1 = __floats2half2_rn(s[mf][2 * g][2],     s[mf][2 * g][3]);
                __half2 h2 = __floats2half2_rn(s[mf][2 * g + 1][0], s[mf][2 * g + 1][1]);
                __half2 h3 = __floats2half2_rn(s[mf][2 * g + 1][2], s[mf][2 * g + 1][3]);
                ap[mf][g][0] = *(uint32_t*)&h0;
                ap[mf][g][1] = *(uint32_t*)&h1;
                ap[mf][g][2] = *(uint32_t*)&h2;
                ap[mf][g][3] = *(uint32_t*)&h3;
            }
        }

#pragma unroll
        for (int g = 0; g < 4; g++) {
#pragma unroll
            for (int dd = 0; dd < 2; dd++) {
                uint32_t bv[4];
                uint32_t addr = smV +
                    (uint32_t)(ck + g * 16 + ((l >> 3) & 1) * 8 + (l & 7)) * ATT_RS +
                    (uint32_t)(dd * 2 + (l >> 4)) * 16u;
                ldsm4t(bv, addr);
#pragma unroll
                for (int mf = 0; mf < 2; mf++) {
                    mma16816(acc_o[mf][dd * 2],     ap[mf][g], bv);
                    mma16816(acc_o[mf][dd * 2 + 1], ap[mf][g], bv + 2);
                }
            }
        }
    }

#pragma unroll
    for (int mf = 0; mf < 2; mf++) {
#pragma unroll
        for (int hh = 0; hh < 2; hh++) {
            float inv = 1.f / lrow[mf][hh];
            int tok = q0 + mf * 16 + (l >> 2) + hh * 8;
            __half* op = oh + (size_t)(b * SQ + tok) * DM + h * 32 + 2 * (l & 3);
#pragma unroll
            for (int db = 0; db < 4; db++) {
                __half2 r = __floats2half2_rn(acc_o[mf][db][hh * 2] * inv,
                                              acc_o[mf][db][hh * 2 + 1] * inv);
                *(__half2*)(op + db * 8) = r;
            }
        }
    }
}

// ================= HMMA fp16 pipelined GEMM (128x128 tile) =================
enum { EPL_GELU = 2, EPL_IMGTOK = 3, EPL_GATE = 4, EPL_QKVH = 5 };

#define STG_B 32768u
#define GSMEM_BYTES (3u * STG_B)

template <int MODE>
__device__ __forceinline__ void epi_store2(
    float* __restrict__ out, __half* __restrict__ outh,
    int N, int row, int col, float vx, float vy,
    const float* __restrict__ bias, const float* __restrict__ res,
    const float* __restrict__ extra, const int* __restrict__ idx) {
    float2 bb = *(const float2*)(bias + col);
    vx += bb.x;
    vy += bb.y;
    if (MODE == EPL_GELU) {
        *(__half2*)&outh[(size_t)row * N + col] =
            __floats2half2_rn(gelu_exact(vx), gelu_exact(vy));
    } else if (MODE == EPL_QKVH) {
        float sc = (col < 256) ? 0.17677669529663687f : 1.0f;
        *(__half2*)&outh[(size_t)row * N + col] = __floats2half2_rn(vx * sc, vy * sc);
    } else if (MODE == EPL_IMGTOK) {
        int b = row >> 6, tt = row & 63;
        int yy = tt >> 3, xx = tt & 7;
        vx += pos2d_val(yy, xx, col);
        vy += pos2d_val(yy, xx, col + 1);
        *(float2*)&out[((size_t)(b * SQ + NCV + tt)) * DM + col] = make_float2(vx, vy);
    } else {  // EPL_GATE
        int b = row >> 8, n = row & 255;
        int p = idx[n];
        float2 hc = *(const float2*)&res[(size_t)row * DM + col];
        float2 hn = *(const float2*)&extra[((size_t)(b * SQ + n)) * DM + col];
        float g0 = 1.f / (1.f + expf(-vx));
        float g1 = 1.f / (1.f + expf(-vy));
        float2 r;
        r.x = hc.x + g0 * (hn.x - hc.x);
        r.y = hc.y + g1 * (hn.y - hc.y);
        *(float2*)&out[((size_t)b * WSQ + p) * DM + col] = r;
    }
}

template <int MODE>
__global__ void __launch_bounds__(256) mma_gemm_k(
    const __half* __restrict__ Ah, const __half* __restrict__ Bh,
    const float* __restrict__ bias, float* __restrict__ out,
    __half* __restrict__ outh,
    int M, int N, int K,
    const float* __restrict__ res, const float* __restrict__ extra,
    const int* __restrict__ idx) {
    extern __shared__ char sm[];
    const uint32_t smb = smem_u32(sm);
    const int tid = threadIdx.x;
    const int lane = tid & 31;
    const int w = tid >> 5;
    const int wm = w >> 1;
    const int wn = w & 1;
    const int m0 = blockIdx.y * 128;
    const int n0 = blockIdx.x * 128;

    float acc[2][8][4];
#pragma unroll
    for (int i = 0; i < 2; i++)
#pragma unroll
        for (int j = 0; j < 8; j++)
#pragma unroll
            for (int q = 0; q < 4; q++) acc[i][j][q] = 0.f;

    const int nkt = K >> 6;

    int crow[4], ck8[4];
    size_t asrc[4], bsrc[4];
    uint32_t coff[4];
#pragma unroll
    for (int j = 0; j < 4; j++) {
        int c = tid + 256 * j;
        crow[j] = c >> 3;
        ck8[j] = c & 7;
        coff[j] = (uint32_t)crow[j] * 128u + (uint32_t)((ck8[j] ^ (crow[j] & 7)) << 4);
        asrc[j] = (size_t)(m0 + crow[j]) * K + ck8[j] * 8;
        bsrc[j] = (size_t)(n0 + crow[j]) * K + ck8[j] * 8;
    }

#define ISSUE_STAGE(kt)                                                        \
    do {                                                                       \
        const int kk0 = (kt) << 6;                                             \
        const uint32_t sb = smb + (uint32_t)((kt) % 3) * STG_B;                \
        _Pragma("unroll") for (int j = 0; j < 4; j++) {                        \
            cp16(sb + coff[j],          Ah + asrc[j] + kk0);                   \
            cp16(sb + 16384u + coff[j], Bh + bsrc[j] + kk0);                   \
        }                                                                      \
        asm volatile("cp.async.commit_group;" ::: "memory");                   \
    } while (0)

    ISSUE_STAGE(0);
    ISSUE_STAGE(1);

    const uint32_t rowAb[2] = {
        (uint32_t)(wm * 32 + 0  + (lane & 7) + ((lane >> 3) & 1) * 8) * 128u,
        (uint32_t)(wm * 32 + 16 + (lane & 7) + ((lane >> 3) & 1) * 8) * 128u};
    const int a_k8add = lane >> 4;
    uint32_t rowBb[4];
#pragma unroll
    for (int nfp = 0; nfp < 4; nfp++)
        rowBb[nfp] = (uint32_t)(wn * 64 + nfp * 16 + ((lane >> 4) << 3) + (lane & 7)) * 128u;
    const int b_k8add = (lane >> 3) & 1;
    const uint32_t swz = (uint32_t)(lane & 7);

    for (int kt = 0; kt < nkt; kt++) {
        if (kt + 1 < nkt) {
            asm volatile("cp.async.wait_group 1;" ::: "memory");
        } else {
            asm volatile("cp.async.wait_group 0;" ::: "memory");
        }
        __syncthreads();
        if (kt + 2 < nkt) ISSUE_STAGE(kt + 2);

        const uint32_t sb = smb + (uint32_t)(kt % 3) * STG_B;
#pragma unroll
        for (int ks = 0; ks < 4; ks++) {
            uint32_t ah[2][4];
#pragma unroll
            for (int mf = 0; mf < 2; mf++) {
                uint32_t off = rowAb[mf] +
                    ((((uint32_t)(ks * 2 + a_k8add)) ^ swz) << 4);
                ldsm4(ah[mf], sb + off);
            }
#pragma unroll
            for (int nfp = 0; nfp < 4; nfp++) {
                uint32_t off = rowBb[nfp] +
                    ((((uint32_t)(ks * 2 + b_k8add)) ^ swz) << 4);
                uint32_t bh[4];
                ldsm4(bh, sb + 16384u + off);
#pragma unroll
                for (int mf = 0; mf < 2; mf++) {
                    mma16816(acc[mf][2 * nfp],     ah[mf], bh);
                    mma16816(acc[mf][2 * nfp + 1], ah[mf], bh + 2);
                }
            }
        }
    }
#undef ISSUE_STAGE

#pragma unroll
    for (int mf = 0; mf < 2; mf++) {
        int row = m0 + wm * 32 + mf * 16 + (lane >> 2);
#pragma unroll
        for (int nf = 0; nf < 8; nf++) {
            int col = n0 + wn * 64 + nf * 8 + (lane & 3) * 2;
            epi_store2<MODE>(out, outh, N, row, col,
                             acc[mf][nf][0], acc[mf][nf][1], bias, res, extra, idx);
            epi_store2<MODE>(out, outh, N, row + 8, col,
                             acc[mf][nf][2], acc[mf][nf][3], bias, res, extra, idx);
        }
    }
}

// ======== fused GEMM + residual + LayerNorm (128x256 tile, full rows) ========
// C = A@W^T + bias + res; if !FINAL: xout=C (fp32), lnh_out=LN(C) fp16
//                         if FINAL:  xout=LN(C) fp32 (g_ln), lnh_out=cth upper half
#define STG2_B 49152u                     // A 16KB | B 32KB per stage
#define GB_OFF  (3u * STG2_B)             // gamma/beta: 512 floats
#define STAT_OFF (GB_OFF + 2048u)         // float2 stats[4][32][2]
#define GSMEM2 (STAT_OFF + 2048u)         // 153600... (3*49152+4096 = 151552)

template <bool FINAL>
__global__ void __launch_bounds__(256) gemm_resln_k(
    const __half* __restrict__ Ah, const __half* __restrict__ Bh,
    const float* __restrict__ bias,
    const float* res,          // residual input (may alias xout)
    float* xout,               // fp32 output
    __half* __restrict__ lnh_out,
    int K,
    const float* __restrict__ gam, const float* __restrict__ bet) {
    extern __shared__ char sm[];
    const uint32_t smb = smem_u32(sm);
    const int tid = threadIdx.x;
    const int lane = tid & 31;
    const int w = tid >> 5;
    const int wm = w >> 1;   // 0..3
    const int wn = w & 1;    // 0..1, warp tile 32x128
    const int m0 = blockIdx.y * 128;

    float* gbuf = (float*)(sm + GB_OFF);
    float2* stats = (float2*)(sm + STAT_OFF);
    if (tid < 256) {
        gbuf[tid] = gam[tid];
        gbuf[256 + tid] = bet[tid];
    }

    float acc[2][16][4];
#pragma unroll
    for (int i = 0; i < 2; i++)
#pragma unroll
        for (int j = 0; j < 16; j++)
#pragma unroll
            for (int q = 0; q < 4; q++) acc[i][j][q] = 0.f;

    const int nkt = K >> 6;

    // copy coords: A 4 chunks, B 8 chunks per thread per stage
    uint32_t coffA[4];
    size_t asrc[4];
#pragma unroll
    for (int j = 0; j < 4; j++) {
        int c = tid + 256 * j;
        int crow = c >> 3, ck8 = c & 7;
        coffA[j] = (uint32_t)crow * 128u + (uint32_t)((ck8 ^ (crow & 7)) << 4);
        asrc[j] = (size_t)(m0 + crow) * K + ck8 * 8;
    }
    uint32_t coffB[8];
    size_t bsrc[8];
#pragma unroll
    for (int j = 0; j < 8; j++) {
        int c = tid + 256 * j;
        int crow = c >> 3, ck8 = c & 7;
        coffB[j] = (uint32_t)crow * 128u + (uint32_t)((ck8 ^ (crow & 7)) << 4);
        bsrc[j] = (size_t)crow * K + ck8 * 8;
    }

#define ISSUE_STAGE2(kt)                                                       \
    do {                                                                       \
        const int kk0 = (kt) << 6;                                             \
        const uint32_t sb = smb + (uint32_t)((kt) % 3) * STG2_B;               \
        _Pragma("unroll") for (int j = 0; j < 4; j++)                          \
            cp16(sb + coffA[j], Ah + asrc[j] + kk0);                           \
        _Pragma("unroll") for (int j = 0; j < 8; j++)                          \
            cp16(sb + 16384u + coffB[j], Bh + bsrc[j] + kk0);                  \
        asm volatile("cp.async.commit_group;" ::: "memory");                   \
    } while (0)

    ISSUE_STAGE2(0);
    ISSUE_STAGE2(1);

    const uint32_t rowAb[2] = {
        (uint32_t)(wm * 32 + 0  + (lane & 7) + ((lane >> 3) & 1) * 8) * 128u,
        (uint32_t)(wm * 32 + 16 + (lane & 7) + ((lane >> 3) & 1) * 8) * 128u};
    const int a_k8add = lane >> 4;
    uint32_t rowBb[8];
#pragma unroll
    for (int nfp = 0; nfp < 8; nfp++)
        rowBb[nfp] = (uint32_t)(wn * 128 + nfp * 16 + ((lane >> 4) << 3) + (lane & 7)) * 128u;
    const int b_k8add = (lane >> 3) & 1;
    const uint32_t swz = (uint32_t)(lane & 7);

    for (int kt = 0; kt < nkt; kt++) {
        if (kt + 1 < nkt) {
            asm volatile("cp.async.wait_group 1;" ::: "memory");
        } else {
            asm volatile("cp.async.wait_group 0;" ::: "memory");
        }
        __syncthreads();
        if (kt + 2 < nkt) ISSUE_STAGE2(kt + 2);

        const uint32_t sb = smb + (uint32_t)(kt % 3) * STG2_B;
#pragma unroll
        for (int ks = 0; ks < 4; ks++) {
            uint32_t ah[2][4];
#pragma unroll
            for (int mf = 0; mf < 2; mf++) {
                uint32_t off = rowAb[mf] +
                    ((((uint32_t)(ks * 2 + a_k8add)) ^ swz) << 4);
                ldsm4(ah[mf], sb + off);
            }
#pragma unroll
            for (int nfp = 0; nfp < 8; nfp++) {
                uint32_t off = rowBb[nfp] +
                    ((((uint32_t)(ks * 2 + b_k8add)) ^ swz) << 4);
                uint32_t bh[4];
                ldsm4(bh, sb + 16384u + off);
#pragma unroll
                for (int mf = 0; mf < 2; mf++) {
                    mma16816(acc[mf][2 * nfp],     ah[mf], bh);
                    mma16816(acc[mf][2 * nfp + 1], ah[mf], bh + 2);
                }
            }
        }
    }
#undef ISSUE_STAGE2

    // ---- epilogue: acc += bias + res; row stats; LN ----
#pragma unroll
    for (int mf = 0; mf < 2; mf++) {
        const int r1 = m0 + wm * 32 + mf * 16 + (lane >> 2);
        const int r2 = r1 + 8;
        float s1 = 0.f, q1 = 0.f, s2 = 0.f, q2 = 0.f;
#pragma unroll
        for (int nf = 0; nf < 16; nf++) {
            const int col = wn * 128 + nf * 8 + (lane & 3) * 2;
            float2 bb = *(const float2*)&bias[col];
            float2 e1 = *(const float2*)&res[(size_t)r1 * DM + col];
            float2 e2 = *(const float2*)&res[(size_t)r2 * DM + col];
            acc[mf][nf][0] += bb.x + e1.x;
            acc[mf][nf][1] += bb.y + e1.y;
            acc[mf][nf][2] += bb.x + e2.x;
            acc[mf][nf][3] += bb.y + e2.y;
            s1 += acc[mf][nf][0] + acc[mf][nf][1];
            q1 += acc[mf][nf][0] * acc[mf][nf][0] + acc[mf][nf][1] * acc[mf][nf][1];
            s2 += acc[mf][nf][2] + acc[mf][nf][3];
            q2 += acc[mf][nf][2] * acc[mf][nf][2] + acc[mf][nf][3] * acc[mf][nf][3];
        }
        s1 += __shfl_xor_sync(0xffffffffu, s1, 1); q1 += __shfl_xor_sync(0xffffffffu, q1, 1);
        s1 += __shfl_xor_sync(0xffffffffu, s1, 2); q1 += __shfl_xor_sync(0xffffffffu, q1, 2);
        s2 += __shfl_xor_sync(0xffffffffu, s2, 1); q2 += __shfl_xor_sync(0xffffffffu, q2, 1);
        s2 += __shfl_xor_sync(0xffffffffu, s2, 2); q2 += __shfl_xor_sync(0xffffffffu, q2, 2);
        if ((lane & 3) == 0) {
            int lr1 = mf * 16 + (lane >> 2);
            stats[(wm * 32 + lr1) * 2 + wn] = make_float2(s1, q1);
            stats[(wm * 32 + lr1 + 8) * 2 + wn] = make_float2(s2, q2);
        }
    }
    __syncthreads();

#pragma unroll
    for (int mf = 0; mf < 2; mf++) {
        const int lr1 = wm * 32 + mf * 16 + (lane >> 2);
        const int r1 = m0 + lr1, r2 = r1 + 8;
        float2 p0 = stats[lr1 * 2], p1 = stats[lr1 * 2 + 1];
        float2 p2 = stats[(lr1 + 8) * 2], p3 = stats[(lr1 + 8) * 2 + 1];
        float mu1 = (p0.x + p1.x) * (1.0f / 256.0f);
        float iv1 = rsqrtf((p0.y + p1.y) * (1.0f / 256.0f) - mu1 * mu1 + 1e-5f);
        float mu2 = (p2.x + p3.x) * (1.0f / 256.0f);
        float iv2 = rsqrtf((p2.y + p3.y) * (1.0f / 256.0f) - mu2 * mu2 + 1e-5f);

        int b1, n1, b2, n2;
        if (FINAL) { b1 = r1 / SQ; n1 = r1 - b1 * SQ; b2 = r2 / SQ; n2 = r2 - b2 * SQ; }

#pragma unroll
        for (int nf = 0; nf < 16; nf++) {
            const int col = wn * 128 + nf * 8 + (lane & 3) * 2;
            float g0 = gbuf[col], g1 = gbuf[col + 1];
            float be0 = gbuf[256 + col], be1 = gbuf[256 + col + 1];
            float l10 = (acc[mf][nf][0] - mu1) * iv1 * g0 + be0;
            float l11 = (acc[mf][nf][1] - mu1) * iv1 * g1 + be1;
            float l20 = (acc[mf][nf][2] - mu2) * iv2 * g0 + be0;
            float l21 = (acc[mf][nf][3] - mu2) * iv2 * g1 + be1;
            if (!FINAL) {
                *(float2*)&xout[(size_t)r1 * DM + col] = make_float2(acc[mf][nf][0], acc[mf][nf][1]);
                *(float2*)&xout[(size_t)r2 * DM + col] = make_float2(acc[mf][nf][2], acc[mf][nf][3]);
                *(__half2*)&lnh_out[(size_t)r1 * DM + col] = __floats2half2_rn(l10, l11);
                *(__half2*)&lnh_out[(size_t)r2 * DM + col] = __floats2half2_rn(l20, l21);
            } else {
                *(float2*)&xout[(size_t)r1 * DM + col] = make_float2(l10, l11);
                *(float2*)&xout[(size_t)r2 * DM + col] = make_float2(l20, l21);
                if (n1 < NCV)
                    *(__half2*)&lnh_out[((size_t)(b1 * NCV + n1)) * 512 + 256 + col] =
                        __floats2half2_rn(l10, l11);
                if (n2 < NCV)
                    *(__half2*)&lnh_out[((size_t)(b2 * NCV + n2)) * 512 + 256 + col] =
                        __floats2half2_rn(l20, l21);
            }
        }
    }
}

// ---------------- host launcher ----------------
extern "C" void kernel_launch(void* const* d_in, const int* in_sizes, int n_in,
                              void* d_out, int out_size) {
    const float* h_map   = (const float*)d_in[0];
    const float* frame   = (const float*)d_in[1];
    const int*   idx     = (const int*)  d_in[2];
    const float* Wqkv    = (const float*)d_in[3];
    const float* bqkv    = (const float*)d_in[4];
    const float* Wo      = (const float*)d_in[5];
    const float* bo      = (const float*)d_in[6];
    const float* ln1g    = (const float*)d_in[7];
    const float* ln1b    = (const float*)d_in[8];
    const float* W1      = (const float*)d_in[9];
    const float* b1      = (const float*)d_in[10];
    const float* W2      = (const float*)d_in[11];
    const float* b2      = (const float*)d_in[12];
    const float* ln2g    = (const float*)d_in[13];
    const float* ln2b    = (const float*)d_in[14];
    const float* nfg     = (const float*)d_in[15];
    const float* nfb     = (const float*)d_in[16];
    const float* patch_w = (const float*)d_in[17];
    const float* patch_b = (const float*)d_in[18];
    const float* gate_w  = (const float*)d_in[19];
    const float* gate_b  = (const float*)d_in[20];
    float* out = (float*)d_out;

    float *x, *ln, *hcv;
    __half *lnh, *qkvh, *ath, *h1h, *cth, *pth, *wh;
    cudaGetSymbolAddress((void**)&x, g_x);
    cudaGetSymbolAddress((void**)&ln, g_ln);
    cudaGetSymbolAddress((void**)&hcv, g_hcv);
    cudaGetSymbolAddress((void**)&lnh, g_lnh);
    cudaGetSymbolAddress((void**)&qkvh, g_qkvh);
    cudaGetSymbolAddress((void**)&ath, g_ath);
    cudaGetSymbolAddress((void**)&h1h, g_h1h);
    cudaGetSymbolAddress((void**)&cth, g_cth);
    cudaGetSymbolAddress((void**)&pth, g_pth);
    cudaGetSymbolAddress((void**)&wh, g_wh);

    cudaFuncSetAttribute(mma_gemm_k<EPL_GELU>,   cudaFuncAttributeMaxDynamicSharedMemorySize, GSMEM_BYTES);
    cudaFuncSetAttribute(mma_gemm_k<EPL_IMGTOK>, cudaFuncAttributeMaxDynamicSharedMemorySize, GSMEM_BYTES);
    cudaFuncSetAttribute(mma_gemm_k<EPL_GATE>,   cudaFuncAttributeMaxDynamicSharedMemorySize, GSMEM_BYTES);
    cudaFuncSetAttribute(mma_gemm_k<EPL_QKVH>,   cudaFuncAttributeMaxDynamicSharedMemorySize, GSMEM_BYTES);
    cudaFuncSetAttribute(gemm_resln_k<false>,    cudaFuncAttributeMaxDynamicSharedMemorySize, GSMEM2);
    cudaFuncSetAttribute(gemm_resln_k<true>,     cudaFuncAttributeMaxDynamicSharedMemorySize, GSMEM2);
    cudaFuncSetAttribute(attn_fa_k, cudaFuncAttributeMaxDynamicSharedMemorySize, ATT_SMEM);

    // pass-through copy; gated scatter overwrites idx positions
    cudaMemcpyAsync(out, h_map, sizeof(float) * (size_t)BB * WSQ * DM,
                    cudaMemcpyDeviceToDevice, 0);

    // weight conversions
    wcvt_k<<<1179648 / 1024, 256>>>(Wqkv,    wh + WOFF_QKV);
    wcvt_k<<<393216  / 1024, 256>>>(Wo,      wh + WOFF_WO);
    wcvt_k<<<1572864 / 1024, 256>>>(W1,      wh + WOFF_W1);
    wcvt_k<<<1572864 / 1024, 256>>>(W2,      wh + WOFF_W2);
    wcvt_k<<<196608  / 1024, 256>>>(patch_w, wh + WOFF_PW);
    wcvt_k<<<131072  / 1024, 256>>>(gate_w,  wh + WOFF_GW);

    embed_k<<<16384, 256>>>(h_map, idx, hcv, cth, x);
    im2col_k<<<(4096 * 768) / 256, 256>>>(frame, pth);
    mma_gemm_k<EPL_IMGTOK><<<dim3(2, 32), 256, GSMEM_BYTES>>>(
        pth, wh + WOFF_PW, patch_b, x, nullptr,
        4096, 256, 768, nullptr, nullptr, nullptr);

    const int NTOK = BB * SQ;  // 20480

    // entry LN (layer 0 ln1)
    ln_k<<<NTOK / 8, 256>>>(x, lnh, ln1g, ln1b);

    for (int l = 0; l < NDEPTH; l++) {
        mma_gemm_k<EPL_QKVH><<<dim3(6, 160), 256, GSMEM_BYTES>>>(
            lnh, wh + WOFF_QKV + (size_t)l * 196608,
            bqkv + l * 768, nullptr, qkvh,
            NTOK, 768, 256, nullptr, nullptr, nullptr);
        attn_fa_k<<<BB * NHEADS, 320, ATT_SMEM>>>(qkvh, ath);
        // Wo + residual + LN2
        gemm_resln_k<false><<<dim3(1, 160), 256, GSMEM2>>>(
            ath, wh + WOFF_WO + (size_t)l * 65536, bo + l * 256,
            x, x, lnh, 256, ln2g + l * 256, ln2b + l * 256);
        mma_gemm_k<EPL_GELU><<<dim3(8, 160), 256, GSMEM_BYTES>>>(
            lnh, wh + WOFF_W1 + (size_t)l * 262144,
            b1 + l * 1024, nullptr, h1h,
            NTOK, 1024, 256, nullptr, nullptr, nullptr);
        // W2 + residual + LN (next ln1, or final LN)
        if (l + 1 < NDEPTH) {
            gemm_resln_k<false><<<dim3(1, 160), 256, GSMEM2>>>(
                h1h, wh + WOFF_W2 + (size_t)l * 262144, b2 + l * 256,
                x, x, lnh, 1024, ln1g + (l + 1) * 256, ln1b + (l + 1) * 256);
        } else {
            gemm_resln_k<true><<<dim3(1, 160), 256, GSMEM2>>>(
                h1h, wh + WOFF_W2 + (size_t)l * 262144, b2 + l * 256,
                x, ln, cth, 1024, nfg, nfb);
        }
    }

    // gate: A = cth (filled by embed low half + final W2 upper half)
    mma_gemm_k<EPL_GATE><<<dim3(2, 128), 256, GSMEM_BYTES>>>(
        cth, wh + WOFF_GW, gate_b, out, nullptr,
        16384, 256, 512, hcv, ln, idx);
}

// round 9
// speedup vs baseline: 1.1380x; 1.1380x over previous
#include <cuda_runtime.h>
#include <cuda_fp16.h>
#include <math.h>
#include <stdint.h>

#define BB 64
#define SQ 320
#define NCV 256
#define DM 256
#define HIDN 1024
#define NHEADS 8
#define NDEPTH 6
#define WSQ 1089

// ---------------- device scratch ----------------
__device__ float g_x[(size_t)BB * SQ * DM];
__device__ float g_ln[(size_t)BB * SQ * DM];     // final LN fp32 (gate 'extra')
__device__ float g_hcv[(size_t)BB * NCV * DM];

// fp16 activation buffers
__device__ __half g_lnh[(size_t)BB * SQ * DM];
__device__ __half g_qkvh[(size_t)BB * SQ * 3 * DM];
__device__ __half g_ath[(size_t)BB * SQ * DM];
__device__ __half g_h1h[(size_t)BB * SQ * HIDN];
__device__ __half g_cth[(size_t)BB * NCV * 2 * DM];
__device__ __half g_pth[(size_t)BB * 64 * 768];

// fp16 weights (one pool, fixed offsets, in halves)
#define WOFF_QKV   0u
#define WOFF_WO    1179648u
#define WOFF_W1    1572864u
#define WOFF_W2    3145728u
#define WOFF_PW    4718592u
#define WOFF_GW    4915200u
#define WPOOL_N    5046272u
__device__ __half g_wh[WPOOL_N];

// ---------------- helpers ----------------
__device__ __forceinline__ float pos2d_val(int yy, int xx, int d) {
    int dd = d & 127;
    int i = dd >> 1;
    float freq = expf((float)(2 * i) * (-0.07195578415606394f));
    float coord = (d < 128) ? (float)yy : (float)xx;
    float ang = coord * freq;
    return (d & 1) ? cosf(ang) : sinf(ang);
}

__device__ __forceinline__ float gelu_exact(float v) {
    return 0.5f * v * (1.0f + erff(v * 0.70710678118654752f));
}

__device__ __forceinline__ uint32_t smem_u32(const void* p) {
    uint32_t a;
    asm("{ .reg .u64 t; cvta.to.shared.u64 t, %1; cvt.u32.u64 %0, t; }" : "=r"(a) : "l"(p));
    return a;
}

__device__ __forceinline__ void cp16(uint32_t dst, const void* src) {
    asm volatile("cp.async.cg.shared.global [%0], [%1], 16;" :: "r"(dst), "l"(src));
}

__device__ __forceinline__ void ldsm4(uint32_t* r, uint32_t addr) {
    asm volatile("ldmatrix.sync.aligned.m8n8.x4.shared.b16 {%0,%1,%2,%3}, [%4];"
                 : "=r"(r[0]), "=r"(r[1]), "=r"(r[2]), "=r"(r[3]) : "r"(addr));
}

__device__ __forceinline__ void ldsm4t(uint32_t* r, uint32_t addr) {
    asm volatile("ldmatrix.sync.aligned.m8n8.x4.trans.shared.b16 {%0,%1,%2,%3}, [%4];"
                 : "=r"(r[0]), "=r"(r[1]), "=r"(r[2]), "=r"(r[3]) : "r"(addr));
}

__device__ __forceinline__ void mma16816(float* c, const uint32_t* a, const uint32_t* b) {
    asm volatile(
        "mma.sync.aligned.m16n8k16.row.col.f32.f16.f16.f32 "
        "{%0,%1,%2,%3}, {%4,%5,%6,%7}, {%8,%9}, {%0,%1,%2,%3};\n"
        : "+f"(c[0]), "+f"(c[1]), "+f"(c[2]), "+f"(c[3])
        : "r"(a[0]), "r"(a[1]), "r"(a[2]), "r"(a[3]), "r"(b[0]), "r"(b[1]));
}

// ---------------- ALL weights fp32 -> fp16, one launch ----------------
// float4 units: QKV [0,294912) WO [294912,393216) W1 [393216,786432)
// W2 [786432,1179648) PW [1179648,1228800) GW [1228800,1261568)
__global__ void __launch_bounds__(256) wcvt_all_k(
    const float* __restrict__ s0, const float* __restrict__ s1,
    const float* __restrict__ s2, const float* __restrict__ s3,
    const float* __restrict__ s4, const float* __restrict__ s5,
    __half* __restrict__ h) {
    int i = blockIdx.x * 256 + threadIdx.x;
    const float* src;
    int base;
    if (i < 393216) {
        if (i < 294912) { src = s0; base = 0; }
        else            { src = s1; base = 294912; }
    } else if (i < 1179648) {
        if (i < 786432) { src = s2; base = 393216; }
        else            { src = s3; base = 786432; }
    } else {
        if (i < 1228800) { src = s4; base = 1179648; }
        else             { src = s5; base = 1228800; }
    }
    float4 v = ((const float4*)src)[i - base];
    __half2* hp = (__half2*)(h + (size_t)i * 4);
    hp[0] = __floats2half2_rn(v.x, v.y);
    hp[1] = __floats2half2_rn(v.z, v.w);
}

// ---------------- embed (fills cth low half) / im2col ----------------
__global__ void __launch_bounds__(256) embed_k(const float* __restrict__ h_map,
                                               const int* __restrict__ idx,
                                               float* __restrict__ hcv,
                                               __half* __restrict__ cth,
                                               float* __restrict__ x) {
    int gid = blockIdx.x * 256 + threadIdx.x;
    int d = gid & 255;
    int n = (gid >> 8) & 255;
    int b = gid >> 16;
    int p = idx[n];
    float h = h_map[((size_t)b * WSQ + p) * DM + d];
    hcv[gid] = h;
    cth[((size_t)(b * 256 + n)) * 512 + d] = __float2half_rn(h);
    x[((size_t)(b * SQ + n)) * DM + d] = h + pos2d_val(p / 33, p % 33, d);
}

__global__ void __launch_bounds__(256) im2col_k(const float* __restrict__ frame,
                                                __half* __restrict__ ph) {
    int gid = blockIdx.x * 256 + threadIdx.x;
    int k = gid % 768;
    int m = gid / 768;
    int c = k >> 8;
    int r = (k >> 4) & 15;
    int q = k & 15;
    int t = m & 63, b = m >> 6;
    int yy = (t >> 3) * 16 + r;
    int xx = (t & 7) * 16 + q;
    ph[gid] = __float2half_rn(frame[(((size_t)b * 3 + c) * 128 + yy) * 128 + xx]);
}

// ---------------- LayerNorm: x -> lnh ----------------
__global__ void __launch_bounds__(256) ln_k(const float* __restrict__ x,
                                            __half* __restrict__ yh,
                                            const float* __restrict__ gam,
                                            const float* __restrict__ bet) {
    int warp = threadIdx.x >> 5;
    int lane = threadIdx.x & 31;
    int tok = blockIdx.x * 8 + warp;
    const float* xp = x + (size_t)tok * DM;
    float v[8];
    float sum = 0.f, sq = 0.f;
#pragma unroll
    for (int i = 0; i < 8; i++) {
        v[i] = xp[lane + 32 * i];
        sum += v[i];
        sq += v[i] * v[i];
    }
#pragma unroll
    for (int off = 16; off; off >>= 1) {
        sum += __shfl_xor_sync(0xffffffffu, sum, off);
        sq  += __shfl_xor_sync(0xffffffffu, sq, off);
    }
    float mu = sum * (1.0f / 256.0f);
    float var = sq * (1.0f / 256.0f) - mu * mu;
    float inv = rsqrtf(var + 1e-5f);
#pragma unroll
    for (int i = 0; i < 8; i++) {
        int d = lane + 32 * i;
        yh[(size_t)tok * DM + d] = __float2half_rn((v[i] - mu) * inv * gam[d] + bet[d]);
    }
}

// ---------------- final LayerNorm: x -> ln fp32 + cth upper half ----------------
__global__ void __launch_bounds__(256) lnfinal_k(const float* __restrict__ x,
                                                 float* __restrict__ y,
                                                 __half* __restrict__ cth,
                                                 const float* __restrict__ gam,
                                                 const float* __restrict__ bet) {
    int warp = threadIdx.x >> 5;
    int lane = threadIdx.x & 31;
    int tok = blockIdx.x * 8 + warp;
    int b = tok / SQ;
    int n = tok - b * SQ;
    const float* xp = x + (size_t)tok * DM;
    float v[8];
    float sum = 0.f, sq = 0.f;
#pragma unroll
    for (int i = 0; i < 8; i++) {
        v[i] = xp[lane + 32 * i];
        sum += v[i];
        sq += v[i] * v[i];
    }
#pragma unroll
    for (int off = 16; off; off >>= 1) {
        sum += __shfl_xor_sync(0xffffffffu, sum, off);
        sq  += __shfl_xor_sync(0xffffffffu, sq, off);
    }
    float mu = sum * (1.0f / 256.0f);
    float var = sq * (1.0f / 256.0f) - mu * mu;
    float inv = rsqrtf(var + 1e-5f);
#pragma unroll
    for (int i = 0; i < 8; i++) {
        int d = lane + 32 * i;
        float r = (v[i] - mu) * inv * gam[d] + bet[d];
        y[(size_t)tok * DM + d] = r;
        if (n < NCV)
            cth[((size_t)(b * NCV + n)) * 512 + 256 + d] = __float2half_rn(r);
    }
}

// ================= fused flash attention (mma.sync fp16) =================
#define ATT_RS 80u
#define ATT_TEN (320u * ATT_RS)
#define ATT_SMEM (3u * ATT_TEN)

__global__ void __launch_bounds__(320) attn_fa_k(const __half* __restrict__ qkvh,
                                                 __half* __restrict__ oh) {
    extern __shared__ char sm[];
    const uint32_t smb = smem_u32(sm);
    const int b = blockIdx.x >> 3;
    const int h = blockIdx.x & 7;
    const int tid = threadIdx.x;
    const int l = tid & 31;
    const int w = tid >> 5;

#pragma unroll
    for (int j = 0; j < 12; j++) {
        int c = j * 320 + tid;
        int tz = c / 1280;
        int rem = c - tz * 1280;
        int r = rem >> 2;
        int ch = rem & 3;
        const __half* src = qkvh + (size_t)(b * SQ + r) * 768 + tz * 256 + h * 32 + ch * 8;
        cp16(smb + (uint32_t)tz * ATT_TEN + (uint32_t)r * ATT_RS + (uint32_t)ch * 16u, src);
    }
    asm volatile("cp.async.commit_group;" ::: "memory");
    asm volatile("cp.async.wait_group 0;" ::: "memory");
    __syncthreads();

    const uint32_t smQ = smb, smK = smb + ATT_TEN, smV = smb + 2 * ATT_TEN;
    const int q0 = w * 32;

    uint32_t aq[2][2][4];
#pragma unroll
    for (int mf = 0; mf < 2; mf++)
#pragma unroll
        for (int kc = 0; kc < 2; kc++) {
            uint32_t addr = smQ +
                (uint32_t)(q0 + mf * 16 + (l & 7) + ((l >> 3) & 1) * 8) * ATT_RS +
                (uint32_t)(kc * 2 + (l >> 4)) * 16u;
            ldsm4(aq[mf][kc], addr);
        }

    float mrow[2][2] = {{-1e30f, -1e30f}, {-1e30f, -1e30f}};
    float lrow[2][2] = {{0.f, 0.f}, {0.f, 0.f}};
    float acc_o[2][4][4];
#pragma unroll
    for (int mf = 0; mf < 2; mf++)
#pragma unroll
        for (int db = 0; db < 4; db++)
#pragma unroll
            for (int q = 0; q < 4; q++) acc_o[mf][db][q] = 0.f;

    for (int ck = 0; ck < 320; ck += 64) {
        float s[2][8][4];
#pragma unroll
        for (int mf = 0; mf < 2; mf++)
#pragma unroll
            for (int nb = 0; nb < 8; nb++)
#pragma unroll
                for (int q = 0; q < 4; q++) s[mf][nb][q] = 0.f;

#pragma unroll
        for (int g = 0; g < 4; g++) {
#pragma unroll
            for (int ks = 0; ks < 2; ks++) {
                uint32_t bk[4];
                uint32_t addr = smK +
                    (uint32_t)(ck + g * 16 + ((l >> 4) << 3) + (l & 7)) * ATT_RS +
                    (uint32_t)(ks * 2 + ((l >> 3) & 1)) * 16u;
                ldsm4(bk, addr);
#pragma unroll
                for (int mf = 0; mf < 2; mf++) {
                    mma16816(s[mf][2 * g],     aq[mf][ks], bk);
                    mma16816(s[mf][2 * g + 1], aq[mf][ks], bk + 2);
                }
            }
        }

        uint32_t ap[2][4][4];
#pragma unroll
        for (int mf = 0; mf < 2; mf++) {
#pragma unroll
            for (int hh = 0; hh < 2; hh++) {
                float mx = -1e30f;
#pragma unroll
                for (int nb = 0; nb < 8; nb++) {
                    mx = fmaxf(mx, fmaxf(s[mf][nb][hh * 2], s[mf][nb][hh * 2 + 1]));
                }
                mx = fmaxf(mx, __shfl_xor_sync(0xffffffffu, mx, 1));
                mx = fmaxf(mx, __shfl_xor_sync(0xffffffffu, mx, 2));
                float mnew = fmaxf(mrow[mf][hh], mx);
                float corr = __expf(mrow[mf][hh] - mnew);
                mrow[mf][hh] = mnew;
                float lsum = 0.f;
#pragma unroll
                for (int nb = 0; nb < 8; nb++) {
                    float p0 = __expf(s[mf][nb][hh * 2]     - mnew);
                    float p1 = __expf(s[mf][nb][hh * 2 + 1] - mnew);
                    s[mf][nb][hh * 2] = p0;
                    s[mf][nb][hh * 2 + 1] = p1;
                    lsum += p0 + p1;
                }
                lsum += __shfl_xor_sync(0xffffffffu, lsum, 1);
                lsum += __shfl_xor_sync(0xffffffffu, lsum, 2);
                lrow[mf][hh] = lrow[mf][hh] * corr + lsum;
#pragma unroll
                for (int db = 0; db < 4; db++) {
                    acc_o[mf][db][hh * 2]     *= corr;
                    acc_o[mf][db][hh * 2 + 1] *= corr;
                }
            }
#pragma unroll
            for (int g = 0; g < 4; g++) {
                __half2 h0 = __floats2half2_rn(s[mf][2 * g][0],     s[mf][2 * g][1]);
                __half2 h1 = __floats2half2_rn(s[mf][2 * g][2],     s[mf][2 * g][3]);
                __half2 h2 = __floats2half2_rn(s[mf][2 * g + 1][0], s[mf][2 * g + 1][1]);
                __half2 h3 = __floats2half2_rn(s[mf][2 * g + 1][2], s[mf][2 * g + 1][3]);
                ap[mf][g][0] = *(uint32_t*)&h0;
                ap[mf][g][1] = *(uint32_t*)&h1;
                ap[mf][g][2] = *(uint32_t*)&h2;
                ap[mf][g][3] = *(uint32_t*)&h3;
            }
        }

#pragma unroll
        for (int g = 0; g < 4; g++) {
#pragma unroll
            for (int dd = 0; dd < 2; dd++) {
                uint32_t bv[4];
                uint32_t addr = smV +
                    (uint32_t)(ck + g * 16 + ((l >> 3) & 1) * 8 + (l & 7)) * ATT_RS +
                    (uint32_t)(dd * 2 + (l >> 4)) * 16u;
                ldsm4t(bv, addr);
#pragma unroll
                for (int mf = 0; mf < 2; mf++) {
                    mma16816(acc_o[mf][dd * 2],     ap[mf][g], bv);
                    mma16816(acc_o[mf][dd * 2 + 1], ap[mf][g], bv + 2);
                }
            }
        }
    }

#pragma unroll
    for (int mf = 0; mf < 2; mf++) {
#pragma unroll
        for (int hh = 0; hh < 2; hh++) {
            float inv = 1.f / lrow[mf][hh];
            int tok = q0 + mf * 16 + (l >> 2) + hh * 8;
            __half* op = oh + (size_t)(b * SQ + tok) * DM + h * 32 + 2 * (l & 3);
#pragma unroll
            for (int db = 0; db < 4; db++) {
                __half2 r = __floats2half2_rn(acc_o[mf][db][hh * 2] * inv,
                                              acc_o[mf][db][hh * 2 + 1] * inv);
                *(__half2*)(op + db * 8) = r;
            }
        }
    }
}

// ================= HMMA fp16 pipelined GEMM (128x128, 2 CTA/SM) =================
enum { EPL_PLAIN = 0, EPL_RES = 1, EPL_GELU = 2, EPL_IMGTOK = 3, EPL_GATE = 4, EPL_QKVH = 5 };

#define STG_B 32768u
#define GSMEM_BYTES (3u * STG_B)

template <int MODE>
__device__ __forceinline__ void epi_store2(
    float* __restrict__ out, __half* __restrict__ outh,
    int N, int row, int col, float vx, float vy,
    const float* __restrict__ bias, const float* __restrict__ res,
    const float* __restrict__ extra, const int* __restrict__ idx) {
    float2 bb = *(const float2*)(bias + col);
    vx += bb.x;
    vy += bb.y;
    if (MODE == EPL_PLAIN) {
        *(float2*)&out[(size_t)row * N + col] = make_float2(vx, vy);
    } else if (MODE == EPL_RES) {
        float2 rr = *(const float2*)&res[(size_t)row * N + col];
        *(float2*)&out[(size_t)row * N + col] = make_float2(vx + rr.x, vy + rr.y);
    } else if (MODE == EPL_GELU) {
        *(__half2*)&outh[(size_t)row * N + col] =
            __floats2half2_rn(gelu_exact(vx), gelu_exact(vy));
    } else if (MODE == EPL_QKVH) {
        float sc = (col < 256) ? 0.17677669529663687f : 1.0f;
        *(__half2*)&outh[(size_t)row * N + col] = __floats2half2_rn(vx * sc, vy * sc);
    } else if (MODE == EPL_IMGTOK) {
        int b = row >> 6, tt = row & 63;
        int yy = tt >> 3, xx = tt & 7;
        vx += pos2d_val(yy, xx, col);
        vy += pos2d_val(yy, xx, col + 1);
        *(float2*)&out[((size_t)(b * SQ + NCV + tt)) * DM + col] = make_float2(vx, vy);
    } else {  // EPL_GATE
        int b = row >> 8, n = row & 255;
        int p = idx[n];
        float2 hc = *(const float2*)&res[(size_t)row * DM + col];
        float2 hn = *(const float2*)&extra[((size_t)(b * SQ + n)) * DM + col];
        float g0 = 1.f / (1.f + expf(-vx));
        float g1 = 1.f / (1.f + expf(-vy));
        float2 r;
        r.x = hc.x + g0 * (hn.x - hc.x);
        r.y = hc.y + g1 * (hn.y - hc.y);
        *(float2*)&out[((size_t)b * WSQ + p) * DM + col] = r;
    }
}

template <int MODE>
__global__ void __launch_bounds__(256, 2) mma_gemm_k(
    const __half* __restrict__ Ah, const __half* __restrict__ Bh,
    const float* __restrict__ bias, float* __restrict__ out,
    __half* __restrict__ outh,
    int M, int N, int K,
    const float* __restrict__ res, const float* __restrict__ extra,
    const int* __restrict__ idx) {
    extern __shared__ char sm[];
    const uint32_t smb = smem_u32(sm);
    const int tid = threadIdx.x;
    const int lane = tid & 31;
    const int w = tid >> 5;
    const int wm = w >> 1;
    const int wn = w & 1;
    const int m0 = blockIdx.y * 128;
    const int n0 = blockIdx.x * 128;

    float acc[2][8][4];
#pragma unroll
    for (int i = 0; i < 2; i++)
#pragma unroll
        for (int j = 0; j < 8; j++)
#pragma unroll
            for (int q = 0; q < 4; q++) acc[i][j][q] = 0.f;

    const int nkt = K >> 6;

    // 32-bit copy offsets (element units) to keep register count <=128
    uint32_t asrc[4], bsrc[4], coff[4];
#pragma unroll
    for (int j = 0; j < 4; j++) {
        int c = tid + 256 * j;
        int crow = c >> 3;
        int ck8 = c & 7;
        coff[j] = (uint32_t)crow * 128u + (uint32_t)((ck8 ^ (crow & 7)) << 4);
        asrc[j] = (uint32_t)(m0 + crow) * (uint32_t)K + (uint32_t)(ck8 * 8);
        bsrc[j] = (uint32_t)(n0 + crow) * (uint32_t)K + (uint32_t)(ck8 * 8);
    }

#define ISSUE_STAGE(kt)                                                        \
    do {                                                                       \
        const uint32_t kk0 = (uint32_t)(kt) << 6;                              \
        const uint32_t sb = smb + (uint32_t)((kt) % 3) * STG_B;                \
        _Pragma("unroll") for (int j = 0; j < 4; j++) {                        \
            cp16(sb + coff[j],          Ah + asrc[j] + kk0);                   \
            cp16(sb + 16384u + coff[j], Bh + bsrc[j] + kk0);                   \
        }                                                                      \
        asm volatile("cp.async.commit_group;" ::: "memory");                   \
    } while (0)

    ISSUE_STAGE(0);
    ISSUE_STAGE(1);

    const uint32_t rowAb[2] = {
        (uint32_t)(wm * 32 + 0  + (lane & 7) + ((lane >> 3) & 1) * 8) * 128u,
        (uint32_t)(wm * 32 + 16 + (lane & 7) + ((lane >> 3) & 1) * 8) * 128u};
    const int a_k8add = lane >> 4;
    uint32_t rowBb[4];
#pragma unroll
    for (int nfp = 0; nfp < 4; nfp++)
        rowBb[nfp] = (uint32_t)(wn * 64 + nfp * 16 + ((lane >> 4) << 3) + (lane & 7)) * 128u;
    const int b_k8add = (lane >> 3) & 1;
    const uint32_t swz = (uint32_t)(lane & 7);

    for (int kt = 0; kt < nkt; kt++) {
        if (kt + 1 < nkt) {
            asm volatile("cp.async.wait_group 1;" ::: "memory");
        } else {
            asm volatile("cp.async.wait_group 0;" ::: "memory");
        }
        __syncthreads();
        if (kt + 2 < nkt) ISSUE_STAGE(kt + 2);

        const uint32_t sb = smb + (uint32_t)(kt % 3) * STG_B;
#pragma unroll
        for (int ks = 0; ks < 4; ks++) {
            uint32_t ah[2][4];
#pragma unroll
            for (int mf = 0; mf < 2; mf++) {
                uint32_t off = rowAb[mf] +
                    ((((uint32_t)(ks * 2 + a_k8add)) ^ swz) << 4);
                ldsm4(ah[mf], sb + off);
            }
#pragma unroll
            for (int nfp = 0; nfp < 4; nfp++) {
                uint32_t off = rowBb[nfp] +
                    ((((uint32_t)(ks * 2 + b_k8add)) ^ swz) << 4);
                uint32_t bh[4];
                ldsm4(bh, sb + 16384u + off);
#pragma unroll
                for (int mf = 0; mf < 2; mf++) {
                    mma16816(acc[mf][2 * nfp],     ah[mf], bh);
                    mma16816(acc[mf][2 * nfp + 1], ah[mf], bh + 2);
                }
            }
        }
    }
#undef ISSUE_STAGE

#pragma unroll
    for (int mf = 0; mf < 2; mf++) {
        int row = m0 + wm * 32 + mf * 16 + (lane >> 2);
#pragma unroll
        for (int nf = 0; nf < 8; nf++) {
            int col = n0 + wn * 64 + nf * 8 + (lane & 3) * 2;
            epi_store2<MODE>(out, outh, N, row, col,
                             acc[mf][nf][0], acc[mf][nf][1], bias, res, extra, idx);
            epi_store2<MODE>(out, outh, N, row + 8, col,
                             acc[mf][nf][2], acc[mf][nf][3], bias, res, extra, idx);
        }
    }
}

// ---------------- host launcher ----------------
extern "C" void kernel_launch(void* const* d_in, const int* in_sizes, int n_in,
                              void* d_out, int out_size) {
    const float* h_map   = (const float*)d_in[0];
    const float* frame   = (const float*)d_in[1];
    const int*   idx     = (const int*)  d_in[2];
    const float* Wqkv    = (const float*)d_in[3];
    const float* bqkv    = (const float*)d_in[4];
    const float* Wo      = (const float*)d_in[5];
    const float* bo      = (const float*)d_in[6];
    const float* ln1g    = (const float*)d_in[7];
    const float* ln1b    = (const float*)d_in[8];
    const float* W1      = (const float*)d_in[9];
    const float* b1      = (const float*)d_in[10];
    const float* W2      = (const float*)d_in[11];
    const float* b2      = (const float*)d_in[12];
    const float* ln2g    = (const float*)d_in[13];
    const float* ln2b    = (const float*)d_in[14];
    const float* nfg     = (const float*)d_in[15];
    const float* nfb     = (const float*)d_in[16];
    const float* patch_w = (const float*)d_in[17];
    const float* patch_b = (const float*)d_in[18];
    const float* gate_w  = (const float*)d_in[19];
    const float* gate_b  = (const float*)d_in[20];
    float* out = (float*)d_out;

    float *x, *ln, *hcv;
    __half *lnh, *qkvh, *ath, *h1h, *cth, *pth, *wh;
    cudaGetSymbolAddress((void**)&x, g_x);
    cudaGetSymbolAddress((void**)&ln, g_ln);
    cudaGetSymbolAddress((void**)&hcv, g_hcv);
    cudaGetSymbolAddress((void**)&lnh, g_lnh);
    cudaGetSymbolAddress((void**)&qkvh, g_qkvh);
    cudaGetSymbolAddress((void**)&ath, g_ath);
    cudaGetSymbolAddress((void**)&h1h, g_h1h);
    cudaGetSymbolAddress((void**)&cth, g_cth);
    cudaGetSymbolAddress((void**)&pth, g_pth);
    cudaGetSymbolAddress((void**)&wh, g_wh);

    cudaFuncSetAttribute(mma_gemm_k<EPL_GELU>,   cudaFuncAttributeMaxDynamicSharedMemorySize, GSMEM_BYTES);
    cudaFuncSetAttribute(mma_gemm_k<EPL_IMGTOK>, cudaFuncAttributeMaxDynamicSharedMemorySize, GSMEM_BYTES);
    cudaFuncSetAttribute(mma_gemm_k<EPL_GATE>,   cudaFuncAttributeMaxDynamicSharedMemorySize, GSMEM_BYTES);
    cudaFuncSetAttribute(mma_gemm_k<EPL_QKVH>,   cudaFuncAttributeMaxDynamicSharedMemorySize, GSMEM_BYTES);
    cudaFuncSetAttribute(mma_gemm_k<EPL_RES>,    cudaFuncAttributeMaxDynamicSharedMemorySize, GSMEM_BYTES);
    cudaFuncSetAttribute(attn_fa_k, cudaFuncAttributeMaxDynamicSharedMemorySize, ATT_SMEM);

    // pass-through copy; gated scatter overwrites idx positions
    cudaMemcpyAsync(out, h_map, sizeof(float) * (size_t)BB * WSQ * DM,
                    cudaMemcpyDeviceToDevice, 0);

    // all weight conversions, single launch
    wcvt_all_k<<<1261568 / 256, 256>>>(Wqkv, Wo, W1, W2, patch_w, gate_w, wh);

    embed_k<<<16384, 256>>>(h_map, idx, hcv, cth, x);
    im2col_k<<<(4096 * 768) / 256, 256>>>(frame, pth);
    mma_gemm_k<EPL_IMGTOK><<<dim3(2, 32), 256, GSMEM_BYTES>>>(
        pth, wh + WOFF_PW, patch_b, x, nullptr,
        4096, 256, 768, nullptr, nullptr, nullptr);

    const int NTOK = BB * SQ;  // 20480
    for (int l = 0; l < NDEPTH; l++) {
        ln_k<<<NTOK / 8, 256>>>(x, lnh, ln1g + l * 256, ln1b + l * 256);
        mma_gemm_k<EPL_QKVH><<<dim3(6, 160), 256, GSMEM_BYTES>>>(
            lnh, wh + WOFF_QKV + (size_t)l * 196608,
            bqkv + l * 768, nullptr, qkvh,
            NTOK, 768, 256, nullptr, nullptr, nullptr);
        attn_fa_k<<<BB * NHEADS, 320, ATT_SMEM>>>(qkvh, ath);
        mma_gemm_k<EPL_RES><<<dim3(2, 160), 256, GSMEM_BYTES>>>(
            ath, wh + WOFF_WO + (size_t)l * 65536,
            bo + l * 256, x, nullptr,
            NTOK, 256, 256, x, nullptr, nullptr);
        ln_k<<<NTOK / 8, 256>>>(x, lnh, ln2g + l * 256, ln2b + l * 256);
        mma_gemm_k<EPL_GELU><<<dim3(8, 160), 256, GSMEM_BYTES>>>(
            lnh, wh + WOFF_W1 + (size_t)l * 262144,
            b1 + l * 1024, nullptr, h1h,
            NTOK, 1024, 256, nullptr, nullptr, nullptr);
        mma_gemm_k<EPL_RES><<<dim3(2, 160), 256, GSMEM_BYTES>>>(
            h1h, wh + WOFF_W2 + (size_t)l * 262144,
            b2 + l * 256, x, nullptr,
            NTOK, 256, 1024, x, nullptr, nullptr);
    }

    lnfinal_k<<<NTOK / 8, 256>>>(x, ln, cth, nfg, nfb);
    mma_gemm_k<EPL_GATE><<<dim3(2, 128), 256, GSMEM_BYTES>>>(
        cth, wh + WOFF_GW, gate_b, out, nullptr,
        16384, 256, 512, hcv, ln, idx);
}

// round 10
// speedup vs baseline: 1.1381x; 1.0001x over previous
#include <cuda_runtime.h>
#include <cuda_fp16.h>
#include <math.h>
#include <stdint.h>

#define BB 64
#define SQ 320
#define NCV 256
#define DM 256
#define HIDN 1024
#define NHEADS 8
#define NDEPTH 6
#define WSQ 1089

// ---------------- device scratch ----------------
__device__ float g_x[(size_t)BB * SQ * DM];
__device__ float g_ln[(size_t)BB * SQ * DM];     // final LN fp32 (gate 'extra')
__device__ float g_hcv[(size_t)BB * NCV * DM];

__device__ __half g_lnh[(size_t)BB * SQ * DM];
__device__ __half g_qkvh[(size_t)BB * SQ * 3 * DM];
__device__ __half g_ath[(size_t)BB * SQ * DM];
__device__ __half g_h1h[(size_t)BB * SQ * HIDN];
__device__ __half g_cth[(size_t)BB * NCV * 2 * DM];
__device__ __half g_pth[(size_t)BB * 64 * 768];

#define WOFF_QKV   0u
#define WOFF_WO    1179648u
#define WOFF_W1    1572864u
#define WOFF_W2    3145728u
#define WOFF_PW    4718592u
#define WOFF_GW    4915200u
#define WPOOL_N    5046272u
__device__ __half g_wh[WPOOL_N];

// ---------------- helpers ----------------
__device__ __forceinline__ float pos2d_val(int yy, int xx, int d) {
    int dd = d & 127;
    int i = dd >> 1;
    float freq = expf((float)(2 * i) * (-0.07195578415606394f));
    float coord = (d < 128) ? (float)yy : (float)xx;
    float ang = coord * freq;
    return (d & 1) ? cosf(ang) : sinf(ang);
}

__device__ __forceinline__ float gelu_exact(float v) {
    return 0.5f * v * (1.0f + erff(v * 0.70710678118654752f));
}

__device__ __forceinline__ uint32_t smem_u32(const void* p) {
    uint32_t a;
    asm("{ .reg .u64 t; cvta.to.shared.u64 t, %1; cvt.u32.u64 %0, t; }" : "=r"(a) : "l"(p));
    return a;
}

__device__ __forceinline__ void cp16(uint32_t dst, const void* src) {
    asm volatile("cp.async.cg.shared.global [%0], [%1], 16;" :: "r"(dst), "l"(src));
}

__device__ __forceinline__ void ldsm4(uint32_t* r, uint32_t addr) {
    asm volatile("ldmatrix.sync.aligned.m8n8.x4.shared.b16 {%0,%1,%2,%3}, [%4];"
                 : "=r"(r[0]), "=r"(r[1]), "=r"(r[2]), "=r"(r[3]) : "r"(addr));
}

__device__ __forceinline__ void ldsm4t(uint32_t* r, uint32_t addr) {
    asm volatile("ldmatrix.sync.aligned.m8n8.x4.trans.shared.b16 {%0,%1,%2,%3}, [%4];"
                 : "=r"(r[0]), "=r"(r[1]), "=r"(r[2]), "=r"(r[3]) : "r"(addr));
}

__device__ __forceinline__ void mma16816(float* c, const uint32_t* a, const uint32_t* b) {
    asm volatile(
        "mma.sync.aligned.m16n8k16.row.col.f32.f16.f16.f32 "
        "{%0,%1,%2,%3}, {%4,%5,%6,%7}, {%8,%9}, {%0,%1,%2,%3};\n"
        : "+f"(c[0]), "+f"(c[1]), "+f"(c[2]), "+f"(c[3])
        : "r"(a[0]), "r"(a[1]), "r"(a[2]), "r"(a[3]), "r"(b[0]), "r"(b[1]));
}

// ---------------- ALL weights fp32 -> fp16, one launch ----------------
__global__ void __launch_bounds__(256) wcvt_all_k(
    const float* __restrict__ s0, const float* __restrict__ s1,
    const float* __restrict__ s2, const float* __restrict__ s3,
    const float* __restrict__ s4, const float* __restrict__ s5,
    __half* __restrict__ h) {
    int i = blockIdx.x * 256 + threadIdx.x;
    const float* src;
    int base;
    if (i < 393216) {
        if (i < 294912) { src = s0; base = 0; }
        else            { src = s1; base = 294912; }
    } else if (i < 1179648) {
        if (i < 786432) { src = s2; base = 393216; }
        else            { src = s3; base = 786432; }
    } else {
        if (i < 1228800) { src = s4; base = 1179648; }
        else             { src = s5; base = 1228800; }
    }
    float4 v = ((const float4*)src)[i - base];
    __half2* hp = (__half2*)(h + (size_t)i * 4);
    hp[0] = __floats2half2_rn(v.x, v.y);
    hp[1] = __floats2half2_rn(v.z, v.w);
}

// ---------------- embed / im2col ----------------
__global__ void __launch_bounds__(256) embed_k(const float* __restrict__ h_map,
                                               const int* __restrict__ idx,
                                               float* __restrict__ hcv,
                                               __half* __restrict__ cth,
                                               float* __restrict__ x) {
    int gid = blockIdx.x * 256 + threadIdx.x;
    int d = gid & 255;
    int n = (gid >> 8) & 255;
    int b = gid >> 16;
    int p = idx[n];
    float h = h_map[((size_t)b * WSQ + p) * DM + d];
    hcv[gid] = h;
    cth[((size_t)(b * 256 + n)) * 512 + d] = __float2half_rn(h);
    x[((size_t)(b * SQ + n)) * DM + d] = h + pos2d_val(p / 33, p % 33, d);
}

__global__ void __launch_bounds__(256) im2col_k(const float* __restrict__ frame,
                                                __half* __restrict__ ph) {
    int gid = blockIdx.x * 256 + threadIdx.x;
    int k = gid % 768;
    int m = gid / 768;
    int c = k >> 8;
    int r = (k >> 4) & 15;
    int q = k & 15;
    int t = m & 63, b = m >> 6;
    int yy = (t >> 3) * 16 + r;
    int xx = (t & 7) * 16 + q;
    ph[gid] = __float2half_rn(frame[(((size_t)b * 3 + c) * 128 + yy) * 128 + xx]);
}

// ---------------- entry LayerNorm (layer 0 only): x -> lnh ----------------
__global__ void __launch_bounds__(256) ln_k(const float* __restrict__ x,
                                            __half* __restrict__ yh,
                                            const float* __restrict__ gam,
                                            const float* __restrict__ bet) {
    int warp = threadIdx.x >> 5;
    int lane = threadIdx.x & 31;
    int tok = blockIdx.x * 8 + warp;
    const float* xp = x + (size_t)tok * DM;
    float v[8];
    float sum = 0.f, sq = 0.f;
#pragma unroll
    for (int i = 0; i < 8; i++) {
        v[i] = xp[lane + 32 * i];
        sum += v[i];
        sq += v[i] * v[i];
    }
#pragma unroll
    for (int off = 16; off; off >>= 1) {
        sum += __shfl_xor_sync(0xffffffffu, sum, off);
        sq  += __shfl_xor_sync(0xffffffffu, sq, off);
    }
    float mu = sum * (1.0f / 256.0f);
    float var = sq * (1.0f / 256.0f) - mu * mu;
    float inv = rsqrtf(var + 1e-5f);
#pragma unroll
    for (int i = 0; i < 8; i++) {
        int d = lane + 32 * i;
        yh[(size_t)tok * DM + d] = __float2half_rn((v[i] - mu) * inv * gam[d] + bet[d]);
    }
}

// ================= fused flash attention (mma.sync fp16) =================
#define ATT_RS 80u
#define ATT_TEN (320u * ATT_RS)
#define ATT_SMEM (3u * ATT_TEN)

__global__ void __launch_bounds__(320) attn_fa_k(const __half* __restrict__ qkvh,
                                                 __half* __restrict__ oh) {
    extern __shared__ char sm[];
    const uint32_t smb = smem_u32(sm);
    const int b = blockIdx.x >> 3;
    const int h = blockIdx.x & 7;
    const int tid = threadIdx.x;
    const int l = tid & 31;
    const int w = tid >> 5;

#pragma unroll
    for (int j = 0; j < 12; j++) {
        int c = j * 320 + tid;
        int tz = c / 1280;
        int rem = c - tz * 1280;
        int r = rem >> 2;
        int ch = rem & 3;
        const __half* src = qkvh + (size_t)(b * SQ + r) * 768 + tz * 256 + h * 32 + ch * 8;
        cp16(smb + (uint32_t)tz * ATT_TEN + (uint32_t)r * ATT_RS + (uint32_t)ch * 16u, src);
    }
    asm volatile("cp.async.commit_group;" ::: "memory");
    asm volatile("cp.async.wait_group 0;" ::: "memory");
    __syncthreads();

    const uint32_t smQ = smb, smK = smb + ATT_TEN, smV = smb + 2 * ATT_TEN;
    const int q0 = w * 32;

    uint32_t aq[2][2][4];
#pragma unroll
    for (int mf = 0; mf < 2; mf++)
#pragma unroll
        for (int kc = 0; kc < 2; kc++) {
            uint32_t addr = smQ +
                (uint32_t)(q0 + mf * 16 + (l & 7) + ((l >> 3) & 1) * 8) * ATT_RS +
                (uint32_t)(kc * 2 + (l >> 4)) * 16u;
            ldsm4(aq[mf][kc], addr);
        }

    float mrow[2][2] = {{-1e30f, -1e30f}, {-1e30f, -1e30f}};
    float lrow[2][2] = {{0.f, 0.f}, {0.f, 0.f}};
    float acc_o[2][4][4];
#pragma unroll
    for (int mf = 0; mf < 2; mf++)
#pragma unroll
        for (int db = 0; db < 4; db++)
#pragma unroll
            for (int q = 0; q < 4; q++) acc_o[mf][db][q] = 0.f;

    for (int ck = 0; ck < 320; ck += 64) {
        float s[2][8][4];
#pragma unroll
        for (int mf = 0; mf < 2; mf++)
#pragma unroll
            for (int nb = 0; nb < 8; nb++)
#pragma unroll
                for (int q = 0; q < 4; q++) s[mf][nb][q] = 0.f;

#pragma unroll
        for (int g = 0; g < 4; g++) {
#pragma unroll
            for (int ks = 0; ks < 2; ks++) {
                uint32_t bk[4];
                uint32_t addr = smK +
                    (uint32_t)(ck + g * 16 + ((l >> 4) << 3) + (l & 7)) * ATT_RS +
                    (uint32_t)(ks * 2 + ((l >> 3) & 1)) * 16u;
                ldsm4(bk, addr);
#pragma unroll
                for (int mf = 0; mf < 2; mf++) {
                    mma16816(s[mf][2 * g],     aq[mf][ks], bk);
                    mma16816(s[mf][2 * g + 1], aq[mf][ks], bk + 2);
                }
            }
        }

        uint32_t ap[2][4][4];
#pragma unroll
        for (int mf = 0; mf < 2; mf++) {
#pragma unroll
            for (int hh = 0; hh < 2; hh++) {
                float mx = -1e30f;
#pragma unroll
                for (int nb = 0; nb < 8; nb++) {
                    mx = fmaxf(mx, fmaxf(s[mf][nb][hh * 2], s[mf][nb][hh * 2 + 1]));
                }
                mx = fmaxf(mx, __shfl_xor_sync(0xffffffffu, mx, 1));
                mx = fmaxf(mx, __shfl_xor_sync(0xffffffffu, mx, 2));
                float mnew = fmaxf(mrow[mf][hh], mx);
                float corr = __expf(mrow[mf][hh] - mnew);
                mrow[mf][hh] = mnew;
                float lsum = 0.f;
#pragma unroll
                for (int nb = 0; nb < 8; nb++) {
                    float p0 = __expf(s[mf][nb][hh * 2]     - mnew);
                    float p1 = __expf(s[mf][nb][hh * 2 + 1] - mnew);
                    s[mf][nb][hh * 2] = p0;
                    s[mf][nb][hh * 2 + 1] = p1;
                    lsum += p0 + p1;
                }
                lsum += __shfl_xor_sync(0xffffffffu, lsum, 1);
                lsum += __shfl_xor_sync(0xffffffffu, lsum, 2);
                lrow[mf][hh] = lrow[mf][hh] * corr + lsum;
#pragma unroll
                for (int db = 0; db < 4; db++) {
                    acc_o[mf][db][hh * 2]     *= corr;
                    acc_o[mf][db][hh * 2 + 1] *= corr;
                }
            }
#pragma unroll
            for (int g = 0; g < 4; g++) {
                __half2 h0 = __floats2half2_rn(s[mf][2 * g][0],     s[mf][2 * g][1]);
                __half2 h1 = __floats2half2_rn(s[mf][2 * g][2],     s[mf][2 * g][3]);
                __half2 h2 = __floats2half2_rn(s[mf][2 * g + 1][0], s[mf][2 * g + 1][1]);
                __half2 h3 = __floats2half2_rn(s[mf][2 * g + 1][2], s[mf][2 * g + 1][3]);
                ap[mf][g][0] = *(uint32_t*)&h0;
                ap[mf][g][1] = *(uint32_t*)&h1;
                ap[mf][g][2] = *(uint32_t*)&h2;
                ap[mf][g][3] = *(uint32_t*)&h3;
            }
        }

#pragma unroll
        for (int g = 0; g < 4; g++) {
#pragma unroll
            for (int dd = 0; dd < 2; dd++) {
                uint32_t bv[4];
                uint32_t addr = smV +
                    (uint32_t)(ck + g * 16 + ((l >> 3) & 1) * 8 + (l & 7)) * ATT_RS +
                    (uint32_t)(dd * 2 + (l >> 4)) * 16u;
                ldsm4t(bv, addr);
#pragma unroll
                for (int mf = 0; mf < 2; mf++) {
                    mma16816(acc_o[mf][dd * 2],     ap[mf][g], bv);
                    mma16816(acc_o[mf][dd * 2 + 1], ap[mf][g], bv + 2);
                }
            }
        }
    }

#pragma unroll
    for (int mf = 0; mf < 2; mf++) {
#pragma unroll
        for (int hh = 0; hh < 2; hh++) {
            float inv = 1.f / lrow[mf][hh];
            int tok = q0 + mf * 16 + (l >> 2) + hh * 8;
            __half* op = oh + (size_t)(b * SQ + tok) * DM + h * 32 + 2 * (l & 3);
#pragma unroll
            for (int db = 0; db < 4; db++) {
                __half2 r = __floats2half2_rn(acc_o[mf][db][hh * 2] * inv,
                                              acc_o[mf][db][hh * 2 + 1] * inv);
                *(__half2*)(op + db * 8) = r;
            }
        }
    }
}

// ================= HMMA fp16 pipelined GEMM (128x128, 2 CTA/SM) =================
enum { EPL_GELU = 2, EPL_IMGTOK = 3, EPL_GATE = 4, EPL_QKVH = 5 };

#define STG_B 32768u
#define GSMEM_BYTES (3u * STG_B)

template <int MODE>
__device__ __forceinline__ void epi_store2(
    float* __restrict__ out, __half* __restrict__ outh,
    int N, int row, int col, float vx, float vy,
    const float* __restrict__ bias, const float* __restrict__ res,
    const float* __restrict__ extra, const int* __restrict__ idx) {
    float2 bb = *(const float2*)(bias + col);
    vx += bb.x;
    vy += bb.y;
    if (MODE == EPL_GELU) {
        *(__half2*)&outh[(size_t)row * N + col] =
            __floats2half2_rn(gelu_exact(vx), gelu_exact(vy));
    } else if (MODE == EPL_QKVH) {
        float sc = (col < 256) ? 0.17677669529663687f : 1.0f;
        *(__half2*)&outh[(size_t)row * N + col] = __floats2half2_rn(vx * sc, vy * sc);
    } else if (MODE == EPL_IMGTOK) {
        int b = row >> 6, tt = row & 63;
        int yy = tt >> 3, xx = tt & 7;
        vx += pos2d_val(yy, xx, col);
        vy += pos2d_val(yy, xx, col + 1);
        *(float2*)&out[((size_t)(b * SQ + NCV + tt)) * DM + col] = make_float2(vx, vy);
    } else {  // EPL_GATE
        int b = row >> 8, n = row & 255;
        int p = idx[n];
        float2 hc = *(const float2*)&res[(size_t)row * DM + col];
        float2 hn = *(const float2*)&extra[((size_t)(b * SQ + n)) * DM + col];
        float g0 = 1.f / (1.f + expf(-vx));
        float g1 = 1.f / (1.f + expf(-vy));
        float2 r;
        r.x = hc.x + g0 * (hn.x - hc.x);
        r.y = hc.y + g1 * (hn.y - hc.y);
        *(float2*)&out[((size_t)b * WSQ + p) * DM + col] = r;
    }
}

template <int MODE>
__global__ void __launch_bounds__(256, 2) mma_gemm_k(
    const __half* __restrict__ Ah, const __half* __restrict__ Bh,
    const float* __restrict__ bias, float* __restrict__ out,
    __half* __restrict__ outh,
    int M, int N, int K,
    const float* __restrict__ res, const float* __restrict__ extra,
    const int* __restrict__ idx) {
    extern __shared__ char sm[];
    const uint32_t smb = smem_u32(sm);
    const int tid = threadIdx.x;
    const int lane = tid & 31;
    const int w = tid >> 5;
    const int wm = w >> 1;
    const int wn = w & 1;
    const int m0 = blockIdx.y * 128;
    const int n0 = blockIdx.x * 128;

    float acc[2][8][4];
#pragma unroll
    for (int i = 0; i < 2; i++)
#pragma unroll
        for (int j = 0; j < 8; j++)
#pragma unroll
            for (int q = 0; q < 4; q++) acc[i][j][q] = 0.f;

    const int nkt = K >> 6;

    uint32_t asrc[4], bsrc[4], coff[4];
#pragma unroll
    for (int j = 0; j < 4; j++) {
        int c = tid + 256 * j;
        int crow = c >> 3;
        int ck8 = c & 7;
        coff[j] = (uint32_t)crow * 128u + (uint32_t)((ck8 ^ (crow & 7)) << 4);
        asrc[j] = (uint32_t)(m0 + crow) * (uint32_t)K + (uint32_t)(ck8 * 8);
        bsrc[j] = (uint32_t)(n0 + crow) * (uint32_t)K + (uint32_t)(ck8 * 8);
    }

#define ISSUE_STAGE(kt)                                                        \
    do {                                                                       \
        const uint32_t kk0 = (uint32_t)(kt) << 6;                              \
        const uint32_t sb = smb + (uint32_t)((kt) % 3) * STG_B;                \
        _Pragma("unroll") for (int j = 0; j < 4; j++) {                        \
            cp16(sb + coff[j],          Ah + asrc[j] + kk0);                   \
            cp16(sb + 16384u + coff[j], Bh + bsrc[j] + kk0);                   \
        }                                                                      \
        asm volatile("cp.async.commit_group;" ::: "memory");                   \
    } while (0)

    ISSUE_STAGE(0);
    ISSUE_STAGE(1);

    const uint32_t rowAb[2] = {
        (uint32_t)(wm * 32 + 0  + (lane & 7) + ((lane >> 3) & 1) * 8) * 128u,
        (uint32_t)(wm * 32 + 16 + (lane & 7) + ((lane >> 3) & 1) * 8) * 128u};
    const int a_k8add = lane >> 4;
    uint32_t rowBb[4];
#pragma unroll
    for (int nfp = 0; nfp < 4; nfp++)
        rowBb[nfp] = (uint32_t)(wn * 64 + nfp * 16 + ((lane >> 4) << 3) + (lane & 7)) * 128u;
    const int b_k8add = (lane >> 3) & 1;
    const uint32_t swz = (uint32_t)(lane & 7);

    for (int kt = 0; kt < nkt; kt++) {
        if (kt + 1 < nkt) {
            asm volatile("cp.async.wait_group 1;" ::: "memory");
        } else {
            asm volatile("cp.async.wait_group 0;" ::: "memory");
        }
        __syncthreads();
        if (kt + 2 < nkt) ISSUE_STAGE(kt + 2);

        const uint32_t sb = smb + (uint32_t)(kt % 3) * STG_B;
#pragma unroll
        for (int ks = 0; ks < 4; ks++) {
            uint32_t ah[2][4];
#pragma unroll
            for (int mf = 0; mf < 2; mf++) {
                uint32_t off = rowAb[mf] +
                    ((((uint32_t)(ks * 2 + a_k8add)) ^ swz) << 4);
                ldsm4(ah[mf], sb + off);
            }
#pragma unroll
            for (int nfp = 0; nfp < 4; nfp++) {
                uint32_t off = rowBb[nfp] +
                    ((((uint32_t)(ks * 2 + b_k8add)) ^ swz) << 4);
                uint32_t bh[4];
                ldsm4(bh, sb + 16384u + off);
#pragma unroll
                for (int mf = 0; mf < 2; mf++) {
                    mma16816(acc[mf][2 * nfp],     ah[mf], bh);
                    mma16816(acc[mf][2 * nfp + 1], ah[mf], bh + 2);
                }
            }
        }
    }
#undef ISSUE_STAGE

#pragma unroll
    for (int mf = 0; mf < 2; mf++) {
        int row = m0 + wm * 32 + mf * 16 + (lane >> 2);
#pragma unroll
        for (int nf = 0; nf < 8; nf++) {
            int col = n0 + wn * 64 + nf * 8 + (lane & 3) * 2;
            epi_store2<MODE>(out, outh, N, row, col,
                             acc[mf][nf][0], acc[mf][nf][1], bias, res, extra, idx);
            epi_store2<MODE>(out, outh, N, row + 8, col,
                             acc[mf][nf][2], acc[mf][nf][3], bias, res, extra, idx);
        }
    }
}

// ======== fused GEMM(64x256) + bias + residual + LayerNorm ========
// Tile 64(M) x 256(N), 8 warps (2M x 4N), warp tile 32x64, BK=64, double-buffer.
// C = A@W^T + bias + res (written to xout fp32 unless FINAL);
// !FINAL: lnh_out = LN(C) fp16 (next layer's input)
// FINAL:  xout(g_ln) = LN(C) fp32, lnh_out = cth upper half for n<NCV
#define STG64_B 40960u                    // A 8KB | B 32KB per stage
#define GB64_OFF (2u * STG64_B)           // 81920: gamma/beta 512 floats (2KB)
#define ST64_OFF (GB64_OFF + 2048u)       // stats: 64 rows x 4 warps x float2 (2KB)
#define GSMEM64 (ST64_OFF + 2048u)        // 86016 -> 2 CTAs/SM

template <bool FINAL>
__global__ void __launch_bounds__(256, 2) gemm64_resln_k(
    const __half* __restrict__ Ah, const __half* __restrict__ Bh,
    const float* __restrict__ bias,
    const float* res, float* xout, __half* __restrict__ lnh_out,
    int K, const float* __restrict__ gam, const float* __restrict__ bet) {
    extern __shared__ char sm[];
    const uint32_t smb = smem_u32(sm);
    const int tid = threadIdx.x;
    const int lane = tid & 31;
    const int w = tid >> 5;
    const int wm = w >> 2;   // 0..1 -> M offset wm*32
    const int wn = w & 3;    // 0..3 -> N offset wn*64
    const int m0 = blockIdx.y * 64;

    float* gbuf = (float*)(sm + GB64_OFF);
    float2* stats = (float2*)(sm + ST64_OFF);
    gbuf[tid] = gam[tid];
    gbuf[256 + tid] = bet[tid];

    float acc[2][8][4];
#pragma unroll
    for (int i = 0; i < 2; i++)
#pragma unroll
        for (int j = 0; j < 8; j++)
#pragma unroll
            for (int q = 0; q < 4; q++) acc[i][j][q] = 0.f;

    const int nkt = K >> 6;

    // copy coords: A 2 chunks (64*8=512), B 8 chunks (256*8=2048) per thread
    uint32_t acoff[2], asrc[2];
#pragma unroll
    for (int j = 0; j < 2; j++) {
        int c = tid + 256 * j;
        int crow = c >> 3, ck8 = c & 7;
        acoff[j] = (uint32_t)crow * 128u + (uint32_t)((ck8 ^ (crow & 7)) << 4);
        asrc[j] = (uint32_t)(m0 + crow) * (uint32_t)K + (uint32_t)(ck8 * 8);
    }
    uint32_t bcoff[8], bsrc[8];
#pragma unroll
    for (int j = 0; j < 8; j++) {
        int c = tid + 256 * j;
        int crow = c >> 3, ck8 = c & 7;
        bcoff[j] = (uint32_t)crow * 128u + (uint32_t)((ck8 ^ (crow & 7)) << 4);
        bsrc[j] = (uint32_t)crow * (uint32_t)K + (uint32_t)(ck8 * 8);
    }

#define ISSUE64(kt)                                                            \
    do {                                                                       \
        const uint32_t kk0 = (uint32_t)(kt) << 6;                              \
        const uint32_t sb = smb + (uint32_t)((kt) & 1) * STG64_B;              \
        _Pragma("unroll") for (int j = 0; j < 2; j++)                          \
            cp16(sb + acoff[j], Ah + asrc[j] + kk0);                           \
        _Pragma("unroll") for (int j = 0; j < 8; j++)                          \
            cp16(sb + 8192u + bcoff[j], Bh + bsrc[j] + kk0);                   \
        asm volatile("cp.async.commit_group;" ::: "memory");                   \
    } while (0)

    ISSUE64(0);
    ISSUE64(1);

    const uint32_t rowAb[2] = {
        (uint32_t)(wm * 32 + 0  + (lane & 7) + ((lane >> 3) & 1) * 8) * 128u,
        (uint32_t)(wm * 32 + 16 + (lane & 7) + ((lane >> 3) & 1) * 8) * 128u};
    const int a_k8add = lane >> 4;
    uint32_t rowBb[4];
#pragma unroll
    for (int nfp = 0; nfp < 4; nfp++)
        rowBb[nfp] = (uint32_t)(wn * 64 + nfp * 16 + ((lane >> 4) << 3) + (lane & 7)) * 128u;
    const int b_k8add = (lane >> 3) & 1;
    const uint32_t swz = (uint32_t)(lane & 7);

    for (int kt = 0; kt < nkt; kt++) {
        if (kt + 1 < nkt) {
            asm volatile("cp.async.wait_group 1;" ::: "memory");
        } else {
            asm volatile("cp.async.wait_group 0;" ::: "memory");
        }
        __syncthreads();

        const uint32_t sb = smb + (uint32_t)(kt & 1) * STG64_B;
#pragma unroll
        for (int ks = 0; ks < 4; ks++) {
            uint32_t ah[2][4];
#pragma unroll
            for (int mf = 0; mf < 2; mf++) {
                uint32_t off = rowAb[mf] +
                    ((((uint32_t)(ks * 2 + a_k8add)) ^ swz) << 4);
                ldsm4(ah[mf], sb + off);
            }
#pragma unroll
            for (int nfp = 0; nfp < 4; nfp++) {
                uint32_t off = rowBb[nfp] +
                    ((((uint32_t)(ks * 2 + b_k8add)) ^ swz) << 4);
                uint32_t bh[4];
                ldsm4(bh, sb + 8192u + off);
#pragma unroll
                for (int mf = 0; mf < 2; mf++) {
                    mma16816(acc[mf][2 * nfp],     ah[mf], bh);
                    mma16816(acc[mf][2 * nfp + 1], ah[mf], bh + 2);
                }
            }
        }
        __syncthreads();
        if (kt + 2 < nkt) ISSUE64(kt + 2);
    }
#undef ISSUE64

    // ---- epilogue: acc += bias + res; per-row LN across the 4 N-warps ----
#pragma unroll
    for (int mf = 0; mf < 2; mf++) {
        const int lra = wm * 32 + mf * 16 + (lane >> 2);
        const int r1 = m0 + lra;
        const int r2 = r1 + 8;
        float s1 = 0.f, q1 = 0.f, s2 = 0.f, q2 = 0.f;
#pragma unroll
        for (int nf = 0; nf < 8; nf++) {
            const int col = wn * 64 + nf * 8 + (lane & 3) * 2;
            float2 bb = *(const float2*)&bias[col];
            float2 e1 = *(const float2*)&res[(size_t)r1 * DM + col];
            float2 e2 = *(const float2*)&res[(size_t)r2 * DM + col];
            acc[mf][nf][0] += bb.x + e1.x;
            acc[mf][nf][1] += bb.y + e1.y;
            acc[mf][nf][2] += bb.x + e2.x;
            acc[mf][nf][3] += bb.y + e2.y;
            s1 += acc[mf][nf][0] + acc[mf][nf][1];
            q1 += acc[mf][nf][0] * acc[mf][nf][0] + acc[mf][nf][1] * acc[mf][nf][1];
            s2 += acc[mf][nf][2] + acc[mf][nf][3];
            q2 += acc[mf][nf][2] * acc[mf][nf][2] + acc[mf][nf][3] * acc[mf][nf][3];
        }
        s1 += __shfl_xor_sync(0xffffffffu, s1, 1); q1 += __shfl_xor_sync(0xffffffffu, q1, 1);
        s1 += __shfl_xor_sync(0xffffffffu, s1, 2); q1 += __shfl_xor_sync(0xffffffffu, q1, 2);
        s2 += __shfl_xor_sync(0xffffffffu, s2, 1); q2 += __shfl_xor_sync(0xffffffffu, q2, 1);
        s2 += __shfl_xor_sync(0xffffffffu, s2, 2); q2 += __shfl_xor_sync(0xffffffffu, q2, 2);
        if ((lane & 3) == 0) {
            stats[lra * 4 + wn] = make_float2(s1, q1);
            stats[(lra + 8) * 4 + wn] = make_float2(s2, q2);
        }
    }
    __syncthreads();

#pragma unroll
    for (int mf = 0; mf < 2; mf++) {
        const int lra = wm * 32 + mf * 16 + (lane >> 2);
        const int r1 = m0 + lra, r2 = r1 + 8;
        float2 a0 = stats[lra * 4 + 0], a1 = stats[lra * 4 + 1];
        float2 a2 = stats[lra * 4 + 2], a3 = stats[lra * 4 + 3];
        float mu1 = (a0.x + a1.x + a2.x + a3.x) * (1.0f / 256.0f);
        float iv1 = rsqrtf((a0.y + a1.y + a2.y + a3.y) * (1.0f / 256.0f) - mu1 * mu1 + 1e-5f);
        float2 c0 = stats[(lra + 8) * 4 + 0], c1 = stats[(lra + 8) * 4 + 1];
        float2 c2 = stats[(lra + 8) * 4 + 2], c3 = stats[(lra + 8) * 4 + 3];
        float mu2 = (c0.x + c1.x + c2.x + c3.x) * (1.0f / 256.0f);
        float iv2 = rsqrtf((c0.y + c1.y + c2.y + c3.y) * (1.0f / 256.0f) - mu2 * mu2 + 1e-5f);

        int b1 = 0, n1 = 0, b2 = 0, n2 = 0;
        if (FINAL) { b1 = r1 / SQ; n1 = r1 - b1 * SQ; b2 = r2 / SQ; n2 = r2 - b2 * SQ; }

#pragma unroll
        for (int nf = 0; nf < 8; nf++) {
            const int col = wn * 64 + nf * 8 + (lane & 3) * 2;
            float g0 = gbuf[col], g1 = gbuf[col + 1];
            float be0 = gbuf[256 + col], be1 = gbuf[256 + col + 1];
            float l10 = (acc[mf][nf][0] - mu1) * iv1 * g0 + be0;
            float l11 = (acc[mf][nf][1] - mu1) * iv1 * g1 + be1;
            float l20 = (acc[mf][nf][2] - mu2) * iv2 * g0 + be0;
            float l21 = (acc[mf][nf][3] - mu2) * iv2 * g1 + be1;
            if (!FINAL) {
                *(float2*)&xout[(size_t)r1 * DM + col] =
                    make_float2(acc[mf][nf][0], acc[mf][nf][1]);
                *(float2*)&xout[(size_t)r2 * DM + col] =
                    make_float2(acc[mf][nf][2], acc[mf][nf][3]);
                *(__half2*)&lnh_out[(size_t)r1 * DM + col] = __floats2half2_rn(l10, l11);
                *(__half2*)&lnh_out[(size_t)r2 * DM + col] = __floats2half2_rn(l20, l21);
            } else {
                *(float2*)&xout[(size_t)r1 * DM + col] = make_float2(l10, l11);
                *(float2*)&xout[(size_t)r2 * DM + col] = make_float2(l20, l21);
                if (n1 < NCV)
                    *(__half2*)&lnh_out[((size_t)(b1 * NCV + n1)) * 512 + 256 + col] =
                        __floats2half2_rn(l10, l11);
                if (n2 < NCV)
                    *(__half2*)&lnh_out[((size_t)(b2 * NCV + n2)) * 512 + 256 + col] =
                        __floats2half2_rn(l20, l21);
            }
        }
    }
}

// ---------------- host launcher ----------------
extern "C" void kernel_launch(void* const* d_in, const int* in_sizes, int n_in,
                              void* d_out, int out_size) {
    const float* h_map   = (const float*)d_in[0];
    const float* frame   = (const float*)d_in[1];
    const int*   idx     = (const int*)  d_in[2];
    const float* Wqkv    = (const float*)d_in[3];
    const float* bqkv    = (const float*)d_in[4];
    const float* Wo      = (const float*)d_in[5];
    const float* bo      = (const float*)d_in[6];
    const float* ln1g    = (const float*)d_in[7];
    const float* ln1b    = (const float*)d_in[8];
    const float* W1      = (const float*)d_in[9];
    const float* b1      = (const float*)d_in[10];
    const float* W2      = (const float*)d_in[11];
    const float* b2      = (const float*)d_in[12];
    const float* ln2g    = (const float*)d_in[13];
    const float* ln2b    = (const float*)d_in[14];
    const float* nfg     = (const float*)d_in[15];
    const float* nfb     = (const float*)d_in[16];
    const float* patch_w = (const float*)d_in[17];
    const float* patch_b = (const float*)d_in[18];
    const float* gate_w  = (const float*)d_in[19];
    const float* gate_b  = (const float*)d_in[20];
    float* out = (float*)d_out;

    float *x, *ln, *hcv;
    __half *lnh, *qkvh, *ath, *h1h, *cth, *pth, *wh;
    cudaGetSymbolAddress((void**)&x, g_x);
    cudaGetSymbolAddress((void**)&ln, g_ln);
    cudaGetSymbolAddress((void**)&hcv, g_hcv);
    cudaGetSymbolAddress((void**)&lnh, g_lnh);
    cudaGetSymbolAddress((void**)&qkvh, g_qkvh);
    cudaGetSymbolAddress((void**)&ath, g_ath);
    cudaGetSymbolAddress((void**)&h1h, g_h1h);
    cudaGetSymbolAddress((void**)&cth, g_cth);
    cudaGetSymbolAddress((void**)&pth, g_pth);
    cudaGetSymbolAddress((void**)&wh, g_wh);

    cudaFuncSetAttribute(mma_gemm_k<EPL_GELU>,   cudaFuncAttributeMaxDynamicSharedMemorySize, GSMEM_BYTES);
    cudaFuncSetAttribute(mma_gemm_k<EPL_IMGTOK>, cudaFuncAttributeMaxDynamicSharedMemorySize, GSMEM_BYTES);
    cudaFuncSetAttribute(mma_gemm_k<EPL_GATE>,   cudaFuncAttributeMaxDynamicSharedMemorySize, GSMEM_BYTES);
    cudaFuncSetAttribute(mma_gemm_k<EPL_QKVH>,   cudaFuncAttributeMaxDynamicSharedMemorySize, GSMEM_BYTES);
    cudaFuncSetAttribute(gemm64_resln_k<false>,  cudaFuncAttributeMaxDynamicSharedMemorySize, GSMEM64);
    cudaFuncSetAttribute(gemm64_resln_k<true>,   cudaFuncAttributeMaxDynamicSharedMemorySize, GSMEM64);
    cudaFuncSetAttribute(attn_fa_k, cudaFuncAttributeMaxDynamicSharedMemorySize, ATT_SMEM);

    // pass-through copy; gated scatter overwrites idx positions
    cudaMemcpyAsync(out, h_map, sizeof(float) * (size_t)BB * WSQ * DM,
                    cudaMemcpyDeviceToDevice, 0);

    wcvt_all_k<<<1261568 / 256, 256>>>(Wqkv, Wo, W1, W2, patch_w, gate_w, wh);

    embed_k<<<16384, 256>>>(h_map, idx, hcv, cth, x);
    im2col_k<<<(4096 * 768) / 256, 256>>>(frame, pth);
    mma_gemm_k<EPL_IMGTOK><<<dim3(2, 32), 256, GSMEM_BYTES>>>(
        pth, wh + WOFF_PW, patch_b, x, nullptr,
        4096, 256, 768, nullptr, nullptr, nullptr);

    const int NTOK = BB * SQ;  // 20480

    // entry LN (layer 0 ln1)
    ln_k<<<NTOK / 8, 256>>>(x, lnh, ln1g, ln1b);

    for (int l = 0; l < NDEPTH; l++) {
        mma_gemm_k<EPL_QKVH><<<dim3(6, 160), 256, GSMEM_BYTES>>>(
            lnh, wh + WOFF_QKV + (size_t)l * 196608,
            bqkv + l * 768, nullptr, qkvh,
            NTOK, 768, 256, nullptr, nullptr, nullptr);
        attn_fa_k<<<BB * NHEADS, 320, ATT_SMEM>>>(qkvh, ath);
        // Wo + bias + residual + LN2 -> x, lnh
        gemm64_resln_k<false><<<dim3(1, NTOK / 64), 256, GSMEM64>>>(
            ath, wh + WOFF_WO + (size_t)l * 65536, bo + l * 256,
            x, x, lnh, 256, ln2g + l * 256, ln2b + l * 256);
        mma_gemm_k<EPL_GELU><<<dim3(8, 160), 256, GSMEM_BYTES>>>(
            lnh, wh + WOFF_W1 + (size_t)l * 262144,
            b1 + l * 1024, nullptr, h1h,
            NTOK, 1024, 256, nullptr, nullptr, nullptr);
        // W2 + bias + residual + next LN1 (or FINAL LN -> g_ln + cth)
        if (l + 1 < NDEPTH) {
            gemm64_resln_k<false><<<dim3(1, NTOK / 64), 256, GSMEM64>>>(
                h1h, wh + WOFF_W2 + (size_t)l * 262144, b2 + l * 256,
                x, x, lnh, 1024, ln1g + (l + 1) * 256, ln1b + (l + 1) * 256);
        } else {
            gemm64_resln_k<true><<<dim3(1, NTOK / 64), 256, GSMEM64>>>(
                h1h, wh + WOFF_W2 + (size_t)l * 262144, b2 + l * 256,
                x, ln, cth, 1024, nfg, nfb);
        }
    }

    mma_gemm_k<EPL_GATE><<<dim3(2, 128), 256, GSMEM_BYTES>>>(
        cth, wh + WOFF_GW, gate_b, out, nullptr,
        16384, 256, 512, hcv, ln, idx);
}

// round 11
// speedup vs baseline: 1.1411x; 1.0026x over previous
#include <cuda_runtime.h>
#include <cuda_fp16.h>
#include <math.h>
#include <stdint.h>

#define BB 64
#define SQ 320
#define NCV 256
#define DM 256
#define HIDN 1024
#define NHEADS 8
#define NDEPTH 6
#define WSQ 1089

// ---------------- device scratch ----------------
__device__ float g_x[(size_t)BB * SQ * DM];
__device__ float g_ln[(size_t)BB * SQ * DM];     // final LN fp32 (gate 'extra')
__device__ float g_hcv[(size_t)BB * NCV * DM];

__device__ __half g_lnh[(size_t)BB * SQ * DM];
__device__ __half g_qkvh[(size_t)BB * SQ * 3 * DM];
__device__ __half g_ath[(size_t)BB * SQ * DM];
__device__ __half g_h1h[(size_t)BB * SQ * HIDN];
__device__ __half g_cth[(size_t)BB * NCV * 2 * DM];

#define WOFF_QKV   0u
#define WOFF_WO    1179648u
#define WOFF_W1    1572864u
#define WOFF_W2    3145728u
#define WOFF_PW    4718592u
#define WOFF_GW    4915200u
#define WPOOL_N    5046272u
__device__ __half g_wh[WPOOL_N];

// ---------------- helpers ----------------
__device__ __forceinline__ float pos2d_val(int yy, int xx, int d) {
    int dd = d & 127;
    int i = dd >> 1;
    float freq = expf((float)(2 * i) * (-0.07195578415606394f));
    float coord = (d < 128) ? (float)yy : (float)xx;
    float ang = coord * freq;
    return (d & 1) ? cosf(ang) : sinf(ang);
}

__device__ __forceinline__ float gelu_exact(float v) {
    return 0.5f * v * (1.0f + erff(v * 0.70710678118654752f));
}

__device__ __forceinline__ uint32_t smem_u32(const void* p) {
    uint32_t a;
    asm("{ .reg .u64 t; cvta.to.shared.u64 t, %1; cvt.u32.u64 %0, t; }" : "=r"(a) : "l"(p));
    return a;
}

__device__ __forceinline__ void cp16(uint32_t dst, const void* src) {
    asm volatile("cp.async.cg.shared.global [%0], [%1], 16;" :: "r"(dst), "l"(src));
}

__device__ __forceinline__ void ldsm4(uint32_t* r, uint32_t addr) {
    asm volatile("ldmatrix.sync.aligned.m8n8.x4.shared.b16 {%0,%1,%2,%3}, [%4];"
                 : "=r"(r[0]), "=r"(r[1]), "=r"(r[2]), "=r"(r[3]) : "r"(addr));
}

__device__ __forceinline__ void ldsm4t(uint32_t* r, uint32_t addr) {
    asm volatile("ldmatrix.sync.aligned.m8n8.x4.trans.shared.b16 {%0,%1,%2,%3}, [%4];"
                 : "=r"(r[0]), "=r"(r[1]), "=r"(r[2]), "=r"(r[3]) : "r"(addr));
}

__device__ __forceinline__ void mma16816(float* c, const uint32_t* a, const uint32_t* b) {
    asm volatile(
        "mma.sync.aligned.m16n8k16.row.col.f32.f16.f16.f32 "
        "{%0,%1,%2,%3}, {%4,%5,%6,%7}, {%8,%9}, {%0,%1,%2,%3};\n"
        : "+f"(c[0]), "+f"(c[1]), "+f"(c[2]), "+f"(c[3])
        : "r"(a[0]), "r"(a[1]), "r"(a[2]), "r"(a[3]), "r"(b[0]), "r"(b[1]));
}

// ---------------- ALL weights fp32 -> fp16, one launch ----------------
__global__ void __launch_bounds__(256) wcvt_all_k(
    const float* __restrict__ s0, const float* __restrict__ s1,
    const float* __restrict__ s2, const float* __restrict__ s3,
    const float* __restrict__ s4, const float* __restrict__ s5,
    __half* __restrict__ h) {
    int i = blockIdx.x * 256 + threadIdx.x;
    const float* src;
    int base;
    if (i < 393216) {
        if (i < 294912) { src = s0; base = 0; }
        else            { src = s1; base = 294912; }
    } else if (i < 1179648) {
        if (i < 786432) { src = s2; base = 393216; }
        else            { src = s3; base = 786432; }
    } else {
        if (i < 1228800) { src = s4; base = 1179648; }
        else             { src = s5; base = 1228800; }
    }
    float4 v = ((const float4*)src)[i - base];
    __half2* hp = (__half2*)(h + (size_t)i * 4);
    hp[0] = __floats2half2_rn(v.x, v.y);
    hp[1] = __floats2half2_rn(v.z, v.w);
}

// ---------------- embed + entry LN (cv tokens): warp per token ----------------
__global__ void __launch_bounds__(256) embed_ln_k(const float* __restrict__ h_map,
                                                  const int* __restrict__ idx,
                                                  float* __restrict__ hcv,
                                                  __half* __restrict__ cth,
                                                  float* __restrict__ x,
                                                  __half* __restrict__ lnh,
                                                  const float* __restrict__ gam,
                                                  const float* __restrict__ bet) {
    int warp = threadIdx.x >> 5;
    int lane = threadIdx.x & 31;
    int tok = blockIdx.x * 8 + warp;     // 0..16383
    int b = tok >> 8, n = tok & 255;
    int p = idx[n];
    int yy = p / 33, xx = p % 33;
    const float* hp = h_map + ((size_t)b * WSQ + p) * DM;
    float v[8];
    float sum = 0.f, sq = 0.f;
#pragma unroll
    for (int i = 0; i < 8; i++) {
        int d = lane + 32 * i;
        float h = hp[d];
        hcv[((size_t)tok) * DM + d] = h;
        cth[((size_t)tok) * 512 + d] = __float2half_rn(h);
        float xv = h + pos2d_val(yy, xx, d);
        v[i] = xv;
        x[((size_t)(b * SQ + n)) * DM + d] = xv;
        sum += xv;
        sq += xv * xv;
    }
#pragma unroll
    for (int off = 16; off; off >>= 1) {
        sum += __shfl_xor_sync(0xffffffffu, sum, off);
        sq  += __shfl_xor_sync(0xffffffffu, sq, off);
    }
    float mu = sum * (1.0f / 256.0f);
    float var = sq * (1.0f / 256.0f) - mu * mu;
    float inv = rsqrtf(var + 1e-5f);
#pragma unroll
    for (int i = 0; i < 8; i++) {
        int d = lane + 32 * i;
        lnh[((size_t)(b * SQ + n)) * DM + d] =
            __float2half_rn((v[i] - mu) * inv * gam[d] + bet[d]);
    }
}

// ================= fused flash attention (mma.sync fp16) =================
#define ATT_RS 80u
#define ATT_TEN (320u * ATT_RS)
#define ATT_SMEM (3u * ATT_TEN)

__global__ void __launch_bounds__(320) attn_fa_k(const __half* __restrict__ qkvh,
                                                 __half* __restrict__ oh) {
    extern __shared__ char sm[];
    const uint32_t smb = smem_u32(sm);
    const int b = blockIdx.x >> 3;
    const int h = blockIdx.x & 7;
    const int tid = threadIdx.x;
    const int l = tid & 31;
    const int w = tid >> 5;

#pragma unroll
    for (int j = 0; j < 12; j++) {
        int c = j * 320 + tid;
        int tz = c / 1280;
        int rem = c - tz * 1280;
        int r = rem >> 2;
        int ch = rem & 3;
        const __half* src = qkvh + (size_t)(b * SQ + r) * 768 + tz * 256 + h * 32 + ch * 8;
        cp16(smb + (uint32_t)tz * ATT_TEN + (uint32_t)r * ATT_RS + (uint32_t)ch * 16u, src);
    }
    asm volatile("cp.async.commit_group;" ::: "memory");
    asm volatile("cp.async.wait_group 0;" ::: "memory");
    __syncthreads();

    const uint32_t smQ = smb, smK = smb + ATT_TEN, smV = smb + 2 * ATT_TEN;
    const int q0 = w * 32;

    uint32_t aq[2][2][4];
#pragma unroll
    for (int mf = 0; mf < 2; mf++)
#pragma unroll
        for (int kc = 0; kc < 2; kc++) {
            uint32_t addr = smQ +
                (uint32_t)(q0 + mf * 16 + (l & 7) + ((l >> 3) & 1) * 8) * ATT_RS +
                (uint32_t)(kc * 2 + (l >> 4)) * 16u;
            ldsm4(aq[mf][kc], addr);
        }

    float mrow[2][2] = {{-1e30f, -1e30f}, {-1e30f, -1e30f}};
    float lrow[2][2] = {{0.f, 0.f}, {0.f, 0.f}};
    float acc_o[2][4][4];
#pragma unroll
    for (int mf = 0; mf < 2; mf++)
#pragma unroll
        for (int db = 0; db < 4; db++)
#pragma unroll
            for (int q = 0; q < 4; q++) acc_o[mf][db][q] = 0.f;

    for (int ck = 0; ck < 320; ck += 64) {
        float s[2][8][4];
#pragma unroll
        for (int mf = 0; mf < 2; mf++)
#pragma unroll
            for (int nb = 0; nb < 8; nb++)
#pragma unroll
                for (int q = 0; q < 4; q++) s[mf][nb][q] = 0.f;

#pragma unroll
        for (int g = 0; g < 4; g++) {
#pragma unroll
            for (int ks = 0; ks < 2; ks++) {
                uint32_t bk[4];
                uint32_t addr = smK +
                    (uint32_t)(ck + g * 16 + ((l >> 4) << 3) + (l & 7)) * ATT_RS +
                    (uint32_t)(ks * 2 + ((l >> 3) & 1)) * 16u;
                ldsm4(bk, addr);
#pragma unroll
                for (int mf = 0; mf < 2; mf++) {
                    mma16816(s[mf][2 * g],     aq[mf][ks], bk);
                    mma16816(s[mf][2 * g + 1], aq[mf][ks], bk + 2);
                }
            }
        }

        uint32_t ap[2][4][4];
#pragma unroll
        for (int mf = 0; mf < 2; mf++) {
#pragma unroll
            for (int hh = 0; hh < 2; hh++) {
                float mx = -1e30f;
#pragma unroll
                for (int nb = 0; nb < 8; nb++) {
                    mx = fmaxf(mx, fmaxf(s[mf][nb][hh * 2], s[mf][nb][hh * 2 + 1]));
                }
                mx = fmaxf(mx, __shfl_xor_sync(0xffffffffu, mx, 1));
                mx = fmaxf(mx, __shfl_xor_sync(0xffffffffu, mx, 2));
                float mnew = fmaxf(mrow[mf][hh], mx);
                float corr = __expf(mrow[mf][hh] - mnew);
                mrow[mf][hh] = mnew;
                float lsum = 0.f;
#pragma unroll
                for (int nb = 0; nb < 8; nb++) {
                    float p0 = __expf(s[mf][nb][hh * 2]     - mnew);
                    float p1 = __expf(s[mf][nb][hh * 2 + 1] - mnew);
                    s[mf][nb][hh * 2] = p0;
                    s[mf][nb][hh * 2 + 1] = p1;
                    lsum += p0 + p1;
                }
                lsum += __shfl_xor_sync(0xffffffffu, lsum, 1);
                lsum += __shfl_xor_sync(0xffffffffu, lsum, 2);
                lrow[mf][hh] = lrow[mf][hh] * corr + lsum;
#pragma unroll
                for (int db = 0; db < 4; db++) {
                    acc_o[mf][db][hh * 2]     *= corr;
                    acc_o[mf][db][hh * 2 + 1] *= corr;
                }
            }
#pragma unroll
            for (int g = 0; g < 4; g++) {
                __half2 h0 = __floats2half2_rn(s[mf][2 * g][0],     s[mf][2 * g][1]);
                __half2 h1 = __floats2half2_rn(s[mf][2 * g][2],     s[mf][2 * g][3]);
                __half2 h2 = __floats2half2_rn(s[mf][2 * g + 1][0], s[mf][2 * g + 1][1]);
                __half2 h3 = __floats2half2_rn(s[mf][2 * g + 1][2], s[mf][2 * g + 1][3]);
                ap[mf][g][0] = *(uint32_t*)&h0;
                ap[mf][g][1] = *(uint32_t*)&h1;
                ap[mf][g][2] = *(uint32_t*)&h2;
                ap[mf][g][3] = *(uint32_t*)&h3;
            }
        }

#pragma unroll
        for (int g = 0; g < 4; g++) {
#pragma unroll
            for (int dd = 0; dd < 2; dd++) {
                uint32_t bv[4];
                uint32_t addr = smV +
                    (uint32_t)(ck + g * 16 + ((l >> 3) & 1) * 8 + (l & 7)) * ATT_RS +
                    (uint32_t)(dd * 2 + (l >> 4)) * 16u;
                ldsm4t(bv, addr);
#pragma unroll
                for (int mf = 0; mf < 2; mf++) {
                    mma16816(acc_o[mf][dd * 2],     ap[mf][g], bv);
                    mma16816(acc_o[mf][dd * 2 + 1], ap[mf][g], bv + 2);
                }
            }
        }
    }

#pragma unroll
    for (int mf = 0; mf < 2; mf++) {
#pragma unroll
        for (int hh = 0; hh < 2; hh++) {
            float inv = 1.f / lrow[mf][hh];
            int tok = q0 + mf * 16 + (l >> 2) + hh * 8;
            __half* op = oh + (size_t)(b * SQ + tok) * DM + h * 32 + 2 * (l & 3);
#pragma unroll
            for (int db = 0; db < 4; db++) {
                __half2 r = __floats2half2_rn(acc_o[mf][db][hh * 2] * inv,
                                              acc_o[mf][db][hh * 2 + 1] * inv);
                *(__half2*)(op + db * 8) = r;
            }
        }
    }
}

// ================= HMMA fp16 pipelined GEMM (128x128, 2 CTA/SM) =================
enum { EPL_GELU = 2, EPL_GATE = 4, EPL_QKVH = 5 };

#define STG_B 32768u
#define GSMEM_BYTES (3u * STG_B)

template <int MODE>
__device__ __forceinline__ void epi_store2(
    float* __restrict__ out, __half* __restrict__ outh,
    int N, int row, int col, float vx, float vy,
    const float* __restrict__ bias, const float* __restrict__ res,
    const float* __restrict__ extra, const int* __restrict__ idx) {
    float2 bb = *(const float2*)(bias + col);
    vx += bb.x;
    vy += bb.y;
    if (MODE == EPL_GELU) {
        *(__half2*)&outh[(size_t)row * N + col] =
            __floats2half2_rn(gelu_exact(vx), gelu_exact(vy));
    } else if (MODE == EPL_QKVH) {
        float sc = (col < 256) ? 0.17677669529663687f : 1.0f;
        *(__half2*)&outh[(size_t)row * N + col] = __floats2half2_rn(vx * sc, vy * sc);
    } else {  // EPL_GATE
        int b = row >> 8, n = row & 255;
        int p = idx[n];
        float2 hc = *(const float2*)&res[(size_t)row * DM + col];
        float2 hn = *(const float2*)&extra[((size_t)(b * SQ + n)) * DM + col];
        float g0 = 1.f / (1.f + expf(-vx));
        float g1 = 1.f / (1.f + expf(-vy));
        float2 r;
        r.x = hc.x + g0 * (hn.x - hc.x);
        r.y = hc.y + g1 * (hn.y - hc.y);
        *(float2*)&out[((size_t)b * WSQ + p) * DM + col] = r;
    }
}

template <int MODE>
__global__ void __launch_bounds__(256, 2) mma_gemm_k(
    const __half* __restrict__ Ah, const __half* __restrict__ Bh,
    const float* __restrict__ bias, float* __restrict__ out,
    __half* __restrict__ outh,
    int M, int N, int K,
    const float* __restrict__ res, const float* __restrict__ extra,
    const int* __restrict__ idx) {
    extern __shared__ char sm[];
    const uint32_t smb = smem_u32(sm);
    const int tid = threadIdx.x;
    const int lane = tid & 31;
    const int w = tid >> 5;
    const int wm = w >> 1;
    const int wn = w & 1;
    const int m0 = blockIdx.y * 128;
    const int n0 = blockIdx.x * 128;

    float acc[2][8][4];
#pragma unroll
    for (int i = 0; i < 2; i++)
#pragma unroll
        for (int j = 0; j < 8; j++)
#pragma unroll
            for (int q = 0; q < 4; q++) acc[i][j][q] = 0.f;

    const int nkt = K >> 6;

    uint32_t asrc[4], bsrc[4], coff[4];
#pragma unroll
    for (int j = 0; j < 4; j++) {
        int c = tid + 256 * j;
        int crow = c >> 3;
        int ck8 = c & 7;
        coff[j] = (uint32_t)crow * 128u + (uint32_t)((ck8 ^ (crow & 7)) << 4);
        asrc[j] = (uint32_t)(m0 + crow) * (uint32_t)K + (uint32_t)(ck8 * 8);
        bsrc[j] = (uint32_t)(n0 + crow) * (uint32_t)K + (uint32_t)(ck8 * 8);
    }

#define ISSUE_STAGE(kt)                                                        \
    do {                                                                       \
        const uint32_t kk0 = (uint32_t)(kt) << 6;                              \
        const uint32_t sb = smb + (uint32_t)((kt) % 3) * STG_B;                \
        _Pragma("unroll") for (int j = 0; j < 4; j++) {                        \
            cp16(sb + coff[j],          Ah + asrc[j] + kk0);                   \
            cp16(sb + 16384u + coff[j], Bh + bsrc[j] + kk0);                   \
        }                                                                      \
        asm volatile("cp.async.commit_group;" ::: "memory");                   \
    } while (0)

    ISSUE_STAGE(0);
    ISSUE_STAGE(1);

    const uint32_t rowAb[2] = {
        (uint32_t)(wm * 32 + 0  + (lane & 7) + ((lane >> 3) & 1) * 8) * 128u,
        (uint32_t)(wm * 32 + 16 + (lane & 7) + ((lane >> 3) & 1) * 8) * 128u};
    const int a_k8add = lane >> 4;
    uint32_t rowBb[4];
#pragma unroll
    for (int nfp = 0; nfp < 4; nfp++)
        rowBb[nfp] = (uint32_t)(wn * 64 + nfp * 16 + ((lane >> 4) << 3) + (lane & 7)) * 128u;
    const int b_k8add = (lane >> 3) & 1;
    const uint32_t swz = (uint32_t)(lane & 7);

    for (int kt = 0; kt < nkt; kt++) {
        if (kt + 1 < nkt) {
            asm volatile("cp.async.wait_group 1;" ::: "memory");
        } else {
            asm volatile("cp.async.wait_group 0;" ::: "memory");
        }
        __syncthreads();
        if (kt + 2 < nkt) ISSUE_STAGE(kt + 2);

        const uint32_t sb = smb + (uint32_t)(kt % 3) * STG_B;
#pragma unroll
        for (int ks = 0; ks < 4; ks++) {
            uint32_t ah[2][4];
#pragma unroll
            for (int mf = 0; mf < 2; mf++) {
                uint32_t off = rowAb[mf] +
                    ((((uint32_t)(ks * 2 + a_k8add)) ^ swz) << 4);
                ldsm4(ah[mf], sb + off);
            }
#pragma unroll
            for (int nfp = 0; nfp < 4; nfp++) {
                uint32_t off = rowBb[nfp] +
                    ((((uint32_t)(ks * 2 + b_k8add)) ^ swz) << 4);
                uint32_t bh[4];
                ldsm4(bh, sb + 16384u + off);
#pragma unroll
                for (int mf = 0; mf < 2; mf++) {
                    mma16816(acc[mf][2 * nfp],     ah[mf], bh);
                    mma16816(acc[mf][2 * nfp + 1], ah[mf], bh + 2);
                }
            }
        }
    }
#undef ISSUE_STAGE

#pragma unroll
    for (int mf = 0; mf < 2; mf++) {
        int row = m0 + wm * 32 + mf * 16 + (lane >> 2);
#pragma unroll
        for (int nf = 0; nf < 8; nf++) {
            int col = n0 + wn * 64 + nf * 8 + (lane & 3) * 2;
            epi_store2<MODE>(out, outh, N, row, col,
                             acc[mf][nf][0], acc[mf][nf][1], bias, res, extra, idx);
            epi_store2<MODE>(out, outh, N, row + 8, col,
                             acc[mf][nf][2], acc[mf][nf][3], bias, res, extra, idx);
        }
    }
}

// ======== fused GEMM(64x256) + bias + residual + LayerNorm ========
#define STG64_B 40960u
#define GB64_OFF (2u * STG64_B)
#define ST64_OFF (GB64_OFF + 2048u)
#define GSMEM64 (ST64_OFF + 2048u)

template <bool FINAL>
__global__ void __launch_bounds__(256, 2) gemm64_resln_k(
    const __half* __restrict__ Ah, const __half* __restrict__ Bh,
    const float* __restrict__ bias,
    const float* res, float* xout, __half* __restrict__ lnh_out,
    int K, const float* __restrict__ gam, const float* __restrict__ bet) {
    extern __shared__ char sm[];
    const uint32_t smb = smem_u32(sm);
    const int tid = threadIdx.x;
    const int lane = tid & 31;
    const int w = tid >> 5;
    const int wm = w >> 2;
    const int wn = w & 3;
    const int m0 = blockIdx.y * 64;

    float* gbuf = (float*)(sm + GB64_OFF);
    float2* stats = (float2*)(sm + ST64_OFF);
    gbuf[tid] = gam[tid];
    gbuf[256 + tid] = bet[tid];

    float acc[2][8][4];
#pragma unroll
    for (int i = 0; i < 2; i++)
#pragma unroll
        for (int j = 0; j < 8; j++)
#pragma unroll
            for (int q = 0; q < 4; q++) acc[i][j][q] = 0.f;

    const int nkt = K >> 6;

    uint32_t acoff[2], asrc[2];
#pragma unroll
    for (int j = 0; j < 2; j++) {
        int c = tid + 256 * j;
        int crow = c >> 3, ck8 = c & 7;
        acoff[j] = (uint32_t)crow * 128u + (uint32_t)((ck8 ^ (crow & 7)) << 4);
        asrc[j] = (uint32_t)(m0 + crow) * (uint32_t)K + (uint32_t)(ck8 * 8);
    }
    uint32_t bcoff[8], bsrc[8];
#pragma unroll
    for (int j = 0; j < 8; j++) {
        int c = tid + 256 * j;
        int crow = c >> 3, ck8 = c & 7;
        bcoff[j] = (uint32_t)crow * 128u + (uint32_t)((ck8 ^ (crow & 7)) << 4);
        bsrc[j] = (uint32_t)crow * (uint32_t)K + (uint32_t)(ck8 * 8);
    }

#define ISSUE64(kt)                                                            \
    do {                                                                       \
        const uint32_t kk0 = (uint32_t)(kt) << 6;                              \
        const uint32_t sb = smb + (uint32_t)((kt) & 1) * STG64_B;              \
        _Pragma("unroll") for (int j = 0; j < 2; j++)                          \
            cp16(sb + acoff[j], Ah + asrc[j] + kk0);                           \
        _Pragma("unroll") for (int j = 0; j < 8; j++)                          \
            cp16(sb + 8192u + bcoff[j], Bh + bsrc[j] + kk0);                   \
        asm volatile("cp.async.commit_group;" ::: "memory");                   \
    } while (0)

    ISSUE64(0);
    ISSUE64(1);

    const uint32_t rowAb[2] = {
        (uint32_t)(wm * 32 + 0  + (lane & 7) + ((lane >> 3) & 1) * 8) * 128u,
        (uint32_t)(wm * 32 + 16 + (lane & 7) + ((lane >> 3) & 1) * 8) * 128u};
    const int a_k8add = lane >> 4;
    uint32_t rowBb[4];
#pragma unroll
    for (int nfp = 0; nfp < 4; nfp++)
        rowBb[nfp] = (uint32_t)(wn * 64 + nfp * 16 + ((lane >> 4) << 3) + (lane & 7)) * 128u;
    const int b_k8add = (lane >> 3) & 1;
    const uint32_t swz = (uint32_t)(lane & 7);

    for (int kt = 0; kt < nkt; kt++) {
        if (kt + 1 < nkt) {
            asm volatile("cp.async.wait_group 1;" ::: "memory");
        } else {
            asm volatile("cp.async.wait_group 0;" ::: "memory");
        }
        __syncthreads();

        const uint32_t sb = smb + (uint32_t)(kt & 1) * STG64_B;
#pragma unroll
        for (int ks = 0; ks < 4; ks++) {
            uint32_t ah[2][4];
#pragma unroll
            for (int mf = 0; mf < 2; mf++) {
                uint32_t off = rowAb[mf] +
                    ((((uint32_t)(ks * 2 + a_k8add)) ^ swz) << 4);
                ldsm4(ah[mf], sb + off);
            }
#pragma unroll
            for (int nfp = 0; nfp < 4; nfp++) {
                uint32_t off = rowBb[nfp] +
                    ((((uint32_t)(ks * 2 + b_k8add)) ^ swz) << 4);
                uint32_t bh[4];
                ldsm4(bh, sb + 8192u + off);
#pragma unroll
                for (int mf = 0; mf < 2; mf++) {
                    mma16816(acc[mf][2 * nfp],     ah[mf], bh);
                    mma16816(acc[mf][2 * nfp + 1], ah[mf], bh + 2);
                }
            }
        }
        __syncthreads();
        if (kt + 2 < nkt) ISSUE64(kt + 2);
    }
#undef ISSUE64

#pragma unroll
    for (int mf = 0; mf < 2; mf++) {
        const int lra = wm * 32 + mf * 16 + (lane >> 2);
        const int r1 = m0 + lra;
        const int r2 = r1 + 8;
        float s1 = 0.f, q1 = 0.f, s2 = 0.f, q2 = 0.f;
#pragma unroll
        for (int nf = 0; nf < 8; nf++) {
            const int col = wn * 64 + nf * 8 + (lane & 3) * 2;
            float2 bb = *(const float2*)&bias[col];
            float2 e1 = *(const float2*)&res[(size_t)r1 * DM + col];
            float2 e2 = *(const float2*)&res[(size_t)r2 * DM + col];
            acc[mf][nf][0] += bb.x + e1.x;
            acc[mf][nf][1] += bb.y + e1.y;
            acc[mf][nf][2] += bb.x + e2.x;
            acc[mf][nf][3] += bb.y + e2.y;
            s1 += acc[mf][nf][0] + acc[mf][nf][1];
            q1 += acc[mf][nf][0] * acc[mf][nf][0] + acc[mf][nf][1] * acc[mf][nf][1];
            s2 += acc[mf][nf][2] + acc[mf][nf][3];
            q2 += acc[mf][nf][2] * acc[mf][nf][2] + acc[mf][nf][3] * acc[mf][nf][3];
        }
        s1 += __shfl_xor_sync(0xffffffffu, s1, 1); q1 += __shfl_xor_sync(0xffffffffu, q1, 1);
        s1 += __shfl_xor_sync(0xffffffffu, s1, 2); q1 += __shfl_xor_sync(0xffffffffu, q1, 2);
        s2 += __shfl_xor_sync(0xffffffffu, s2, 1); q2 += __shfl_xor_sync(0xffffffffu, q2, 1);
        s2 += __shfl_xor_sync(0xffffffffu, s2, 2); q2 += __shfl_xor_sync(0xffffffffu, q2, 2);
        if ((lane & 3) == 0) {
            stats[lra * 4 + wn] = make_float2(s1, q1);
            stats[(lra + 8) * 4 + wn] = make_float2(s2, q2);
        }
    }
    __syncthreads();

#pragma unroll
    for (int mf = 0; mf < 2; mf++) {
        const int lra = wm * 32 + mf * 16 + (lane >> 2);
        const int r1 = m0 + lra, r2 = r1 + 8;
        float2 a0 = stats[lra * 4 + 0], a1 = stats[lra * 4 + 1];
        float2 a2 = stats[lra * 4 + 2], a3 = stats[lra * 4 + 3];
        float mu1 = (a0.x + a1.x + a2.x + a3.x) * (1.0f / 256.0f);
        float iv1 = rsqrtf((a0.y + a1.y + a2.y + a3.y) * (1.0f / 256.0f) - mu1 * mu1 + 1e-5f);
        float2 c0 = stats[(lra + 8) * 4 + 0], c1 = stats[(lra + 8) * 4 + 1];
        float2 c2 = stats[(lra + 8) * 4 + 2], c3 = stats[(lra + 8) * 4 + 3];
        float mu2 = (c0.x + c1.x + c2.x + c3.x) * (1.0f / 256.0f);
        float iv2 = rsqrtf((c0.y + c1.y + c2.y + c3.y) * (1.0f / 256.0f) - mu2 * mu2 + 1e-5f);

        int b1 = 0, n1 = 0, b2 = 0, n2 = 0;
        if (FINAL) { b1 = r1 / SQ; n1 = r1 - b1 * SQ; b2 = r2 / SQ; n2 = r2 - b2 * SQ; }

#pragma unroll
        for (int nf = 0; nf < 8; nf++) {
            const int col = wn * 64 + nf * 8 + (lane & 3) * 2;
            float g0 = gbuf[col], g1 = gbuf[col + 1];
            float be0 = gbuf[256 + col], be1 = gbuf[256 + col + 1];
            float l10 = (acc[mf][nf][0] - mu1) * iv1 * g0 + be0;
            float l11 = (acc[mf][nf][1] - mu1) * iv1 * g1 + be1;
            float l20 = (acc[mf][nf][2] - mu2) * iv2 * g0 + be0;
            float l21 = (acc[mf][nf][3] - mu2) * iv2 * g1 + be1;
            if (!FINAL) {
                *(float2*)&xout[(size_t)r1 * DM + col] =
                    make_float2(acc[mf][nf][0], acc[mf][nf][1]);
                *(float2*)&xout[(size_t)r2 * DM + col] =
                    make_float2(acc[mf][nf][2], acc[mf][nf][3]);
                *(__half2*)&lnh_out[(size_t)r1 * DM + col] = __floats2half2_rn(l10, l11);
                *(__half2*)&lnh_out[(size_t)r2 * DM + col] = __floats2half2_rn(l20, l21);
            } else {
                *(float2*)&xout[(size_t)r1 * DM + col] = make_float2(l10, l11);
                *(float2*)&xout[(size_t)r2 * DM + col] = make_float2(l20, l21);
                if (n1 < NCV)
                    *(__half2*)&lnh_out[((size_t)(b1 * NCV + n1)) * 512 + 256 + col] =
                        __floats2half2_rn(l10, l11);
                if (n2 < NCV)
                    *(__half2*)&lnh_out[((size_t)(b2 * NCV + n2)) * 512 + 256 + col] =
                        __floats2half2_rn(l20, l21);
            }
        }
    }
}

// ======== patch GEMM: on-the-fly im2col A + bias + pos embed + entry LN ========
// Tile 64(M=img tokens of one batch) x 256(N), blockIdx.y = batch.
// A[t,k] = frame[b, k/256, (t/8)*16 + (k%256)/16, (t%8)*16 + k%16], K=768.
// out rows: x[b*320+256+t], lnh same rows. gam/bet = layer-0 ln1.
#define PATCH_A_OFF 0u          // 2 x 8KB A stages
#define PATCH_B_OFF 16384u      // 2 x 32KB B stages
#define PATCH_GB_OFF 81920u
#define PATCH_ST_OFF 83968u
#define PATCH_SMEM 86016u

__global__ void __launch_bounds__(256, 2) patchgemm_k(
    const float* __restrict__ frame, const __half* __restrict__ Bh,
    const float* __restrict__ bias,
    float* __restrict__ xout, __half* __restrict__ lnh_out,
    const float* __restrict__ gam, const float* __restrict__ bet) {
    extern __shared__ char sm[];
    const uint32_t smb = smem_u32(sm);
    const int tid = threadIdx.x;
    const int lane = tid & 31;
    const int w = tid >> 5;
    const int wm = w >> 2;
    const int wn = w & 3;
    const int b = blockIdx.y;
    const int nkt = 12;  // K = 768

    float* gbuf = (float*)(sm + PATCH_GB_OFF);
    float2* stats = (float2*)(sm + PATCH_ST_OFF);
    gbuf[tid] = gam[tid];
    gbuf[256 + tid] = bet[tid];

    float acc[2][8][4];
#pragma unroll
    for (int i = 0; i < 2; i++)
#pragma unroll
        for (int j = 0; j < 8; j++)
#pragma unroll
            for (int q = 0; q < 4; q++) acc[i][j][q] = 0.f;

    // A gather coords: 2 chunks per thread
    uint32_t acoff[2];
    int at[2], ack8[2];
#pragma unroll
    for (int j = 0; j < 2; j++) {
        int c = tid + 256 * j;
        at[j] = c >> 3;
        ack8[j] = c & 7;
        acoff[j] = (uint32_t)at[j] * 128u + (uint32_t)((ack8[j] ^ (at[j] & 7)) << 4);
    }
    // B copy coords: 8 chunks per thread
    uint32_t bcoff[8], bsrc[8];
#pragma unroll
    for (int j = 0; j < 8; j++) {
        int c = tid + 256 * j;
        int crow = c >> 3, ck8 = c & 7;
        bcoff[j] = (uint32_t)crow * 128u + (uint32_t)((ck8 ^ (crow & 7)) << 4);
        bsrc[j] = (uint32_t)crow * 768u + (uint32_t)(ck8 * 8);
    }

    float areg[2][8];
#define LOAD_A(kt)                                                             \
    do {                                                                       \
        _Pragma("unroll") for (int j = 0; j < 2; j++) {                        \
            int k0 = ((kt) * 8 + ack8[j]) * 8;                                 \
            int cch = k0 >> 8, rem = k0 & 255;                                 \
            int rr = rem >> 4, qq = rem & 15;                                  \
            const float* fp = frame +                                          \
                (((size_t)(b * 3 + cch) * 128 + (at[j] >> 3) * 16 + rr) * 128  \
                 + (at[j] & 7) * 16 + qq);                                     \
            float4 v0 = *(const float4*)fp;                                    \
            float4 v1 = *(const float4*)(fp + 4);                              \
            areg[j][0] = v0.x; areg[j][1] = v0.y; areg[j][2] = v0.z;           \
            areg[j][3] = v0.w; areg[j][4] = v1.x; areg[j][5] = v1.y;           \
            areg[j][6] = v1.z; areg[j][7] = v1.w;                              \
        }                                                                      \
    } while (0)

#define STS_A(kt)                                                              \
    do {                                                                       \
        const uint32_t sa = smb + (uint32_t)((kt) & 1) * 8192u;                \
        _Pragma("unroll") for (int j = 0; j < 2; j++) {                        \
            __half2 h0 = __floats2half2_rn(areg[j][0], areg[j][1]);            \
            __half2 h1 = __floats2half2_rn(areg[j][2], areg[j][3]);            \
            __half2 h2 = __floats2half2_rn(areg[j][4], areg[j][5]);            \
            __half2 h3 = __floats2half2_rn(areg[j][6], areg[j][7]);            \
            uint4 pk = make_uint4(*(uint32_t*)&h0, *(uint32_t*)&h1,            \
                                  *(uint32_t*)&h2, *(uint32_t*)&h3);           \
            *(uint4*)(sm + (sa - smb) + acoff[j]) = pk;                        \
        }                                                                      \
    } while (0)

#define ISSUE_B(kt)                                                            \
    do {                                                                       \
        const uint32_t kk0 = (uint32_t)(kt) << 6;                              \
        const uint32_t sb = smb + PATCH_B_OFF + (uint32_t)((kt) & 1) * 32768u; \
        _Pragma("unroll") for (int j = 0; j < 8; j++)                          \
            cp16(sb + bcoff[j], Bh + bsrc[j] + kk0);                           \
        asm volatile("cp.async.commit_group;" ::: "memory");                   \
    } while (0)

    LOAD_A(0);
    ISSUE_B(0);
    ISSUE_B(1);
    STS_A(0);

    const uint32_t rowAb[2] = {
        (uint32_t)(wm * 32 + 0  + (lane & 7) + ((lane >> 3) & 1) * 8) * 128u,
        (uint32_t)(wm * 32 + 16 + (lane & 7) + ((lane >> 3) & 1) * 8) * 128u};
    const int a_k8add = lane >> 4;
    uint32_t rowBb[4];
#pragma unroll
    for (int nfp = 0; nfp < 4; nfp++)
        rowBb[nfp] = (uint32_t)(wn * 64 + nfp * 16 + ((lane >> 4) << 3) + (lane & 7)) * 128u;
    const int b_k8add = (lane >> 3) & 1;
    const uint32_t swz = (uint32_t)(lane & 7);

    for (int kt = 0; kt < nkt; kt++) {
        if (kt + 1 < nkt) {
            asm volatile("cp.async.wait_group 1;" ::: "memory");
        } else {
            asm volatile("cp.async.wait_group 0;" ::: "memory");
        }
        __syncthreads();   // A(kt) STS'd + B(kt) landed

        if (kt + 1 < nkt) LOAD_A(kt + 1);

        const uint32_t sa = smb + (uint32_t)(kt & 1) * 8192u;
        const uint32_t sb = smb + PATCH_B_OFF + (uint32_t)(kt & 1) * 32768u;
#pragma unroll
        for (int ks = 0; ks < 4; ks++) {
            uint32_t ah[2][4];
#pragma unroll
            for (int mf = 0; mf < 2; mf++) {
                uint32_t off = rowAb[mf] +
                    ((((uint32_t)(ks * 2 + a_k8add)) ^ swz) << 4);
                ldsm4(ah[mf], sa + off);
            }
#pragma unroll
            for (int nfp = 0; nfp < 4; nfp++) {
                uint32_t off = rowBb[nfp] +
                    ((((uint32_t)(ks * 2 + b_k8add)) ^ swz) << 4);
                uint32_t bh[4];
                ldsm4(bh, sb + off);
#pragma unroll
                for (int mf = 0; mf < 2; mf++) {
                    mma16816(acc[mf][2 * nfp],     ah[mf], bh);
                    mma16816(acc[mf][2 * nfp + 1], ah[mf], bh + 2);
                }
            }
        }
        __syncthreads();   // done reading this kt's buffers
        if (kt + 1 < nkt) STS_A(kt + 1);
        if (kt + 2 < nkt) ISSUE_B(kt + 2);
    }
#undef LOAD_A
#undef STS_A
#undef ISSUE_B

    // ---- epilogue: bias + pos; entry LN; write x + lnh ----
#pragma unroll
    for (int mf = 0; mf < 2; mf++) {
        const int lra = wm * 32 + mf * 16 + (lane >> 2);   // token t1
        const int t1 = lra, t2 = lra + 8;
        float s1 = 0.f, q1 = 0.f, s2 = 0.f, q2 = 0.f;
#pragma unroll
        for (int nf = 0; nf < 8; nf++) {
            const int col = wn * 64 + nf * 8 + (lane & 3) * 2;
            float2 bb = *(const float2*)&bias[col];
            acc[mf][nf][0] += bb.x + pos2d_val(t1 >> 3, t1 & 7, col);
            acc[mf][nf][1] += bb.y + pos2d_val(t1 >> 3, t1 & 7, col + 1);
            acc[mf][nf][2] += bb.x + pos2d_val(t2 >> 3, t2 & 7, col);
            acc[mf][nf][3] += bb.y + pos2d_val(t2 >> 3, t2 & 7, col + 1);
            s1 += acc[mf][nf][0] + acc[mf][nf][1];
            q1 += acc[mf][nf][0] * acc[mf][nf][0] + acc[mf][nf][1] * acc[mf][nf][1];
            s2 += acc[mf][nf][2] + acc[mf][nf][3];
            q2 += acc[mf][nf][2] * acc[mf][nf][2] + acc[mf][nf][3] * acc[mf][nf][3];
        }
        s1 += __shfl_xor_sync(0xffffffffu, s1, 1); q1 += __shfl_xor_sync(0xffffffffu, q1, 1);
        s1 += __shfl_xor_sync(0xffffffffu, s1, 2); q1 += __shfl_xor_sync(0xffffffffu, q1, 2);
        s2 += __shfl_xor_sync(0xffffffffu, s2, 1); q2 += __shfl_xor_sync(0xffffffffu, q2, 1);
        s2 += __shfl_xor_sync(0xffffffffu, s2, 2); q2 += __shfl_xor_sync(0xffffffffu, q2, 2);
        if ((lane & 3) == 0) {
            stats[lra * 4 + wn] = make_float2(s1, q1);
            stats[(lra + 8) * 4 + wn] = make_float2(s2, q2);
        }
    }
    __syncthreads();

#pragma unroll
    for (int mf = 0; mf < 2; mf++) {
        const int lra = wm * 32 + mf * 16 + (lane >> 2);
        const int t1 = lra, t2 = lra + 8;
        const int r1 = b * SQ + NCV + t1;
        const int r2 = b * SQ + NCV + t2;
        float2 a0 = stats[lra * 4 + 0], a1 = stats[lra * 4 + 1];
        float2 a2 = stats[lra * 4 + 2], a3 = stats[lra * 4 + 3];
        float mu1 = (a0.x + a1.x + a2.x + a3.x) * (1.0f / 256.0f);
        float iv1 = rsqrtf((a0.y + a1.y + a2.y + a3.y) * (1.0f / 256.0f) - mu1 * mu1 + 1e-5f);
        float2 c0 = stats[(lra + 8) * 4 + 0], c1 = stats[(lra + 8) * 4 + 1];
        float2 c2 = stats[(lra + 8) * 4 + 2], c3 = stats[(lra + 8) * 4 + 3];
        float mu2 = (c0.x + c1.x + c2.x + c3.x) * (1.0f / 256.0f);
        float iv2 = rsqrtf((c0.y + c1.y + c2.y + c3.y) * (1.0f / 256.0f) - mu2 * mu2 + 1e-5f);

#pragma unroll
        for (int nf = 0; nf < 8; nf++) {
            const int col = wn * 64 + nf * 8 + (lane & 3) * 2;
            float g0 = gbuf[col], g1 = gbuf[col + 1];
            float be0 = gbuf[256 + col], be1 = gbuf[256 + col + 1];
            *(float2*)&xout[(size_t)r1 * DM + col] =
                make_float2(acc[mf][nf][0], acc[mf][nf][1]);
            *(float2*)&xout[(size_t)r2 * DM + col] =
                make_float2(acc[mf][nf][2], acc[mf][nf][3]);
            *(__half2*)&lnh_out[(size_t)r1 * DM + col] = __floats2half2_rn(
                (acc[mf][nf][0] - mu1) * iv1 * g0 + be0,
                (acc[mf][nf][1] - mu1) * iv1 * g1 + be1);
            *(__half2*)&lnh_out[(size_t)r2 * DM + col] = __floats2half2_rn(
                (acc[mf][nf][2] - mu2) * iv2 * g0 + be0,
                (acc[mf][nf][3] - mu2) * iv2 * g1 + be1);
        }
    }
}

// ---------------- host launcher ----------------
extern "C" void kernel_launch(void* const* d_in, const int* in_sizes, int n_in,
                              void* d_out, int out_size) {
    const float* h_map   = (const float*)d_in[0];
    const float* frame   = (const float*)d_in[1];
    const int*   idx     = (const int*)  d_in[2];
    const float* Wqkv    = (const float*)d_in[3];
    const float* bqkv    = (const float*)d_in[4];
    const float* Wo      = (const float*)d_in[5];
    const float* bo      = (const float*)d_in[6];
    const float* ln1g    = (const float*)d_in[7];
    const float* ln1b    = (const float*)d_in[8];
    const float* W1      = (const float*)d_in[9];
    const float* b1      = (const float*)d_in[10];
    const float* W2      = (const float*)d_in[11];
    const float* b2      = (const float*)d_in[12];
    const float* ln2g    = (const float*)d_in[13];
    const float* ln2b    = (const float*)d_in[14];
    const float* nfg     = (const float*)d_in[15];
    const float* nfb     = (const float*)d_in[16];
    const float* patch_w = (const float*)d_in[17];
    const float* patch_b = (const float*)d_in[18];
    const float* gate_w  = (const float*)d_in[19];
    const float* gate_b  = (const float*)d_in[20];
    float* out = (float*)d_out;

    float *x, *ln, *hcv;
    __half *lnh, *qkvh, *ath, *h1h, *cth, *wh;
    cudaGetSymbolAddress((void**)&x, g_x);
    cudaGetSymbolAddress((void**)&ln, g_ln);
    cudaGetSymbolAddress((void**)&hcv, g_hcv);
    cudaGetSymbolAddress((void**)&lnh, g_lnh);
    cudaGetSymbolAddress((void**)&qkvh, g_qkvh);
    cudaGetSymbolAddress((void**)&ath, g_ath);
    cudaGetSymbolAddress((void**)&h1h, g_h1h);
    cudaGetSymbolAddress((void**)&cth, g_cth);
    cudaGetSymbolAddress((void**)&wh, g_wh);

    cudaFuncSetAttribute(mma_gemm_k<EPL_GELU>,  cudaFuncAttributeMaxDynamicSharedMemorySize, GSMEM_BYTES);
    cudaFuncSetAttribute(mma_gemm_k<EPL_GATE>,  cudaFuncAttributeMaxDynamicSharedMemorySize, GSMEM_BYTES);
    cudaFuncSetAttribute(mma_gemm_k<EPL_QKVH>,  cudaFuncAttributeMaxDynamicSharedMemorySize, GSMEM_BYTES);
    cudaFuncSetAttribute(gemm64_resln_k<false>, cudaFuncAttributeMaxDynamicSharedMemorySize, GSMEM64);
    cudaFuncSetAttribute(gemm64_resln_k<true>,  cudaFuncAttributeMaxDynamicSharedMemorySize, GSMEM64);
    cudaFuncSetAttribute(patchgemm_k, cudaFuncAttributeMaxDynamicSharedMemorySize, PATCH_SMEM);
    cudaFuncSetAttribute(attn_fa_k, cudaFuncAttributeMaxDynamicSharedMemorySize, ATT_SMEM);

    // pass-through copy; gated scatter overwrites idx positions
    cudaMemcpyAsync(out, h_map, sizeof(float) * (size_t)BB * WSQ * DM,
                    cudaMemcpyDeviceToDevice, 0);

    wcvt_all_k<<<1261568 / 256, 256>>>(Wqkv, Wo, W1, W2, patch_w, gate_w, wh);

    // embed + entry LN for cv tokens
    embed_ln_k<<<2048, 256>>>(h_map, idx, hcv, cth, x, lnh, ln1g, ln1b);
    // patch GEMM (fused im2col + pos + entry LN) for img tokens
    patchgemm_k<<<dim3(1, 64), 256, PATCH_SMEM>>>(
        frame, wh + WOFF_PW, patch_b, x, lnh, ln1g, ln1b);

    const int NTOK = BB * SQ;  // 20480
    for (int l = 0; l < NDEPTH; l++) {
        mma_gemm_k<EPL_QKVH><<<dim3(6, 160), 256, GSMEM_BYTES>>>(
            lnh, wh + WOFF_QKV + (size_t)l * 196608,
            bqkv + l * 768, nullptr, qkvh,
            NTOK, 768, 256, nullptr, nullptr, nullptr);
        attn_fa_k<<<BB * NHEADS, 320, ATT_SMEM>>>(qkvh, ath);
        gemm64_resln_k<false><<<dim3(1, NTOK / 64), 256, GSMEM64>>>(
            ath, wh + WOFF_WO + (size_t)l * 65536, bo + l * 256,
            x, x, lnh, 256, ln2g + l * 256, ln2b + l * 256);
        mma_gemm_k<EPL_GELU><<<dim3(8, 160), 256, GSMEM_BYTES>>>(
            lnh, wh + WOFF_W1 + (size_t)l * 262144,
            b1 + l * 1024, nullptr, h1h,
            NTOK, 1024, 256, nullptr, nullptr, nullptr);
        if (l + 1 < NDEPTH) {
            gemm64_resln_k<false><<<dim3(1, NTOK / 64), 256, GSMEM64>>>(
                h1h, wh + WOFF_W2 + (size_t)l * 262144, b2 + l * 256,
                x, x, lnh, 1024, ln1g + (l + 1) * 256, ln1b + (l + 1) * 256);
        } else {
            gemm64_resln_k<true><<<dim3(1, NTOK / 64), 256, GSMEM64>>>(
                h1h, wh + WOFF_W2 + (size_t)l * 262144, b2 + l * 256,
                x, ln, cth, 1024, nfg, nfb);
        }
    }

    mma_gemm_k<EPL_GATE><<<dim3(2, 128), 256, GSMEM_BYTES>>>(
        cth, wh + WOFF_GW, gate_b, out, nullptr,
        16384, 256, 512, hcv, ln, idx);
}

// round 12
// speedup vs baseline: 1.1547x; 1.0119x over previous
#include <cuda_runtime.h>
#include <cuda_fp16.h>
#include <math.h>
#include <stdint.h>

#define BB 64
#define SQ 320
#define NCV 256
#define DM 256
#define HIDN 1024
#define NHEADS 8
#define NDEPTH 6
#define WSQ 1089

// ---------------- device scratch ----------------
__device__ float g_x[(size_t)BB * SQ * DM];
__device__ float g_ln[(size_t)BB * SQ * DM];
__device__ float g_hcv[(size_t)BB * NCV * DM];

__device__ __half g_lnh[(size_t)BB * SQ * DM];
__device__ __half g_qkvh[(size_t)BB * SQ * 3 * DM];
__device__ __half g_ath[(size_t)BB * SQ * DM];
__device__ __half g_h1h[(size_t)BB * SQ * HIDN];
__device__ __half g_cth[(size_t)BB * NCV * 2 * DM];

#define WOFF_QKV   0u
#define WOFF_WO    1179648u
#define WOFF_W1    1572864u
#define WOFF_W2    3145728u
#define WOFF_PW    4718592u
#define WOFF_GW    4915200u
#define WPOOL_N    5046272u
__device__ __half g_wh[WPOOL_N];

// ---------------- helpers ----------------
__device__ __forceinline__ float pos2d_val(int yy, int xx, int d) {
    int dd = d & 127;
    int i = dd >> 1;
    float freq = expf((float)(2 * i) * (-0.07195578415606394f));
    float coord = (d < 128) ? (float)yy : (float)xx;
    float ang = coord * freq;
    return (d & 1) ? cosf(ang) : sinf(ang);
}

__device__ __forceinline__ float gelu_exact(float v) {
    return 0.5f * v * (1.0f + erff(v * 0.70710678118654752f));
}

__device__ __forceinline__ uint32_t smem_u32(const void* p) {
    uint32_t a;
    asm("{ .reg .u64 t; cvta.to.shared.u64 t, %1; cvt.u32.u64 %0, t; }" : "=r"(a) : "l"(p));
    return a;
}

__device__ __forceinline__ void cp16(uint32_t dst, const void* src) {
    asm volatile("cp.async.cg.shared.global [%0], [%1], 16;" :: "r"(dst), "l"(src));
}

__device__ __forceinline__ void ldsm4(uint32_t* r, uint32_t addr) {
    asm volatile("ldmatrix.sync.aligned.m8n8.x4.shared.b16 {%0,%1,%2,%3}, [%4];"
                 : "=r"(r[0]), "=r"(r[1]), "=r"(r[2]), "=r"(r[3]) : "r"(addr));
}

__device__ __forceinline__ void ldsm4t(uint32_t* r, uint32_t addr) {
    asm volatile("ldmatrix.sync.aligned.m8n8.x4.trans.shared.b16 {%0,%1,%2,%3}, [%4];"
                 : "=r"(r[0]), "=r"(r[1]), "=r"(r[2]), "=r"(r[3]) : "r"(addr));
}

__device__ __forceinline__ void mma16816(float* c, const uint32_t* a, const uint32_t* b) {
    asm volatile(
        "mma.sync.aligned.m16n8k16.row.col.f32.f16.f16.f32 "
        "{%0,%1,%2,%3}, {%4,%5,%6,%7}, {%8,%9}, {%0,%1,%2,%3};\n"
        : "+f"(c[0]), "+f"(c[1]), "+f"(c[2]), "+f"(c[3])
        : "r"(a[0]), "r"(a[1]), "r"(a[2]), "r"(a[3]), "r"(b[0]), "r"(b[1]));
}

// ---------------- ALL weights fp32 -> fp16, one launch ----------------
__global__ void __launch_bounds__(256) wcvt_all_k(
    const float* __restrict__ s0, const float* __restrict__ s1,
    const float* __restrict__ s2, const float* __restrict__ s3,
    const float* __restrict__ s4, const float* __restrict__ s5,
    __half* __restrict__ h) {
    int i = blockIdx.x * 256 + threadIdx.x;
    const float* src;
    int base;
    if (i < 393216) {
        if (i < 294912) { src = s0; base = 0; }
        else            { src = s1; base = 294912; }
    } else if (i < 1179648) {
        if (i < 786432) { src = s2; base = 393216; }
        else            { src = s3; base = 786432; }
    } else {
        if (i < 1228800) { src = s4; base = 1179648; }
        else             { src = s5; base = 1228800; }
    }
    float4 v = ((const float4*)src)[i - base];
    __half2* hp = (__half2*)(h + (size_t)i * 4);
    hp[0] = __floats2half2_rn(v.x, v.y);
    hp[1] = __floats2half2_rn(v.z, v.w);
}

// ---------------- copy h_map->out + embed + entry LN (one kernel) ----------------
// blocks [0, 8712): copy 8 rows each (warp per row, 64*1089 = 69696 rows)
// blocks [8712, 8712+2048): embed+LN for cv tokens (warp per token)
#define COPY_BLKS 8712
__global__ void __launch_bounds__(256) copyembed_k(const float* __restrict__ h_map,
                                                   float* __restrict__ out,
                                                   const int* __restrict__ idx,
                                                   float* __restrict__ hcv,
                                                   __half* __restrict__ cth,
                                                   float* __restrict__ x,
                                                   __half* __restrict__ lnh,
                                                   const float* __restrict__ gam,
                                                   const float* __restrict__ bet) {
    int warp = threadIdx.x >> 5;
    int lane = threadIdx.x & 31;
    if (blockIdx.x < COPY_BLKS) {
        int row = blockIdx.x * 8 + warp;   // < 69696
        const float4* s = (const float4*)(h_map + (size_t)row * DM) + lane;
        float4* d = (float4*)(out + (size_t)row * DM) + lane;
        d[0] = s[0];
        d[32] = s[32];
        return;
    }
    int tok = (blockIdx.x - COPY_BLKS) * 8 + warp;   // 0..16383
    int b = tok >> 8, n = tok & 255;
    int p = idx[n];
    int yy = p / 33, xx = p % 33;
    const float* hp = h_map + ((size_t)b * WSQ + p) * DM;
    float v[8];
    float sum = 0.f, sq = 0.f;
#pragma unroll
    for (int i = 0; i < 8; i++) {
        int d = lane + 32 * i;
        float h = hp[d];
        hcv[((size_t)tok) * DM + d] = h;
        cth[((size_t)tok) * 512 + d] = __float2half_rn(h);
        float xv = h + pos2d_val(yy, xx, d);
        v[i] = xv;
        x[((size_t)(b * SQ + n)) * DM + d] = xv;
        sum += xv;
        sq += xv * xv;
    }
#pragma unroll
    for (int off = 16; off; off >>= 1) {
        sum += __shfl_xor_sync(0xffffffffu, sum, off);
        sq  += __shfl_xor_sync(0xffffffffu, sq, off);
    }
    float mu = sum * (1.0f / 256.0f);
    float var = sq * (1.0f / 256.0f) - mu * mu;
    float inv = rsqrtf(var + 1e-5f);
#pragma unroll
    for (int i = 0; i < 8; i++) {
        int d = lane + 32 * i;
        lnh[((size_t)(b * SQ + n)) * DM + d] =
            __float2half_rn((v[i] - mu) * inv * gam[d] + bet[d]);
    }
}

// ================= fused flash attention (mma.sync fp16) =================
#define ATT_RS 80u
#define ATT_TEN (320u * ATT_RS)
#define ATT_SMEM (3u * ATT_TEN)

__global__ void __launch_bounds__(320) attn_fa_k(const __half* __restrict__ qkvh,
                                                 __half* __restrict__ oh) {
    extern __shared__ char sm[];
    const uint32_t smb = smem_u32(sm);
    const int b = blockIdx.x >> 3;
    const int h = blockIdx.x & 7;
    const int tid = threadIdx.x;
    const int l = tid & 31;
    const int w = tid >> 5;

#pragma unroll
    for (int j = 0; j < 12; j++) {
        int c = j * 320 + tid;
        int tz = c / 1280;
        int rem = c - tz * 1280;
        int r = rem >> 2;
        int ch = rem & 3;
        const __half* src = qkvh + (size_t)(b * SQ + r) * 768 + tz * 256 + h * 32 + ch * 8;
        cp16(smb + (uint32_t)tz * ATT_TEN + (uint32_t)r * ATT_RS + (uint32_t)ch * 16u, src);
    }
    asm volatile("cp.async.commit_group;" ::: "memory");
    asm volatile("cp.async.wait_group 0;" ::: "memory");
    __syncthreads();

    const uint32_t smQ = smb, smK = smb + ATT_TEN, smV = smb + 2 * ATT_TEN;
    const int q0 = w * 32;

    uint32_t aq[2][2][4];
#pragma unroll
    for (int mf = 0; mf < 2; mf++)
#pragma unroll
        for (int kc = 0; kc < 2; kc++) {
            uint32_t addr = smQ +
                (uint32_t)(q0 + mf * 16 + (l & 7) + ((l >> 3) & 1) * 8) * ATT_RS +
                (uint32_t)(kc * 2 + (l >> 4)) * 16u;
            ldsm4(aq[mf][kc], addr);
        }

    float mrow[2][2] = {{-1e30f, -1e30f}, {-1e30f, -1e30f}};
    float lrow[2][2] = {{0.f, 0.f}, {0.f, 0.f}};
    float acc_o[2][4][4];
#pragma unroll
    for (int mf = 0; mf < 2; mf++)
#pragma unroll
        for (int db = 0; db < 4; db++)
#pragma unroll
            for (int q = 0; q < 4; q++) acc_o[mf][db][q] = 0.f;

    for (int ck = 0; ck < 320; ck += 64) {
        float s[2][8][4];
#pragma unroll
        for (int mf = 0; mf < 2; mf++)
#pragma unroll
            for (int nb = 0; nb < 8; nb++)
#pragma unroll
                for (int q = 0; q < 4; q++) s[mf][nb][q] = 0.f;

#pragma unroll
        for (int g = 0; g < 4; g++) {
#pragma unroll
            for (int ks = 0; ks < 2; ks++) {
                uint32_t bk[4];
                uint32_t addr = smK +
                    (uint32_t)(ck + g * 16 + ((l >> 4) << 3) + (l & 7)) * ATT_RS +
                    (uint32_t)(ks * 2 + ((l >> 3) & 1)) * 16u;
                ldsm4(bk, addr);
#pragma unroll
                for (int mf = 0; mf < 2; mf++) {
                    mma16816(s[mf][2 * g],     aq[mf][ks], bk);
                    mma16816(s[mf][2 * g + 1], aq[mf][ks], bk + 2);
                }
            }
        }

        uint32_t ap[2][4][4];
#pragma unroll
        for (int mf = 0; mf < 2; mf++) {
#pragma unroll
            for (int hh = 0; hh < 2; hh++) {
                float mx = -1e30f;
#pragma unroll
                for (int nb = 0; nb < 8; nb++) {
                    mx = fmaxf(mx, fmaxf(s[mf][nb][hh * 2], s[mf][nb][hh * 2 + 1]));
                }
                mx = fmaxf(mx, __shfl_xor_sync(0xffffffffu, mx, 1));
                mx = fmaxf(mx, __shfl_xor_sync(0xffffffffu, mx, 2));
                float mnew = fmaxf(mrow[mf][hh], mx);
                float corr = __expf(mrow[mf][hh] - mnew);
                mrow[mf][hh] = mnew;
                float lsum = 0.f;
#pragma unroll
                for (int nb = 0; nb < 8; nb++) {
                    float p0 = __expf(s[mf][nb][hh * 2]     - mnew);
                    float p1 = __expf(s[mf][nb][hh * 2 + 1] - mnew);
                    s[mf][nb][hh * 2] = p0;
                    s[mf][nb][hh * 2 + 1] = p1;
                    lsum += p0 + p1;
                }
                lsum += __shfl_xor_sync(0xffffffffu, lsum, 1);
                lsum += __shfl_xor_sync(0xffffffffu, lsum, 2);
                lrow[mf][hh] = lrow[mf][hh] * corr + lsum;
#pragma unroll
                for (int db = 0; db < 4; db++) {
                    acc_o[mf][db][hh * 2]     *= corr;
                    acc_o[mf][db][hh * 2 + 1] *= corr;
                }
            }
#pragma unroll
            for (int g = 0; g < 4; g++) {
                __half2 h0 = __floats2half2_rn(s[mf][2 * g][0],     s[mf][2 * g][1]);
                __half2 h1 = __floats2half2_rn(s[mf][2 * g][2],     s[mf][2 * g][3]);
                __half2 h2 = __floats2half2_rn(s[mf][2 * g + 1][0], s[mf][2 * g + 1][1]);
                __half2 h3 = __floats2half2_rn(s[mf][2 * g + 1][2], s[mf][2 * g + 1][3]);
                ap[mf][g][0] = *(uint32_t*)&h0;
                ap[mf][g][1] = *(uint32_t*)&h1;
                ap[mf][g][2] = *(uint32_t*)&h2;
                ap[mf][g][3] = *(uint32_t*)&h3;
            }
        }

#pragma unroll
        for (int g = 0; g < 4; g++) {
#pragma unroll
            for (int dd = 0; dd < 2; dd++) {
                uint32_t bv[4];
                uint32_t addr = smV +
                    (uint32_t)(ck + g * 16 + ((l >> 3) & 1) * 8 + (l & 7)) * ATT_RS +
                    (uint32_t)(dd * 2 + (l >> 4)) * 16u;
                ldsm4t(bv, addr);
#pragma unroll
                for (int mf = 0; mf < 2; mf++) {
                    mma16816(acc_o[mf][dd * 2],     ap[mf][g], bv);
                    mma16816(acc_o[mf][dd * 2 + 1], ap[mf][g], bv + 2);
                }
            }
        }
    }

#pragma unroll
    for (int mf = 0; mf < 2; mf++) {
#pragma unroll
        for (int hh = 0; hh < 2; hh++) {
            float inv = 1.f / lrow[mf][hh];
            int tok = q0 + mf * 16 + (l >> 2) + hh * 8;
            __half* op = oh + (size_t)(b * SQ + tok) * DM + h * 32 + 2 * (l & 3);
#pragma unroll
            for (int db = 0; db < 4; db++) {
                __half2 r = __floats2half2_rn(acc_o[mf][db][hh * 2] * inv,
                                              acc_o[mf][db][hh * 2 + 1] * inv);
                *(__half2*)(op + db * 8) = r;
            }
        }
    }
}

// ================= HMMA fp16 pipelined GEMM (128x128, 2 CTA/SM) =================
enum { EPL_GELU = 2, EPL_GATE = 4, EPL_QKVH = 5 };

#define STG_B 32768u
#define GSMEM_BYTES (3u * STG_B)

template <int MODE>
__device__ __forceinline__ void epi_store2(
    float* __restrict__ out, __half* __restrict__ outh,
    int N, int row, int col, float vx, float vy,
    const float* __restrict__ bias, const float* __restrict__ res,
    const float* __restrict__ extra, const int* __restrict__ idx) {
    float2 bb = *(const float2*)(bias + col);
    vx += bb.x;
    vy += bb.y;
    if (MODE == EPL_GELU) {
        *(__half2*)&outh[(size_t)row * N + col] =
            __floats2half2_rn(gelu_exact(vx), gelu_exact(vy));
    } else if (MODE == EPL_QKVH) {
        float sc = (col < 256) ? 0.17677669529663687f : 1.0f;
        *(__half2*)&outh[(size_t)row * N + col] = __floats2half2_rn(vx * sc, vy * sc);
    } else {  // EPL_GATE
        int b = row >> 8, n = row & 255;
        int p = idx[n];
        float2 hc = *(const float2*)&res[(size_t)row * DM + col];
        float2 hn = *(const float2*)&extra[((size_t)(b * SQ + n)) * DM + col];
        float g0 = 1.f / (1.f + expf(-vx));
        float g1 = 1.f / (1.f + expf(-vy));
        float2 r;
        r.x = hc.x + g0 * (hn.x - hc.x);
        r.y = hc.y + g1 * (hn.y - hc.y);
        *(float2*)&out[((size_t)b * WSQ + p) * DM + col] = r;
    }
}

template <int MODE>
__global__ void __launch_bounds__(256, 2) mma_gemm_k(
    const __half* __restrict__ Ah, const __half* __restrict__ Bh,
    const float* __restrict__ bias, float* __restrict__ out,
    __half* __restrict__ outh,
    int M, int N, int K,
    const float* __restrict__ res, const float* __restrict__ extra,
    const int* __restrict__ idx) {
    extern __shared__ char sm[];
    const uint32_t smb = smem_u32(sm);
    const int tid = threadIdx.x;
    const int lane = tid & 31;
    const int w = tid >> 5;
    const int wm = w >> 1;
    const int wn = w & 1;
    const int m0 = blockIdx.y * 128;
    const int n0 = blockIdx.x * 128;

    float acc[2][8][4];
#pragma unroll
    for (int i = 0; i < 2; i++)
#pragma unroll
        for (int j = 0; j < 8; j++)
#pragma unroll
            for (int q = 0; q < 4; q++) acc[i][j][q] = 0.f;

    const int nkt = K >> 6;

    // compressed copy addressing: chunk j offsets are affine
    const uint32_t crow0 = (uint32_t)(tid >> 3);
    const uint32_t ck8i = (uint32_t)(tid & 7);
    const uint32_t coff0 = crow0 * 128u + ((ck8i ^ (crow0 & 7)) << 4);
    const uint32_t asrc0 = (uint32_t)(m0 + (int)crow0) * (uint32_t)K + ck8i * 8u;
    const uint32_t bsrc0 = (uint32_t)(n0 + (int)crow0) * (uint32_t)K + ck8i * 8u;
    const uint32_t kst = 32u * (uint32_t)K;

#define ISSUE_STAGE(kt)                                                        \
    do {                                                                       \
        const uint32_t kk0 = (uint32_t)(kt) << 6;                              \
        const uint32_t sb = smb + (uint32_t)((kt) % 3) * STG_B;                \
        _Pragma("unroll") for (uint32_t j = 0; j < 4; j++) {                   \
            cp16(sb + coff0 + 4096u * j,           Ah + asrc0 + kk0 + kst * j);\
            cp16(sb + 16384u + coff0 + 4096u * j,  Bh + bsrc0 + kk0 + kst * j);\
        }                                                                      \
        asm volatile("cp.async.commit_group;" ::: "memory");                   \
    } while (0)

    ISSUE_STAGE(0);
    ISSUE_STAGE(1);

    const uint32_t rowAb[2] = {
        (uint32_t)(wm * 32 + 0  + (lane & 7) + ((lane >> 3) & 1) * 8) * 128u,
        (uint32_t)(wm * 32 + 16 + (lane & 7) + ((lane >> 3) & 1) * 8) * 128u};
    const int a_k8add = lane >> 4;
    uint32_t rowBb[4];
#pragma unroll
    for (int nfp = 0; nfp < 4; nfp++)
        rowBb[nfp] = (uint32_t)(wn * 64 + nfp * 16 + ((lane >> 4) << 3) + (lane & 7)) * 128u;
    const int b_k8add = (lane >> 3) & 1;
    const uint32_t swz = (uint32_t)(lane & 7);

    for (int kt = 0; kt < nkt; kt++) {
        if (kt + 1 < nkt) {
            asm volatile("cp.async.wait_group 1;" ::: "memory");
        } else {
            asm volatile("cp.async.wait_group 0;" ::: "memory");
        }
        __syncthreads();
        if (kt + 2 < nkt) ISSUE_STAGE(kt + 2);

        const uint32_t sb = smb + (uint32_t)(kt % 3) * STG_B;

        // hoist ALL A fragments of this k-tile (breaks A-ldsm off critical path)
        uint32_t ahh[4][2][4];
#pragma unroll
        for (int ks = 0; ks < 4; ks++)
#pragma unroll
            for (int mf = 0; mf < 2; mf++) {
                uint32_t off = rowAb[mf] +
                    ((((uint32_t)(ks * 2 + a_k8add)) ^ swz) << 4);
                ldsm4(ahh[ks][mf], sb + off);
            }

#pragma unroll
        for (int ks = 0; ks < 4; ks++) {
#pragma unroll
            for (int nfp = 0; nfp < 4; nfp++) {
                uint32_t off = rowBb[nfp] +
                    ((((uint32_t)(ks * 2 + b_k8add)) ^ swz) << 4);
                uint32_t bh[4];
                ldsm4(bh, sb + 16384u + off);
#pragma unroll
                for (int mf = 0; mf < 2; mf++) {
                    mma16816(acc[mf][2 * nfp],     ahh[ks][mf], bh);
                    mma16816(acc[mf][2 * nfp + 1], ahh[ks][mf], bh + 2);
                }
            }
        }
    }
#undef ISSUE_STAGE

#pragma unroll
    for (int mf = 0; mf < 2; mf++) {
        int row = m0 + wm * 32 + mf * 16 + (lane >> 2);
#pragma unroll
        for (int nf = 0; nf < 8; nf++) {
            int col = n0 + wn * 64 + nf * 8 + (lane & 3) * 2;
            epi_store2<MODE>(out, outh, N, row, col,
                             acc[mf][nf][0], acc[mf][nf][1], bias, res, extra, idx);
            epi_store2<MODE>(out, outh, N, row + 8, col,
                             acc[mf][nf][2], acc[mf][nf][3], bias, res, extra, idx);
        }
    }
}

// ======== fused GEMM(64x256) + bias + residual + LayerNorm ========
#define STG64_B 40960u
#define GB64_OFF (2u * STG64_B)
#define ST64_OFF (GB64_OFF + 2048u)
#define GSMEM64 (ST64_OFF + 2048u)

template <bool FINAL>
__global__ void __launch_bounds__(256, 2) gemm64_resln_k(
    const __half* __restrict__ Ah, const __half* __restrict__ Bh,
    const float* __restrict__ bias,
    const float* res, float* xout, __half* __restrict__ lnh_out,
    int K, const float* __restrict__ gam, const float* __restrict__ bet) {
    extern __shared__ char sm[];
    const uint32_t smb = smem_u32(sm);
    const int tid = threadIdx.x;
    const int lane = tid & 31;
    const int w = tid >> 5;
    const int wm = w >> 2;
    const int wn = w & 3;
    const int m0 = blockIdx.y * 64;

    float* gbuf = (float*)(sm + GB64_OFF);
    float2* stats = (float2*)(sm + ST64_OFF);
    gbuf[tid] = gam[tid];
    gbuf[256 + tid] = bet[tid];

    float acc[2][8][4];
#pragma unroll
    for (int i = 0; i < 2; i++)
#pragma unroll
        for (int j = 0; j < 8; j++)
#pragma unroll
            for (int q = 0; q < 4; q++) acc[i][j][q] = 0.f;

    const int nkt = K >> 6;

    const uint32_t crow0 = (uint32_t)(tid >> 3);
    const uint32_t ck8i = (uint32_t)(tid & 7);
    const uint32_t coff0 = crow0 * 128u + ((ck8i ^ (crow0 & 7)) << 4);
    const uint32_t asrc0 = (uint32_t)(m0 + (int)crow0) * (uint32_t)K + ck8i * 8u;
    const uint32_t bsrc0 = crow0 * (uint32_t)K + ck8i * 8u;
    const uint32_t kst = 32u * (uint32_t)K;

#define ISSUE64(kt)                                                            \
    do {                                                                       \
        const uint32_t kk0 = (uint32_t)(kt) << 6;                              \
        const uint32_t sb = smb + (uint32_t)((kt) & 1) * STG64_B;              \
        _Pragma("unroll") for (uint32_t j = 0; j < 2; j++)                     \
            cp16(sb + coff0 + 4096u * j, Ah + asrc0 + kk0 + kst * j);          \
        _Pragma("unroll") for (uint32_t j = 0; j < 8; j++)                     \
            cp16(sb + 8192u + coff0 + 4096u * j, Bh + bsrc0 + kk0 + kst * j);  \
        asm volatile("cp.async.commit_group;" ::: "memory");                   \
    } while (0)

    ISSUE64(0);
    ISSUE64(1);

    const uint32_t rowAb[2] = {
        (uint32_t)(wm * 32 + 0  + (lane & 7) + ((lane >> 3) & 1) * 8) * 128u,
        (uint32_t)(wm * 32 + 16 + (lane & 7) + ((lane >> 3) & 1) * 8) * 128u};
    const int a_k8add = lane >> 4;
    uint32_t rowBb[4];
#pragma unroll
    for (int nfp = 0; nfp < 4; nfp++)
        rowBb[nfp] = (uint32_t)(wn * 64 + nfp * 16 + ((lane >> 4) << 3) + (lane & 7)) * 128u;
    const int b_k8add = (lane >> 3) & 1;
    const uint32_t swz = (uint32_t)(lane & 7);

    for (int kt = 0; kt < nkt; kt++) {
        if (kt + 1 < nkt) {
            asm volatile("cp.async.wait_group 1;" ::: "memory");
        } else {
            asm volatile("cp.async.wait_group 0;" ::: "memory");
        }
        __syncthreads();

        const uint32_t sb = smb + (uint32_t)(kt & 1) * STG64_B;

        uint32_t ahh[4][2][4];
#pragma unroll
        for (int ks = 0; ks < 4; ks++)
#pragma unroll
            for (int mf = 0; mf < 2; mf++) {
                uint32_t off = rowAb[mf] +
                    ((((uint32_t)(ks * 2 + a_k8add)) ^ swz) << 4);
                ldsm4(ahh[ks][mf], sb + off);
            }

#pragma unroll
        for (int ks = 0; ks < 4; ks++) {
#pragma unroll
            for (int nfp = 0; nfp < 4; nfp++) {
                uint32_t off = rowBb[nfp] +
                    ((((uint32_t)(ks * 2 + b_k8add)) ^ swz) << 4);
                uint32_t bh[4];
                ldsm4(bh, sb + 8192u + off);
#pragma unroll
                for (int mf = 0; mf < 2; mf++) {
                    mma16816(acc[mf][2 * nfp],     ahh[ks][mf], bh);
                    mma16816(acc[mf][2 * nfp + 1], ahh[ks][mf], bh + 2);
                }
            }
        }
        __syncthreads();
        if (kt + 2 < nkt) ISSUE64(kt + 2);
    }
#undef ISSUE64

#pragma unroll
    for (int mf = 0; mf < 2; mf++) {
        const int lra = wm * 32 + mf * 16 + (lane >> 2);
        const int r1 = m0 + lra;
        const int r2 = r1 + 8;
        float s1 = 0.f, q1 = 0.f, s2 = 0.f, q2 = 0.f;
#pragma unroll
        for (int nf = 0; nf < 8; nf++) {
            const int col = wn * 64 + nf * 8 + (lane & 3) * 2;
            float2 bb = *(const float2*)&bias[col];
            float2 e1 = *(const float2*)&res[(size_t)r1 * DM + col];
            float2 e2 = *(const float2*)&res[(size_t)r2 * DM + col];
            acc[mf][nf][0] += bb.x + e1.x;
            acc[mf][nf][1] += bb.y + e1.y;
            acc[mf][nf][2] += bb.x + e2.x;
            acc[mf][nf][3] += bb.y + e2.y;
            s1 += acc[mf][nf][0] + acc[mf][nf][1];
            q1 += acc[mf][nf][0] * acc[mf][nf][0] + acc[mf][nf][1] * acc[mf][nf][1];
            s2 += acc[mf][nf][2] + acc[mf][nf][3];
            q2 += acc[mf][nf][2] * acc[mf][nf][2] + acc[mf][nf][3] * acc[mf][nf][3];
        }
        s1 += __shfl_xor_sync(0xffffffffu, s1, 1); q1 += __shfl_xor_sync(0xffffffffu, q1, 1);
        s1 += __shfl_xor_sync(0xffffffffu, s1, 2); q1 += __shfl_xor_sync(0xffffffffu, q1, 2);
        s2 += __shfl_xor_sync(0xffffffffu, s2, 1); q2 += __shfl_xor_sync(0xffffffffu, q2, 1);
        s2 += __shfl_xor_sync(0xffffffffu, s2, 2); q2 += __shfl_xor_sync(0xffffffffu, q2, 2);
        if ((lane & 3) == 0) {
            stats[lra * 4 + wn] = make_float2(s1, q1);
            stats[(lra + 8) * 4 + wn] = make_float2(s2, q2);
        }
    }
    __syncthreads();

#pragma unroll
    for (int mf = 0; mf < 2; mf++) {
        const int lra = wm * 32 + mf * 16 + (lane >> 2);
        const int r1 = m0 + lra, r2 = r1 + 8;
        float2 a0 = stats[lra * 4 + 0], a1 = stats[lra * 4 + 1];
        float2 a2 = stats[lra * 4 + 2], a3 = stats[lra * 4 + 3];
        float mu1 = (a0.x + a1.x + a2.x + a3.x) * (1.0f / 256.0f);
        float iv1 = rsqrtf((a0.y + a1.y + a2.y + a3.y) * (1.0f / 256.0f) - mu1 * mu1 + 1e-5f);
        float2 c0 = stats[(lra + 8) * 4 + 0], c1 = stats[(lra + 8) * 4 + 1];
        float2 c2 = stats[(lra + 8) * 4 + 2], c3 = stats[(lra + 8) * 4 + 3];
        float mu2 = (c0.x + c1.x + c2.x + c3.x) * (1.0f / 256.0f);
        float iv2 = rsqrtf((c0.y + c1.y + c2.y + c3.y) * (1.0f / 256.0f) - mu2 * mu2 + 1e-5f);

        int b1 = 0, n1 = 0, b2 = 0, n2 = 0;
        if (FINAL) { b1 = r1 / SQ; n1 = r1 - b1 * SQ; b2 = r2 / SQ; n2 = r2 - b2 * SQ; }

#pragma unroll
        for (int nf = 0; nf < 8; nf++) {
            const int col = wn * 64 + nf * 8 + (lane & 3) * 2;
            float g0 = gbuf[col], g1 = gbuf[col + 1];
            float be0 = gbuf[256 + col], be1 = gbuf[256 + col + 1];
            float l10 = (acc[mf][nf][0] - mu1) * iv1 * g0 + be0;
            float l11 = (acc[mf][nf][1] - mu1) * iv1 * g1 + be1;
            float l20 = (acc[mf][nf][2] - mu2) * iv2 * g0 + be0;
            float l21 = (acc[mf][nf][3] - mu2) * iv2 * g1 + be1;
            if (!FINAL) {
                *(float2*)&xout[(size_t)r1 * DM + col] =
                    make_float2(acc[mf][nf][0], acc[mf][nf][1]);
                *(float2*)&xout[(size_t)r2 * DM + col] =
                    make_float2(acc[mf][nf][2], acc[mf][nf][3]);
                *(__half2*)&lnh_out[(size_t)r1 * DM + col] = __floats2half2_rn(l10, l11);
                *(__half2*)&lnh_out[(size_t)r2 * DM + col] = __floats2half2_rn(l20, l21);
            } else {
                *(float2*)&xout[(size_t)r1 * DM + col] = make_float2(l10, l11);
                *(float2*)&xout[(size_t)r2 * DM + col] = make_float2(l20, l21);
                if (n1 < NCV)
                    *(__half2*)&lnh_out[((size_t)(b1 * NCV + n1)) * 512 + 256 + col] =
                        __floats2half2_rn(l10, l11);
                if (n2 < NCV)
                    *(__half2*)&lnh_out[((size_t)(b2 * NCV + n2)) * 512 + 256 + col] =
                        __floats2half2_rn(l20, l21);
            }
        }
    }
}

// ======== patch GEMM: on-the-fly im2col A + bias + pos + entry LN ========
#define PATCH_B_OFF 16384u
#define PATCH_GB_OFF 81920u
#define PATCH_ST_OFF 83968u
#define PATCH_SMEM 86016u

__global__ void __launch_bounds__(256, 2) patchgemm_k(
    const float* __restrict__ frame, const __half* __restrict__ Bh,
    const float* __restrict__ bias,
    float* __restrict__ xout, __half* __restrict__ lnh_out,
    const float* __restrict__ gam, const float* __restrict__ bet) {
    extern __shared__ char sm[];
    const uint32_t smb = smem_u32(sm);
    const int tid = threadIdx.x;
    const int lane = tid & 31;
    const int w = tid >> 5;
    const int wm = w >> 2;
    const int wn = w & 3;
    const int b = blockIdx.y;
    const int nkt = 12;

    float* gbuf = (float*)(sm + PATCH_GB_OFF);
    float2* stats = (float2*)(sm + PATCH_ST_OFF);
    gbuf[tid] = gam[tid];
    gbuf[256 + tid] = bet[tid];

    float acc[2][8][4];
#pragma unroll
    for (int i = 0; i < 2; i++)
#pragma unroll
        for (int j = 0; j < 8; j++)
#pragma unroll
            for (int q = 0; q < 4; q++) acc[i][j][q] = 0.f;

    uint32_t acoff[2];
    int at[2], ack8[2];
#pragma unroll
    for (int j = 0; j < 2; j++) {
        int c = tid + 256 * j;
        at[j] = c >> 3;
        ack8[j] = c & 7;
        acoff[j] = (uint32_t)at[j] * 128u + (uint32_t)((ack8[j] ^ (at[j] & 7)) << 4);
    }
    uint32_t bcoff[8], bsrc[8];
#pragma unroll
    for (int j = 0; j < 8; j++) {
        int c = tid + 256 * j;
        int crow = c >> 3, ck8 = c & 7;
        bcoff[j] = (uint32_t)crow * 128u + (uint32_t)((ck8 ^ (crow & 7)) << 4);
        bsrc[j] = (uint32_t)crow * 768u + (uint32_t)(ck8 * 8);
    }

    float areg[2][8];
#define LOAD_A(kt)                                                             \
    do {                                                                       \
        _Pragma("unroll") for (int j = 0; j < 2; j++) {                        \
            int k0 = ((kt) * 8 + ack8[j]) * 8;                                 \
            int cch = k0 >> 8, rem = k0 & 255;                                 \
            int rr = rem >> 4, qq = rem & 15;                                  \
            const float* fp = frame +                                          \
                (((size_t)(b * 3 + cch) * 128 + (at[j] >> 3) * 16 + rr) * 128  \
                 + (at[j] & 7) * 16 + qq);                                     \
            float4 v0 = *(const float4*)fp;                                    \
            float4 v1 = *(const float4*)(fp + 4);                              \
            areg[j][0] = v0.x; areg[j][1] = v0.y; areg[j][2] = v0.z;           \
            areg[j][3] = v0.w; areg[j][4] = v1.x; areg[j][5] = v1.y;           \
            areg[j][6] = v1.z; areg[j][7] = v1.w;                              \
        }                                                                      \
    } while (0)

#define STS_A(kt)                                                              \
    do {                                                                       \
        const uint32_t sa = (uint32_t)((kt) & 1) * 8192u;                      \
        _Pragma("unroll") for (int j = 0; j < 2; j++) {                        \
            __half2 h0 = __floats2half2_rn(areg[j][0], areg[j][1]);            \
            __half2 h1 = __floats2half2_rn(areg[j][2], areg[j][3]);            \
            __half2 h2 = __floats2half2_rn(areg[j][4], areg[j][5]);            \
            __half2 h3 = __floats2half2_rn(areg[j][6], areg[j][7]);            \
            uint4 pk = make_uint4(*(uint32_t*)&h0, *(uint32_t*)&h1,            \
                                  *(uint32_t*)&h2, *(uint32_t*)&h3);           \
            *(uint4*)(sm + sa + acoff[j]) = pk;                                \
        }                                                                      \
    } while (0)

#define ISSUE_B(kt)                                                            \
    do {                                                                       \
        const uint32_t kk0 = (uint32_t)(kt) << 6;                              \
        const uint32_t sb = smb + PATCH_B_OFF + (uint32_t)((kt) & 1) * 32768u; \
        _Pragma("unroll") for (int j = 0; j < 8; j++)                          \
            cp16(sb + bcoff[j], Bh + bsrc[j] + kk0);                           \
        asm volatile("cp.async.commit_group;" ::: "memory");                   \
    } while (0)

    LOAD_A(0);
    ISSUE_B(0);
    ISSUE_B(1);
    STS_A(0);

    const uint32_t rowAb[2] = {
        (uint32_t)(wm * 32 + 0  + (lane & 7) + ((lane >> 3) & 1) * 8) * 128u,
        (uint32_t)(wm * 32 + 16 + (lane & 7) + ((lane >> 3) & 1) * 8) * 128u};
    const int a_k8add = lane >> 4;
    uint32_t rowBb[4];
#pragma unroll
    for (int nfp = 0; nfp < 4; nfp++)
        rowBb[nfp] = (uint32_t)(wn * 64 + nfp * 16 + ((lane >> 4) << 3) + (lane & 7)) * 128u;
    const int b_k8add = (lane >> 3) & 1;
    const uint32_t swz = (uint32_t)(lane & 7);

    for (int kt = 0; kt < nkt; kt++) {
        if (kt + 1 < nkt) {
            asm volatile("cp.async.wait_group 1;" ::: "memory");
        } else {
            asm volatile("cp.async.wait_group 0;" ::: "memory");
        }
        __syncthreads();

        if (kt + 1 < nkt) LOAD_A(kt + 1);

        const uint32_t sa = smb + (uint32_t)(kt & 1) * 8192u;
        const uint32_t sb = smb + PATCH_B_OFF + (uint32_t)(kt & 1) * 32768u;
#pragma unroll
        for (int ks = 0; ks < 4; ks++) {
            uint32_t ah[2][4];
#pragma unroll
            for (int mf = 0; mf < 2; mf++) {
                uint32_t off = rowAb[mf] +
                    ((((uint32_t)(ks * 2 + a_k8add)) ^ swz) << 4);
                ldsm4(ah[mf], sa + off);
            }
#pragma unroll
            for (int nfp = 0; nfp < 4; nfp++) {
                uint32_t off = rowBb[nfp] +
                    ((((uint32_t)(ks * 2 + b_k8add)) ^ swz) << 4);
                uint32_t bh[4];
                ldsm4(bh, sb + off);
#pragma unroll
                for (int mf = 0; mf < 2; mf++) {
                    mma16816(acc[mf][2 * nfp],     ah[mf], bh);
                    mma16816(acc[mf][2 * nfp + 1], ah[mf], bh + 2);
                }
            }
        }
        __syncthreads();
        if (kt + 1 < nkt) STS_A(kt + 1);
        if (kt + 2 < nkt) ISSUE_B(kt + 2);
    }
#undef LOAD_A
#undef STS_A
#undef ISSUE_B

#pragma unroll
    for (int mf = 0; mf < 2; mf++) {
        const int lra = wm * 32 + mf * 16 + (lane >> 2);
        const int t1 = lra, t2 = lra + 8;
        float s1 = 0.f, q1 = 0.f, s2 = 0.f, q2 = 0.f;
#pragma unroll
        for (int nf = 0; nf < 8; nf++) {
            const int col = wn * 64 + nf * 8 + (lane & 3) * 2;
            float2 bb = *(const float2*)&bias[col];
            acc[mf][nf][0] += bb.x + pos2d_val(t1 >> 3, t1 & 7, col);
            acc[mf][nf][1] += bb.y + pos2d_val(t1 >> 3, t1 & 7, col + 1);
            acc[mf][nf][2] += bb.x + pos2d_val(t2 >> 3, t2 & 7, col);
            acc[mf][nf][3] += bb.y + pos2d_val(t2 >> 3, t2 & 7, col + 1);
            s1 += acc[mf][nf][0] + acc[mf][nf][1];
            q1 += acc[mf][nf][0] * acc[mf][nf][0] + acc[mf][nf][1] * acc[mf][nf][1];
            s2 += acc[mf][nf][2] + acc[mf][nf][3];
            q2 += acc[mf][nf][2] * acc[mf][nf][2] + acc[mf][nf][3] * acc[mf][nf][3];
        }
        s1 += __shfl_xor_sync(0xffffffffu, s1, 1); q1 += __shfl_xor_sync(0xffffffffu, q1, 1);
        s1 += __shfl_xor_sync(0xffffffffu, s1, 2); q1 += __shfl_xor_sync(0xffffffffu, q1, 2);
        s2 += __shfl_xor_sync(0xffffffffu, s2, 1); q2 += __shfl_xor_sync(0xffffffffu, q2, 1);
        s2 += __shfl_xor_sync(0xffffffffu, s2, 2); q2 += __shfl_xor_sync(0xffffffffu, q2, 2);
        if ((lane & 3) == 0) {
            stats[lra * 4 + wn] = make_float2(s1, q1);
            stats[(lra + 8) * 4 + wn] = make_float2(s2, q2);
        }
    }
    __syncthreads();

#pragma unroll
    for (int mf = 0; mf < 2; mf++) {
        const int lra = wm * 32 + mf * 16 + (lane >> 2);
        const int t1 = lra, t2 = lra + 8;
        const int r1 = b * SQ + NCV + t1;
        const int r2 = b * SQ + NCV + t2;
        float2 a0 = stats[lra * 4 + 0], a1 = stats[lra * 4 + 1];
        float2 a2 = stats[lra * 4 + 2], a3 = stats[lra * 4 + 3];
        float mu1 = (a0.x + a1.x + a2.x + a3.x) * (1.0f / 256.0f);
        float iv1 = rsqrtf((a0.y + a1.y + a2.y + a3.y) * (1.0f / 256.0f) - mu1 * mu1 + 1e-5f);
        float2 c0 = stats[(lra + 8) * 4 + 0], c1 = stats[(lra + 8) * 4 + 1];
        float2 c2 = stats[(lra + 8) * 4 + 2], c3 = stats[(lra + 8) * 4 + 3];
        float mu2 = (c0.x + c1.x + c2.x + c3.x) * (1.0f / 256.0f);
        float iv2 = rsqrtf((c0.y + c1.y + c2.y + c3.y) * (1.0f / 256.0f) - mu2 * mu2 + 1e-5f);

#pragma unroll
        for (int nf = 0; nf < 8; nf++) {
            const int col = wn * 64 + nf * 8 + (lane & 3) * 2;
            float g0 = gbuf[col], g1 = gbuf[col + 1];
            float be0 = gbuf[256 + col], be1 = gbuf[256 + col + 1];
            *(float2*)&xout[(size_t)r1 * DM + col] =
                make_float2(acc[mf][nf][0], acc[mf][nf][1]);
            *(float2*)&xout[(size_t)r2 * DM + col] =
                make_float2(acc[mf][nf][2], acc[mf][nf][3]);
            *(__half2*)&lnh_out[(size_t)r1 * DM + col] = __floats2half2_rn(
                (acc[mf][nf][0] - mu1) * iv1 * g0 + be0,
                (acc[mf][nf][1] - mu1) * iv1 * g1 + be1);
            *(__half2*)&lnh_out[(size_t)r2 * DM + col] = __floats2half2_rn(
                (acc[mf][nf][2] - mu2) * iv2 * g0 + be0,
                (acc[mf][nf][3] - mu2) * iv2 * g1 + be1);
        }
    }
}

// ---------------- host launcher ----------------
extern "C" void kernel_launch(void* const* d_in, const int* in_sizes, int n_in,
                              void* d_out, int out_size) {
    const float* h_map   = (const float*)d_in[0];
    const float* frame   = (const float*)d_in[1];
    const int*   idx     = (const int*)  d_in[2];
    const float* Wqkv    = (const float*)d_in[3];
    const float* bqkv    = (const float*)d_in[4];
    const float* Wo      = (const float*)d_in[5];
    const float* bo      = (const float*)d_in[6];
    const float* ln1g    = (const float*)d_in[7];
    const float* ln1b    = (const float*)d_in[8];
    const float* W1      = (const float*)d_in[9];
    const float* b1      = (const float*)d_in[10];
    const float* W2      = (const float*)d_in[11];
    const float* b2      = (const float*)d_in[12];
    const float* ln2g    = (const float*)d_in[13];
    const float* ln2b    = (const float*)d_in[14];
    const float* nfg     = (const float*)d_in[15];
    const float* nfb     = (const float*)d_in[16];
    const float* patch_w = (const float*)d_in[17];
    const float* patch_b = (const float*)d_in[18];
    const float* gate_w  = (const float*)d_in[19];
    const float* gate_b  = (const float*)d_in[20];
    float* out = (float*)d_out;

    float *x, *ln, *hcv;
    __half *lnh, *qkvh, *ath, *h1h, *cth, *wh;
    cudaGetSymbolAddress((void**)&x, g_x);
    cudaGetSymbolAddress((void**)&ln, g_ln);
    cudaGetSymbolAddress((void**)&hcv, g_hcv);
    cudaGetSymbolAddress((void**)&lnh, g_lnh);
    cudaGetSymbolAddress((void**)&qkvh, g_qkvh);
    cudaGetSymbolAddress((void**)&ath, g_ath);
    cudaGetSymbolAddress((void**)&h1h, g_h1h);
    cudaGetSymbolAddress((void**)&cth, g_cth);
    cudaGetSymbolAddress((void**)&wh, g_wh);

    cudaFuncSetAttribute(mma_gemm_k<EPL_GELU>,  cudaFuncAttributeMaxDynamicSharedMemorySize, GSMEM_BYTES);
    cudaFuncSetAttribute(mma_gemm_k<EPL_GATE>,  cudaFuncAttributeMaxDynamicSharedMemorySize, GSMEM_BYTES);
    cudaFuncSetAttribute(mma_gemm_k<EPL_QKVH>,  cudaFuncAttributeMaxDynamicSharedMemorySize, GSMEM_BYTES);
    cudaFuncSetAttribute(gemm64_resln_k<false>, cudaFuncAttributeMaxDynamicSharedMemorySize, GSMEM64);
    cudaFuncSetAttribute(gemm64_resln_k<true>,  cudaFuncAttributeMaxDynamicSharedMemorySize, GSMEM64);
    cudaFuncSetAttribute(patchgemm_k, cudaFuncAttributeMaxDynamicSharedMemorySize, PATCH_SMEM);
    cudaFuncSetAttribute(attn_fa_k, cudaFuncAttributeMaxDynamicSharedMemorySize, ATT_SMEM);

    wcvt_all_k<<<1261568 / 256, 256>>>(Wqkv, Wo, W1, W2, patch_w, gate_w, wh);

    // fused copy(out<=h_map) + embed + entry LN
    copyembed_k<<<COPY_BLKS + 2048, 256>>>(h_map, out, idx, hcv, cth, x, lnh, ln1g, ln1b);
    patchgemm_k<<<dim3(1, 64), 256, PATCH_SMEM>>>(
        frame, wh + WOFF_PW, patch_b, x, lnh, ln1g, ln1b);

    const int NTOK = BB * SQ;
    for (int l = 0; l < NDEPTH; l++) {
        mma_gemm_k<EPL_QKVH><<<dim3(6, 160), 256, GSMEM_BYTES>>>(
            lnh, wh + WOFF_QKV + (size_t)l * 196608,
            bqkv + l * 768, nullptr, qkvh,
            NTOK, 768, 256, nullptr, nullptr, nullptr);
        attn_fa_k<<<BB * NHEADS, 320, ATT_SMEM>>>(qkvh, ath);
        gemm64_resln_k<false><<<dim3(1, NTOK / 64), 256, GSMEM64>>>(
            ath, wh + WOFF_WO + (size_t)l * 65536, bo + l * 256,
            x, x, lnh, 256, ln2g + l * 256, ln2b + l * 256);
        mma_gemm_k<EPL_GELU><<<dim3(8, 160), 256, GSMEM_BYTES>>>(
            lnh, wh + WOFF_W1 + (size_t)l * 262144,
            b1 + l * 1024, nullptr, h1h,
            NTOK, 1024, 256, nullptr, nullptr, nullptr);
        if (l + 1 < NDEPTH) {
            gemm64_resln_k<false><<<dim3(1, NTOK / 64), 256, GSMEM64>>>(
                h1h, wh + WOFF_W2 + (size_t)l * 262144, b2 + l * 256,
                x, x, lnh, 1024, ln1g + (l + 1) * 256, ln1b + (l + 1) * 256);
        } else {
            gemm64_resln_k<true><<<dim3(1, NTOK / 64), 256, GSMEM64>>>(
                h1h, wh + WOFF_W2 + (size_t)l * 262144, b2 + l * 256,
                x, ln, cth, 1024, nfg, nfb);
        }
    }

    mma_gemm_k<EPL_GATE><<<dim3(2, 128), 256, GSMEM_BYTES>>>(
        cth, wh + WOFF_GW, gate_b, out, nullptr,
        16384, 256, 512, hcv, ln, idx);
}

// round 13
// speedup vs baseline: 1.1802x; 1.0220x over previous
#include <cuda_runtime.h>
#include <cuda_fp16.h>
#include <math.h>
#include <stdint.h>

#define BB 64
#define SQ 320
#define NCV 256
#define DM 256
#define HIDN 1024
#define NHEADS 8
#define NDEPTH 6
#define WSQ 1089

// ---------------- device scratch ----------------
__device__ float g_x[(size_t)BB * SQ * DM];
__device__ float g_ln[(size_t)BB * SQ * DM];
__device__ float g_hcv[(size_t)BB * NCV * DM];

__device__ __half g_lnh[(size_t)BB * SQ * DM];
__device__ __half g_qkvh[(size_t)BB * SQ * 3 * DM];
__device__ __half g_ath[(size_t)BB * SQ * DM];
__device__ __half g_h1h[(size_t)BB * SQ * HIDN];
__device__ __half g_cth[(size_t)BB * NCV * 2 * DM];

#define WOFF_QKV   0u
#define WOFF_WO    1179648u
#define WOFF_W1    1572864u
#define WOFF_W2    3145728u
#define WOFF_PW    4718592u
#define WOFF_GW    4915200u
#define WPOOL_N    5046272u
__device__ __half g_wh[WPOOL_N];

// ---------------- helpers ----------------
__device__ __forceinline__ float pos2d_val(int yy, int xx, int d) {
    int dd = d & 127;
    int i = dd >> 1;
    float freq = expf((float)(2 * i) * (-0.07195578415606394f));
    float coord = (d < 128) ? (float)yy : (float)xx;
    float ang = coord * freq;
    return (d & 1) ? cosf(ang) : sinf(ang);
}

__device__ __forceinline__ float gelu_exact(float v) {
    return 0.5f * v * (1.0f + erff(v * 0.70710678118654752f));
}

__device__ __forceinline__ uint32_t smem_u32(const void* p) {
    uint32_t a;
    asm("{ .reg .u64 t; cvta.to.shared.u64 t, %1; cvt.u32.u64 %0, t; }" : "=r"(a) : "l"(p));
    return a;
}

__device__ __forceinline__ void cp16(uint32_t dst, const void* src) {
    asm volatile("cp.async.cg.shared.global [%0], [%1], 16;" :: "r"(dst), "l"(src));
}

__device__ __forceinline__ void ldsm4(uint32_t* r, uint32_t addr) {
    asm volatile("ldmatrix.sync.aligned.m8n8.x4.shared.b16 {%0,%1,%2,%3}, [%4];"
                 : "=r"(r[0]), "=r"(r[1]), "=r"(r[2]), "=r"(r[3]) : "r"(addr));
}

__device__ __forceinline__ void ldsm4t(uint32_t* r, uint32_t addr) {
    asm volatile("ldmatrix.sync.aligned.m8n8.x4.trans.shared.b16 {%0,%1,%2,%3}, [%4];"
                 : "=r"(r[0]), "=r"(r[1]), "=r"(r[2]), "=r"(r[3]) : "r"(addr));
}

__device__ __forceinline__ void mma16816(float* c, const uint32_t* a, const uint32_t* b) {
    asm volatile(
        "mma.sync.aligned.m16n8k16.row.col.f32.f16.f16.f32 "
        "{%0,%1,%2,%3}, {%4,%5,%6,%7}, {%8,%9}, {%0,%1,%2,%3};\n"
        : "+f"(c[0]), "+f"(c[1]), "+f"(c[2]), "+f"(c[3])
        : "r"(a[0]), "r"(a[1]), "r"(a[2]), "r"(a[3]), "r"(b[0]), "r"(b[1]));
}

// ---------------- ALL weights fp32 -> fp16, one launch ----------------
__global__ void __launch_bounds__(256) wcvt_all_k(
    const float* __restrict__ s0, const float* __restrict__ s1,
    const float* __restrict__ s2, const float* __restrict__ s3,
    const float* __restrict__ s4, const float* __restrict__ s5,
    __half* __restrict__ h) {
    int i = blockIdx.x * 256 + threadIdx.x;
    const float* src;
    int base;
    if (i < 393216) {
        if (i < 294912) { src = s0; base = 0; }
        else            { src = s1; base = 294912; }
    } else if (i < 1179648) {
        if (i < 786432) { src = s2; base = 393216; }
        else            { src = s3; base = 786432; }
    } else {
        if (i < 1228800) { src = s4; base = 1179648; }
        else             { src = s5; base = 1228800; }
    }
    float4 v = ((const float4*)src)[i - base];
    __half2* hp = (__half2*)(h + (size_t)i * 4);
    hp[0] = __floats2half2_rn(v.x, v.y);
    hp[1] = __floats2half2_rn(v.z, v.w);
}

// ---------------- copy h_map->out + embed + entry LN ----------------
#define COPY_BLKS 8712
__global__ void __launch_bounds__(256) copyembed_k(const float* __restrict__ h_map,
                                                   float* __restrict__ out,
                                                   const int* __restrict__ idx,
                                                   float* __restrict__ hcv,
                                                   __half* __restrict__ cth,
                                                   float* __restrict__ x,
                                                   __half* __restrict__ lnh,
                                                   const float* __restrict__ gam,
                                                   const float* __restrict__ bet) {
    int warp = threadIdx.x >> 5;
    int lane = threadIdx.x & 31;
    if (blockIdx.x < COPY_BLKS) {
        int row = blockIdx.x * 8 + warp;
        const float4* s = (const float4*)(h_map + (size_t)row * DM) + lane;
        float4* d = (float4*)(out + (size_t)row * DM) + lane;
        d[0] = s[0];
        d[32] = s[32];
        return;
    }
    int tok = (blockIdx.x - COPY_BLKS) * 8 + warp;
    int b = tok >> 8, n = tok & 255;
    int p = idx[n];
    int yy = p / 33, xx = p % 33;
    const float* hp = h_map + ((size_t)b * WSQ + p) * DM;
    float v[8];
    float sum = 0.f, sq = 0.f;
#pragma unroll
    for (int i = 0; i < 8; i++) {
        int d = lane + 32 * i;
        float h = hp[d];
        hcv[((size_t)tok) * DM + d] = h;
        cth[((size_t)tok) * 512 + d] = __float2half_rn(h);
        float xv = h + pos2d_val(yy, xx, d);
        v[i] = xv;
        x[((size_t)(b * SQ + n)) * DM + d] = xv;
        sum += xv;
        sq += xv * xv;
    }
#pragma unroll
    for (int off = 16; off; off >>= 1) {
        sum += __shfl_xor_sync(0xffffffffu, sum, off);
        sq  += __shfl_xor_sync(0xffffffffu, sq, off);
    }
    float mu = sum * (1.0f / 256.0f);
    float var = sq * (1.0f / 256.0f) - mu * mu;
    float inv = rsqrtf(var + 1e-5f);
#pragma unroll
    for (int i = 0; i < 8; i++) {
        int d = lane + 32 * i;
        lnh[((size_t)(b * SQ + n)) * DM + d] =
            __float2half_rn((v[i] - mu) * inv * gam[d] + bet[d]);
    }
}

// ================= fused flash attention (fixed-offset softmax) =================
#define ATT_RS 80u
#define ATT_TEN (320u * ATT_RS)
#define ATT_SMEM (3u * ATT_TEN)

__global__ void __launch_bounds__(320) attn_fa_k(const __half* __restrict__ qkvh,
                                                 __half* __restrict__ oh) {
    extern __shared__ char sm[];
    const uint32_t smb = smem_u32(sm);
    const int b = blockIdx.x >> 3;
    const int h = blockIdx.x & 7;
    const int tid = threadIdx.x;
    const int l = tid & 31;
    const int w = tid >> 5;

#pragma unroll
    for (int j = 0; j < 12; j++) {
        int c = j * 320 + tid;
        int tz = c / 1280;
        int rem = c - tz * 1280;
        int r = rem >> 2;
        int ch = rem & 3;
        const __half* src = qkvh + (size_t)(b * SQ + r) * 768 + tz * 256 + h * 32 + ch * 8;
        cp16(smb + (uint32_t)tz * ATT_TEN + (uint32_t)r * ATT_RS + (uint32_t)ch * 16u, src);
    }
    asm volatile("cp.async.commit_group;" ::: "memory");
    asm volatile("cp.async.wait_group 0;" ::: "memory");
    __syncthreads();

    const uint32_t smQ = smb, smK = smb + ATT_TEN, smV = smb + 2 * ATT_TEN;
    const int q0 = w * 32;

    uint32_t aq[2][2][4];
#pragma unroll
    for (int mf = 0; mf < 2; mf++)
#pragma unroll
        for (int kc = 0; kc < 2; kc++) {
            uint32_t addr = smQ +
                (uint32_t)(q0 + mf * 16 + (l & 7) + ((l >> 3) & 1) * 8) * ATT_RS +
                (uint32_t)(kc * 2 + (l >> 4)) * 16u;
            ldsm4(aq[mf][kc], addr);
        }

    float lrow[2][2] = {{0.f, 0.f}, {0.f, 0.f}};
    float acc_o[2][4][4];
#pragma unroll
    for (int mf = 0; mf < 2; mf++)
#pragma unroll
        for (int db = 0; db < 4; db++)
#pragma unroll
            for (int q = 0; q < 4; q++) acc_o[mf][db][q] = 0.f;

    for (int ck = 0; ck < 320; ck += 64) {
        float s[2][8][4];
#pragma unroll
        for (int mf = 0; mf < 2; mf++)
#pragma unroll
            for (int nb = 0; nb < 8; nb++)
#pragma unroll
                for (int q = 0; q < 4; q++) s[mf][nb][q] = 0.f;

#pragma unroll
        for (int g = 0; g < 4; g++) {
#pragma unroll
            for (int ks = 0; ks < 2; ks++) {
                uint32_t bk[4];
                uint32_t addr = smK +
                    (uint32_t)(ck + g * 16 + ((l >> 4) << 3) + (l & 7)) * ATT_RS +
                    (uint32_t)(ks * 2 + ((l >> 3) & 1)) * 16u;
                ldsm4(bk, addr);
#pragma unroll
                for (int mf = 0; mf < 2; mf++) {
                    mma16816(s[mf][2 * g],     aq[mf][ks], bk);
                    mma16816(s[mf][2 * g + 1], aq[mf][ks], bk + 2);
                }
            }
        }

        // fixed-offset softmax: P = exp(s - 4); offset cancels in the ratio.
        uint32_t ap[2][4][4];
#pragma unroll
        for (int mf = 0; mf < 2; mf++) {
            float ls0 = 0.f, ls1 = 0.f;
#pragma unroll
            for (int nb = 0; nb < 8; nb++) {
                float p0 = __expf(s[mf][nb][0] - 4.0f);
                float p1 = __expf(s[mf][nb][1] - 4.0f);
                float p2 = __expf(s[mf][nb][2] - 4.0f);
                float p3 = __expf(s[mf][nb][3] - 4.0f);
                s[mf][nb][0] = p0; s[mf][nb][1] = p1;
                s[mf][nb][2] = p2; s[mf][nb][3] = p3;
                ls0 += p0 + p1;
                ls1 += p2 + p3;
            }
            ls0 += __shfl_xor_sync(0xffffffffu, ls0, 1);
            ls0 += __shfl_xor_sync(0xffffffffu, ls0, 2);
            ls1 += __shfl_xor_sync(0xffffffffu, ls1, 1);
            ls1 += __shfl_xor_sync(0xffffffffu, ls1, 2);
            lrow[mf][0] += ls0;
            lrow[mf][1] += ls1;
#pragma unroll
            for (int g = 0; g < 4; g++) {
                __half2 h0 = __floats2half2_rn(s[mf][2 * g][0],     s[mf][2 * g][1]);
                __half2 h1 = __floats2half2_rn(s[mf][2 * g][2],     s[mf][2 * g][3]);
                __half2 h2 = __floats2half2_rn(s[mf][2 * g + 1][0], s[mf][2 * g + 1][1]);
                __half2 h3 = __floats2half2_rn(s[mf][2 * g + 1][2], s[mf][2 * g + 1][3]);
                ap[mf][g][0] = *(uint32_t*)&h0;
                ap[mf][g][1] = *(uint32_t*)&h1;
                ap[mf][g][2] = *(uint32_t*)&h2;
                ap[mf][g][3] = *(uint32_t*)&h3;
            }
        }

#pragma unroll
        for (int g = 0; g < 4; g++) {
#pragma unroll
            for (int dd = 0; dd < 2; dd++) {
                uint32_t bv[4];
                uint32_t addr = smV +
                    (uint32_t)(ck + g * 16 + ((l >> 3) & 1) * 8 + (l & 7)) * ATT_RS +
                    (uint32_t)(dd * 2 + (l >> 4)) * 16u;
                ldsm4t(bv, addr);
#pragma unroll
                for (int mf = 0; mf < 2; mf++) {
                    mma16816(acc_o[mf][dd * 2],     ap[mf][g], bv);
                    mma16816(acc_o[mf][dd * 2 + 1], ap[mf][g], bv + 2);
                }
            }
        }
    }

#pragma unroll
    for (int mf = 0; mf < 2; mf++) {
#pragma unroll
        for (int hh = 0; hh < 2; hh++) {
            float inv = 1.f / lrow[mf][hh];
            int tok = q0 + mf * 16 + (l >> 2) + hh * 8;
            __half* op = oh + (size_t)(b * SQ + tok) * DM + h * 32 + 2 * (l & 3);
#pragma unroll
            for (int db = 0; db < 4; db++) {
                __half2 r = __floats2half2_rn(acc_o[mf][db][hh * 2] * inv,
                                              acc_o[mf][db][hh * 2 + 1] * inv);
                *(__half2*)(op + db * 8) = r;
            }
        }
    }
}

// ================= HMMA fp16 pipelined GEMM (128x128, 2 CTA/SM) =================
enum { EPL_GELU = 2, EPL_GATE = 4, EPL_QKVH = 5 };

#define STG_B 32768u
#define GSMEM_BYTES (3u * STG_B)

template <int MODE>
__device__ __forceinline__ void epi_store2(
    float* __restrict__ out, __half* __restrict__ outh,
    int N, int row, int col, float vx, float vy,
    const float* __restrict__ bias, const float* __restrict__ res,
    const float* __restrict__ extra, const int* __restrict__ idx) {
    float2 bb = *(const float2*)(bias + col);
    vx += bb.x;
    vy += bb.y;
    if (MODE == EPL_GELU) {
        *(__half2*)&outh[(size_t)row * N + col] =
            __floats2half2_rn(gelu_exact(vx), gelu_exact(vy));
    } else if (MODE == EPL_QKVH) {
        float sc = (col < 256) ? 0.17677669529663687f : 1.0f;
        *(__half2*)&outh[(size_t)row * N + col] = __floats2half2_rn(vx * sc, vy * sc);
    } else {  // EPL_GATE
        int b = row >> 8, n = row & 255;
        int p = idx[n];
        float2 hc = *(const float2*)&res[(size_t)row * DM + col];
        float2 hn = *(const float2*)&extra[((size_t)(b * SQ + n)) * DM + col];
        float g0 = 1.f / (1.f + expf(-vx));
        float g1 = 1.f / (1.f + expf(-vy));
        float2 r;
        r.x = hc.x + g0 * (hn.x - hc.x);
        r.y = hc.y + g1 * (hn.y - hc.y);
        *(float2*)&out[((size_t)b * WSQ + p) * DM + col] = r;
    }
}

template <int MODE>
__global__ void __launch_bounds__(256, 2) mma_gemm_k(
    const __half* __restrict__ Ah, const __half* __restrict__ Bh,
    const float* __restrict__ bias, float* __restrict__ out,
    __half* __restrict__ outh,
    int M, int N, int K,
    const float* __restrict__ res, const float* __restrict__ extra,
    const int* __restrict__ idx) {
    extern __shared__ char sm[];
    const uint32_t smb = smem_u32(sm);
    const int tid = threadIdx.x;
    const int lane = tid & 31;
    const int w = tid >> 5;
    const int wm = w >> 1;
    const int wn = w & 1;
    const int m0 = blockIdx.y * 128;
    const int n0 = blockIdx.x * 128;

    float acc[2][8][4];
#pragma unroll
    for (int i = 0; i < 2; i++)
#pragma unroll
        for (int j = 0; j < 8; j++)
#pragma unroll
            for (int q = 0; q < 4; q++) acc[i][j][q] = 0.f;

    const int nkt = K >> 6;

    const uint32_t crow0 = (uint32_t)(tid >> 3);
    const uint32_t ck8i = (uint32_t)(tid & 7);
    const uint32_t coff0 = crow0 * 128u + ((ck8i ^ (crow0 & 7)) << 4);
    const uint32_t asrc0 = (uint32_t)(m0 + (int)crow0) * (uint32_t)K + ck8i * 8u;
    const uint32_t bsrc0 = (uint32_t)(n0 + (int)crow0) * (uint32_t)K + ck8i * 8u;
    const uint32_t kst = 32u * (uint32_t)K;

#define ISSUE_STAGE(kt)                                                        \
    do {                                                                       \
        const uint32_t kk0 = (uint32_t)(kt) << 6;                              \
        const uint32_t sb = smb + (uint32_t)((kt) % 3) * STG_B;                \
        _Pragma("unroll") for (uint32_t j = 0; j < 4; j++) {                   \
            cp16(sb + coff0 + 4096u * j,           Ah + asrc0 + kk0 + kst * j);\
            cp16(sb + 16384u + coff0 + 4096u * j,  Bh + bsrc0 + kk0 + kst * j);\
        }                                                                      \
        asm volatile("cp.async.commit_group;" ::: "memory");                   \
    } while (0)

    ISSUE_STAGE(0);
    ISSUE_STAGE(1);

    const uint32_t rowAb[2] = {
        (uint32_t)(wm * 32 + 0  + (lane & 7) + ((lane >> 3) & 1) * 8) * 128u,
        (uint32_t)(wm * 32 + 16 + (lane & 7) + ((lane >> 3) & 1) * 8) * 128u};
    const int a_k8add = lane >> 4;
    uint32_t rowBb[4];
#pragma unroll
    for (int nfp = 0; nfp < 4; nfp++)
        rowBb[nfp] = (uint32_t)(wn * 64 + nfp * 16 + ((lane >> 4) << 3) + (lane & 7)) * 128u;
    const int b_k8add = (lane >> 3) & 1;
    const uint32_t swz = (uint32_t)(lane & 7);

    for (int kt = 0; kt < nkt; kt++) {
        if (kt + 1 < nkt) {
            asm volatile("cp.async.wait_group 1;" ::: "memory");
        } else {
            asm volatile("cp.async.wait_group 0;" ::: "memory");
        }
        __syncthreads();
        if (kt + 2 < nkt) ISSUE_STAGE(kt + 2);

        const uint32_t sb = smb + (uint32_t)(kt % 3) * STG_B;

        uint32_t ahh[4][2][4];
#pragma unroll
        for (int ks = 0; ks < 4; ks++)
#pragma unroll
            for (int mf = 0; mf < 2; mf++) {
                uint32_t off = rowAb[mf] +
                    ((((uint32_t)(ks * 2 + a_k8add)) ^ swz) << 4);
                ldsm4(ahh[ks][mf], sb + off);
            }

#pragma unroll
        for (int ks = 0; ks < 4; ks++) {
#pragma unroll
            for (int nfp = 0; nfp < 4; nfp++) {
                uint32_t off = rowBb[nfp] +
                    ((((uint32_t)(ks * 2 + b_k8add)) ^ swz) << 4);
                uint32_t bh[4];
                ldsm4(bh, sb + 16384u + off);
#pragma unroll
                for (int mf = 0; mf < 2; mf++) {
                    mma16816(acc[mf][2 * nfp],     ahh[ks][mf], bh);
                    mma16816(acc[mf][2 * nfp + 1], ahh[ks][mf], bh + 2);
                }
            }
        }
    }
#undef ISSUE_STAGE

#pragma unroll
    for (int mf = 0; mf < 2; mf++) {
        int row = m0 + wm * 32 + mf * 16 + (lane >> 2);
#pragma unroll
        for (int nf = 0; nf < 8; nf++) {
            int col = n0 + wn * 64 + nf * 8 + (lane & 3) * 2;
            epi_store2<MODE>(out, outh, N, row, col,
                             acc[mf][nf][0], acc[mf][nf][1], bias, res, extra, idx);
            epi_store2<MODE>(out, outh, N, row + 8, col,
                             acc[mf][nf][2], acc[mf][nf][3], bias, res, extra, idx);
        }
    }
}

// ======== fused GEMM(32x256) + bias + residual + LayerNorm ========
// Tile 32(M) x 256(N), 8 warps each 32x32, 2-stage. grid y = M/32 (640 for NTOK).
// smem: A0@0(4K) A1@4K B0@8K(32K) B1@40K gb@72K(2K) stats@74K(1K... 32*8*8=2K)
#define G32_A(st)  ((uint32_t)(st) * 4096u)
#define G32_B(st)  (8192u + (uint32_t)(st) * 32768u)
#define G32_GB     73728u
#define G32_ST     75776u
#define GSMEM32    77824u

template <bool FINAL>
__global__ void __launch_bounds__(256, 2) gemm32_resln_k(
    const __half* __restrict__ Ah, const __half* __restrict__ Bh,
    const float* __restrict__ bias,
    const float* res, float* xout, __half* __restrict__ lnh_out,
    int K, const float* __restrict__ gam, const float* __restrict__ bet) {
    extern __shared__ char sm[];
    const uint32_t smb = smem_u32(sm);
    const int tid = threadIdx.x;
    const int lane = tid & 31;
    const int w = tid >> 5;        // warp covers cols w*32..w*32+31, all 32 rows
    const int m0 = blockIdx.y * 32;

    float* gbuf = (float*)(sm + G32_GB);
    float2* stats = (float2*)(sm + G32_ST);
    gbuf[tid] = gam[tid];
    gbuf[256 + tid] = bet[tid];

    float acc[2][4][4];
#pragma unroll
    for (int i = 0; i < 2; i++)
#pragma unroll
        for (int j = 0; j < 4; j++)
#pragma unroll
            for (int q = 0; q < 4; q++) acc[i][j][q] = 0.f;

    const int nkt = K >> 6;

    const uint32_t crow0 = (uint32_t)(tid >> 3);   // 0..31
    const uint32_t ck8i = (uint32_t)(tid & 7);
    const uint32_t coff0 = crow0 * 128u + ((ck8i ^ (crow0 & 7)) << 4);
    const uint32_t asrc0 = (uint32_t)(m0 + (int)crow0) * (uint32_t)K + ck8i * 8u;
    const uint32_t bsrc0 = crow0 * (uint32_t)K + ck8i * 8u;
    const uint32_t kst = 32u * (uint32_t)K;

#define ISSUE32(kt)                                                            \
    do {                                                                       \
        const uint32_t kk0 = (uint32_t)(kt) << 6;                              \
        cp16(smb + G32_A((kt) & 1) + coff0, Ah + asrc0 + kk0);                 \
        const uint32_t sb = smb + G32_B((kt) & 1);                             \
        _Pragma("unroll") for (uint32_t j = 0; j < 8; j++)                     \
            cp16(sb + coff0 + 4096u * j, Bh + bsrc0 + kk0 + kst * j);          \
        asm volatile("cp.async.commit_group;" ::: "memory");                   \
    } while (0)

    ISSUE32(0);
    ISSUE32(1);

    const uint32_t rowAb[2] = {
        (uint32_t)(0  + (lane & 7) + ((lane >> 3) & 1) * 8) * 128u,
        (uint32_t)(16 + (lane & 7) + ((lane >> 3) & 1) * 8) * 128u};
    const int a_k8add = lane >> 4;
    uint32_t rowBb[2];
#pragma unroll
    for (int nfp = 0; nfp < 2; nfp++)
        rowBb[nfp] = (uint32_t)(w * 32 + nfp * 16 + ((lane >> 4) << 3) + (lane & 7)) * 128u;
    const int b_k8add = (lane >> 3) & 1;
    const uint32_t swz = (uint32_t)(lane & 7);

    for (int kt = 0; kt < nkt; kt++) {
        if (kt + 1 < nkt) {
            asm volatile("cp.async.wait_group 1;" ::: "memory");
        } else {
            asm volatile("cp.async.wait_group 0;" ::: "memory");
        }
        __syncthreads();

        const uint32_t sa = smb + G32_A(kt & 1);
        const uint32_t sb = smb + G32_B(kt & 1);

        uint32_t ahh[4][2][4];
#pragma unroll
        for (int ks = 0; ks < 4; ks++)
#pragma unroll
            for (int mf = 0; mf < 2; mf++) {
                uint32_t off = rowAb[mf] +
                    ((((uint32_t)(ks * 2 + a_k8add)) ^ swz) << 4);
                ldsm4(ahh[ks][mf], sa + off);
            }

#pragma unroll
        for (int ks = 0; ks < 4; ks++) {
#pragma unroll
            for (int nfp = 0; nfp < 2; nfp++) {
                uint32_t off = rowBb[nfp] +
                    ((((uint32_t)(ks * 2 + b_k8add)) ^ swz) << 4);
                uint32_t bh[4];
                ldsm4(bh, sb + off);
#pragma unroll
                for (int mf = 0; mf < 2; mf++) {
                    mma16816(acc[mf][2 * nfp],     ahh[ks][mf], bh);
                    mma16816(acc[mf][2 * nfp + 1], ahh[ks][mf], bh + 2);
                }
            }
        }
        __syncthreads();
        if (kt + 2 < nkt) ISSUE32(kt + 2);
    }
#undef ISSUE32

    // ---- epilogue: acc += bias + res; per-row LN across the 8 warps ----
#pragma unroll
    for (int mf = 0; mf < 2; mf++) {
        const int lra = mf * 16 + (lane >> 2);      // 0..31
        const int r1 = m0 + lra;
        const int r2 = r1 + 8;
        float s1 = 0.f, q1 = 0.f, s2 = 0.f, q2 = 0.f;
#pragma unroll
        for (int nf = 0; nf < 4; nf++) {
            const int col = w * 32 + nf * 8 + (lane & 3) * 2;
            float2 bb = *(const float2*)&bias[col];
            float2 e1 = *(const float2*)&res[(size_t)r1 * DM + col];
            float2 e2 = *(const float2*)&res[(size_t)r2 * DM + col];
            acc[mf][nf][0] += bb.x + e1.x;
            acc[mf][nf][1] += bb.y + e1.y;
            acc[mf][nf][2] += bb.x + e2.x;
            acc[mf][nf][3] += bb.y + e2.y;
            s1 += acc[mf][nf][0] + acc[mf][nf][1];
            q1 += acc[mf][nf][0] * acc[mf][nf][0] + acc[mf][nf][1] * acc[mf][nf][1];
            s2 += acc[mf][nf][2] + acc[mf][nf][3];
            q2 += acc[mf][nf][2] * acc[mf][nf][2] + acc[mf][nf][3] * acc[mf][nf][3];
        }
        s1 += __shfl_xor_sync(0xffffffffu, s1, 1); q1 += __shfl_xor_sync(0xffffffffu, q1, 1);
        s1 += __shfl_xor_sync(0xffffffffu, s1, 2); q1 += __shfl_xor_sync(0xffffffffu, q1, 2);
        s2 += __shfl_xor_sync(0xffffffffu, s2, 1); q2 += __shfl_xor_sync(0xffffffffu, q2, 1);
        s2 += __shfl_xor_sync(0xffffffffu, s2, 2); q2 += __shfl_xor_sync(0xffffffffu, q2, 2);
        if ((lane & 3) == 0) {
            stats[lra * 8 + w] = make_float2(s1, q1);
            stats[(lra + 8) * 8 + w] = make_float2(s2, q2);
        }
    }
    __syncthreads();

#pragma unroll
    for (int mf = 0; mf < 2; mf++) {
        const int lra = mf * 16 + (lane >> 2);
        const int r1 = m0 + lra, r2 = r1 + 8;
        float su1 = 0.f, qu1 = 0.f, su2 = 0.f, qu2 = 0.f;
#pragma unroll
        for (int j = 0; j < 8; j++) {
            float2 p = stats[lra * 8 + j];
            su1 += p.x; qu1 += p.y;
            float2 r = stats[(lra + 8) * 8 + j];
            su2 += r.x; qu2 += r.y;
        }
        float mu1 = su1 * (1.0f / 256.0f);
        float iv1 = rsqrtf(qu1 * (1.0f / 256.0f) - mu1 * mu1 + 1e-5f);
        float mu2 = su2 * (1.0f / 256.0f);
        float iv2 = rsqrtf(qu2 * (1.0f / 256.0f) - mu2 * mu2 + 1e-5f);

        int b1 = 0, n1 = 0, b2 = 0, n2 = 0;
        if (FINAL) { b1 = r1 / SQ; n1 = r1 - b1 * SQ; b2 = r2 / SQ; n2 = r2 - b2 * SQ; }

#pragma unroll
        for (int nf = 0; nf < 4; nf++) {
            const int col = w * 32 + nf * 8 + (lane & 3) * 2;
            float g0 = gbuf[col], g1 = gbuf[col + 1];
            float be0 = gbuf[256 + col], be1 = gbuf[256 + col + 1];
            float l10 = (acc[mf][nf][0] - mu1) * iv1 * g0 + be0;
            float l11 = (acc[mf][nf][1] - mu1) * iv1 * g1 + be1;
            float l20 = (acc[mf][nf][2] - mu2) * iv2 * g0 + be0;
            float l21 = (acc[mf][nf][3] - mu2) * iv2 * g1 + be1;
            if (!FINAL) {
                *(float2*)&xout[(size_t)r1 * DM + col] =
                    make_float2(acc[mf][nf][0], acc[mf][nf][1]);
                *(float2*)&xout[(size_t)r2 * DM + col] =
                    make_float2(acc[mf][nf][2], acc[mf][nf][3]);
                *(__half2*)&lnh_out[(size_t)r1 * DM + col] = __floats2half2_rn(l10, l11);
                *(__half2*)&lnh_out[(size_t)r2 * DM + col] = __floats2half2_rn(l20, l21);
            } else {
                *(float2*)&xout[(size_t)r1 * DM + col] = make_float2(l10, l11);
                *(float2*)&xout[(size_t)r2 * DM + col] = make_float2(l20, l21);
                if (n1 < NCV)
                    *(__half2*)&lnh_out[((size_t)(b1 * NCV + n1)) * 512 + 256 + col] =
                        __floats2half2_rn(l10, l11);
                if (n2 < NCV)
                    *(__half2*)&lnh_out[((size_t)(b2 * NCV + n2)) * 512 + 256 + col] =
                        __floats2half2_rn(l20, l21);
            }
        }
    }
}

// ======== patch GEMM: on-the-fly im2col A + bias + pos + entry LN ========
#define PATCH_B_OFF 16384u
#define PATCH_GB_OFF 81920u
#define PATCH_ST_OFF 83968u
#define PATCH_SMEM 86016u

__global__ void __launch_bounds__(256, 2) patchgemm_k(
    const float* __restrict__ frame, const __half* __restrict__ Bh,
    const float* __restrict__ bias,
    float* __restrict__ xout, __half* __restrict__ lnh_out,
    const float* __restrict__ gam, const float* __restrict__ bet) {
    extern __shared__ char sm[];
    const uint32_t smb = smem_u32(sm);
    const int tid = threadIdx.x;
    const int lane = tid & 31;
    const int w = tid >> 5;
    const int wm = w >> 2;
    const int wn = w & 3;
    const int b = blockIdx.y;
    const int nkt = 12;

    float* gbuf = (float*)(sm + PATCH_GB_OFF);
    float2* stats = (float2*)(sm + PATCH_ST_OFF);
    gbuf[tid] = gam[tid];
    gbuf[256 + tid] = bet[tid];

    float acc[2][8][4];
#pragma unroll
    for (int i = 0; i < 2; i++)
#pragma unroll
        for (int j = 0; j < 8; j++)
#pragma unroll
            for (int q = 0; q < 4; q++) acc[i][j][q] = 0.f;

    uint32_t acoff[2];
    int at[2], ack8[2];
#pragma unroll
    for (int j = 0; j < 2; j++) {
        int c = tid + 256 * j;
        at[j] = c >> 3;
        ack8[j] = c & 7;
        acoff[j] = (uint32_t)at[j] * 128u + (uint32_t)((ack8[j] ^ (at[j] & 7)) << 4);
    }
    uint32_t bcoff[8], bsrc[8];
#pragma unroll
    for (int j = 0; j < 8; j++) {
        int c = tid + 256 * j;
        int crow = c >> 3, ck8 = c & 7;
        bcoff[j] = (uint32_t)crow * 128u + (uint32_t)((ck8 ^ (crow & 7)) << 4);
        bsrc[j] = (uint32_t)crow * 768u + (uint32_t)(ck8 * 8);
    }

    float areg[2][8];
#define LOAD_A(kt)                                                             \
    do {                                                                       \
        _Pragma("unroll") for (int j = 0; j < 2; j++) {                        \
            int k0 = ((kt) * 8 + ack8[j]) * 8;                                 \
            int cch = k0 >> 8, rem = k0 & 255;                                 \
            int rr = rem >> 4, qq = rem & 15;                                  \
            const float* fp = frame +                                          \
                (((size_t)(b * 3 + cch) * 128 + (at[j] >> 3) * 16 + rr) * 128  \
                 + (at[j] & 7) * 16 + qq);                                     \
            float4 v0 = *(const float4*)fp;                                    \
            float4 v1 = *(const float4*)(fp + 4);                              \
            areg[j][0] = v0.x; areg[j][1] = v0.y; areg[j][2] = v0.z;           \
            areg[j][3] = v0.w; areg[j][4] = v1.x; areg[j][5] = v1.y;           \
            areg[j][6] = v1.z; areg[j][7] = v1.w;                              \
        }                                                                      \
    } while (0)

#define STS_A(kt)                                                              \
    do {                                                                       \
        const uint32_t sa = (uint32_t)((kt) & 1) * 8192u;                      \
        _Pragma("unroll") for (int j = 0; j < 2; j++) {                        \
            __half2 h0 = __floats2half2_rn(areg[j][0], areg[j][1]);            \
            __half2 h1 = __floats2half2_rn(areg[j][2], areg[j][3]);            \
            __half2 h2 = __floats2half2_rn(areg[j][4], areg[j][5]);            \
            __half2 h3 = __floats2half2_rn(areg[j][6], areg[j][7]);            \
            uint4 pk = make_uint4(*(uint32_t*)&h0, *(uint32_t*)&h1,            \
                                  *(uint32_t*)&h2, *(uint32_t*)&h3);           \
            *(uint4*)(sm + sa + acoff[j]) = pk;                                \
        }                                                                      \
    } while (0)

#define ISSUE_B(kt)                                                            \
    do {                                                                       \
        const uint32_t kk0 = (uint32_t)(kt) << 6;                              \
        const uint32_t sb = smb + PATCH_B_OFF + (uint32_t)((kt) & 1) * 32768u; \
        _Pragma("unroll") for (int j = 0; j < 8; j++)                          \
            cp16(sb + bcoff[j], Bh + bsrc[j] + kk0);                           \
        asm volatile("cp.async.commit_group;" ::: "memory");                   \
    } while (0)

    LOAD_A(0);
    ISSUE_B(0);
    ISSUE_B(1);
    STS_A(0);

    const uint32_t rowAb[2] = {
        (uint32_t)(wm * 32 + 0  + (lane & 7) + ((lane >> 3) & 1) * 8) * 128u,
        (uint32_t)(wm * 32 + 16 + (lane & 7) + ((lane >> 3) & 1) * 8) * 128u};
    const int a_k8add = lane >> 4;
    uint32_t rowBb[4];
#pragma unroll
    for (int nfp = 0; nfp < 4; nfp++)
        rowBb[nfp] = (uint32_t)(wn * 64 + nfp * 16 + ((lane >> 4) << 3) + (lane & 7)) * 128u;
    const int b_k8add = (lane >> 3) & 1;
    const uint32_t swz = (uint32_t)(lane & 7);

    for (int kt = 0; kt < nkt; kt++) {
        if (kt + 1 < nkt) {
            asm volatile("cp.async.wait_group 1;" ::: "memory");
        } else {
            asm volatile("cp.async.wait_group 0;" ::: "memory");
        }
        __syncthreads();

        if (kt + 1 < nkt) LOAD_A(kt + 1);

        const uint32_t sa = smb + (uint32_t)(kt & 1) * 8192u;
        const uint32_t sb = smb + PATCH_B_OFF + (uint32_t)(kt & 1) * 32768u;
#pragma unroll
        for (int ks = 0; ks < 4; ks++) {
            uint32_t ah[2][4];
#pragma unroll
            for (int mf = 0; mf < 2; mf++) {
                uint32_t off = rowAb[mf] +
                    ((((uint32_t)(ks * 2 + a_k8add)) ^ swz) << 4);
                ldsm4(ah[mf], sa + off);
            }
#pragma unroll
            for (int nfp = 0; nfp < 4; nfp++) {
                uint32_t off = rowBb[nfp] +
                    ((((uint32_t)(ks * 2 + b_k8add)) ^ swz) << 4);
                uint32_t bh[4];
                ldsm4(bh, sb + off);
#pragma unroll
                for (int mf = 0; mf < 2; mf++) {
                    mma16816(acc[mf][2 * nfp],     ah[mf], bh);
                    mma16816(acc[mf][2 * nfp + 1], ah[mf], bh + 2);
                }
            }
        }
        __syncthreads();
        if (kt + 1 < nkt) STS_A(kt + 1);
        if (kt + 2 < nkt) ISSUE_B(kt + 2);
    }
#undef LOAD_A
#undef STS_A
#undef ISSUE_B

#pragma unroll
    for (int mf = 0; mf < 2; mf++) {
        const int lra = wm * 32 + mf * 16 + (lane >> 2);
        const int t1 = lra, t2 = lra + 8;
        float s1 = 0.f, q1 = 0.f, s2 = 0.f, q2 = 0.f;
#pragma unroll
        for (int nf = 0; nf < 8; nf++) {
            const int col = wn * 64 + nf * 8 + (lane & 3) * 2;
            float2 bb = *(const float2*)&bias[col];
            acc[mf][nf][0] += bb.x + pos2d_val(t1 >> 3, t1 & 7, col);
            acc[mf][nf][1] += bb.y + pos2d_val(t1 >> 3, t1 & 7, col + 1);
            acc[mf][nf][2] += bb.x + pos2d_val(t2 >> 3, t2 & 7, col);
            acc[mf][nf][3] += bb.y + pos2d_val(t2 >> 3, t2 & 7, col + 1);
            s1 += acc[mf][nf][0] + acc[mf][nf][1];
            q1 += acc[mf][nf][0] * acc[mf][nf][0] + acc[mf][nf][1] * acc[mf][nf][1];
            s2 += acc[mf][nf][2] + acc[mf][nf][3];
            q2 += acc[mf][nf][2] * acc[mf][nf][2] + acc[mf][nf][3] * acc[mf][nf][3];
        }
        s1 += __shfl_xor_sync(0xffffffffu, s1, 1); q1 += __shfl_xor_sync(0xffffffffu, q1, 1);
        s1 += __shfl_xor_sync(0xffffffffu, s1, 2); q1 += __shfl_xor_sync(0xffffffffu, q1, 2);
        s2 += __shfl_xor_sync(0xffffffffu, s2, 1); q2 += __shfl_xor_sync(0xffffffffu, q2, 1);
        s2 += __shfl_xor_sync(0xffffffffu, s2, 2); q2 += __shfl_xor_sync(0xffffffffu, q2, 2);
        if ((lane & 3) == 0) {
            stats[lra * 4 + wn] = make_float2(s1, q1);
            stats[(lra + 8) * 4 + wn] = make_float2(s2, q2);
        }
    }
    __syncthreads();

#pragma unroll
    for (int mf = 0; mf < 2; mf++) {
        const int lra = wm * 32 + mf * 16 + (lane >> 2);
        const int t1 = lra, t2 = lra + 8;
        const int r1 = b * SQ + NCV + t1;
        const int r2 = b * SQ + NCV + t2;
        float2 a0 = stats[lra * 4 + 0], a1 = stats[lra * 4 + 1];
        float2 a2 = stats[lra * 4 + 2], a3 = stats[lra * 4 + 3];
        float mu1 = (a0.x + a1.x + a2.x + a3.x) * (1.0f / 256.0f);
        float iv1 = rsqrtf((a0.y + a1.y + a2.y + a3.y) * (1.0f / 256.0f) - mu1 * mu1 + 1e-5f);
        float2 c0 = stats[(lra + 8) * 4 + 0], c1 = stats[(lra + 8) * 4 + 1];
        float2 c2 = stats[(lra + 8) * 4 + 2], c3 = stats[(lra + 8) * 4 + 3];
        float mu2 = (c0.x + c1.x + c2.x + c3.x) * (1.0f / 256.0f);
        float iv2 = rsqrtf((c0.y + c1.y + c2.y + c3.y) * (1.0f / 256.0f) - mu2 * mu2 + 1e-5f);

#pragma unroll
        for (int nf = 0; nf < 8; nf++) {
            const int col = wn * 64 + nf * 8 + (lane & 3) * 2;
            float g0 = gbuf[col], g1 = gbuf[col + 1];
            float be0 = gbuf[256 + col], be1 = gbuf[256 + col + 1];
            *(float2*)&xout[(size_t)r1 * DM + col] =
                make_float2(acc[mf][nf][0], acc[mf][nf][1]);
            *(float2*)&xout[(size_t)r2 * DM + col] =
                make_float2(acc[mf][nf][2], acc[mf][nf][3]);
            *(__half2*)&lnh_out[(size_t)r1 * DM + col] = __floats2half2_rn(
                (acc[mf][nf][0] - mu1) * iv1 * g0 + be0,
                (acc[mf][nf][1] - mu1) * iv1 * g1 + be1);
            *(__half2*)&lnh_out[(size_t)r2 * DM + col] = __floats2half2_rn(
                (acc[mf][nf][2] - mu2) * iv2 * g0 + be0,
                (acc[mf][nf][3] - mu2) * iv2 * g1 + be1);
        }
    }
}

// ---------------- host launcher ----------------
extern "C" void kernel_launch(void* const* d_in, const int* in_sizes, int n_in,
                              void* d_out, int out_size) {
    const float* h_map   = (const float*)d_in[0];
    const float* frame   = (const float*)d_in[1];
    const int*   idx     = (const int*)  d_in[2];
    const float* Wqkv    = (const float*)d_in[3];
    const float* bqkv    = (const float*)d_in[4];
    const float* Wo      = (const float*)d_in[5];
    const float* bo      = (const float*)d_in[6];
    const float* ln1g    = (const float*)d_in[7];
    const float* ln1b    = (const float*)d_in[8];
    const float* W1      = (const float*)d_in[9];
    const float* b1      = (const float*)d_in[10];
    const float* W2      = (const float*)d_in[11];
    const float* b2      = (const float*)d_in[12];
    const float* ln2g    = (const float*)d_in[13];
    const float* ln2b    = (const float*)d_in[14];
    const float* nfg     = (const float*)d_in[15];
    const float* nfb     = (const float*)d_in[16];
    const float* patch_w = (const float*)d_in[17];
    const float* patch_b = (const float*)d_in[18];
    const float* gate_w  = (const float*)d_in[19];
    const float* gate_b  = (const float*)d_in[20];
    float* out = (float*)d_out;

    float *x, *ln, *hcv;
    __half *lnh, *qkvh, *ath, *h1h, *cth, *wh;
    cudaGetSymbolAddress((void**)&x, g_x);
    cudaGetSymbolAddress((void**)&ln, g_ln);
    cudaGetSymbolAddress((void**)&hcv, g_hcv);
    cudaGetSymbolAddress((void**)&lnh, g_lnh);
    cudaGetSymbolAddress((void**)&qkvh, g_qkvh);
    cudaGetSymbolAddress((void**)&ath, g_ath);
    cudaGetSymbolAddress((void**)&h1h, g_h1h);
    cudaGetSymbolAddress((void**)&cth, g_cth);
    cudaGetSymbolAddress((void**)&wh, g_wh);

    cudaFuncSetAttribute(mma_gemm_k<EPL_GELU>,   cudaFuncAttributeMaxDynamicSharedMemorySize, GSMEM_BYTES);
    cudaFuncSetAttribute(mma_gemm_k<EPL_GATE>,   cudaFuncAttributeMaxDynamicSharedMemorySize, GSMEM_BYTES);
    cudaFuncSetAttribute(mma_gemm_k<EPL_QKVH>,   cudaFuncAttributeMaxDynamicSharedMemorySize, GSMEM_BYTES);
    cudaFuncSetAttribute(gemm32_resln_k<false>,  cudaFuncAttributeMaxDynamicSharedMemorySize, GSMEM32);
    cudaFuncSetAttribute(gemm32_resln_k<true>,   cudaFuncAttributeMaxDynamicSharedMemorySize, GSMEM32);
    cudaFuncSetAttribute(patchgemm_k, cudaFuncAttributeMaxDynamicSharedMemorySize, PATCH_SMEM);
    cudaFuncSetAttribute(attn_fa_k, cudaFuncAttributeMaxDynamicSharedMemorySize, ATT_SMEM);

    wcvt_all_k<<<1261568 / 256, 256>>>(Wqkv, Wo, W1, W2, patch_w, gate_w, wh);
    copyembed_k<<<COPY_BLKS + 2048, 256>>>(h_map, out, idx, hcv, cth, x, lnh, ln1g, ln1b);
    patchgemm_k<<<dim3(1, 64), 256, PATCH_SMEM>>>(
        frame, wh + WOFF_PW, patch_b, x, lnh, ln1g, ln1b);

    const int NTOK = BB * SQ;  // 20480
    for (int l = 0; l < NDEPTH; l++) {
        mma_gemm_k<EPL_QKVH><<<dim3(6, 160), 256, GSMEM_BYTES>>>(
            lnh, wh + WOFF_QKV + (size_t)l * 196608,
            bqkv + l * 768, nullptr, qkvh,
            NTOK, 768, 256, nullptr, nullptr, nullptr);
        attn_fa_k<<<BB * NHEADS, 320, ATT_SMEM>>>(qkvh, ath);
        gemm32_resln_k<false><<<dim3(1, NTOK / 32), 256, GSMEM32>>>(
            ath, wh + WOFF_WO + (size_t)l * 65536, bo + l * 256,
            x, x, lnh, 256, ln2g + l * 256, ln2b + l * 256);
        mma_gemm_k<EPL_GELU><<<dim3(8, 160), 256, GSMEM_BYTES>>>(
            lnh, wh + WOFF_W1 + (size_t)l * 262144,
            b1 + l * 1024, nullptr, h1h,
            NTOK, 1024, 256, nullptr, nullptr, nullptr);
        if (l + 1 < NDEPTH) {
            gemm32_resln_k<false><<<dim3(1, NTOK / 32), 256, GSMEM32>>>(
                h1h, wh + WOFF_W2 + (size_t)l * 262144, b2 + l * 256,
                x, x, lnh, 1024, ln1g + (l + 1) * 256, ln1b + (l + 1) * 256);
        } else {
            gemm32_resln_k<true><<<dim3(1, NTOK / 32), 256, GSMEM32>>>(
                h1h, wh + WOFF_W2 + (size_t)l * 262144, b2 + l * 256,
                x, ln, cth, 1024, nfg, nfb);
        }
    }

    mma_gemm_k<EPL_GATE><<<dim3(2, 128), 256, GSMEM_BYTES>>>(
        cth, wh + WOFF_GW, gate_b, out, nullptr,
        16384, 256, 512, hcv, ln, idx);
}

// round 14
// speedup vs baseline: 1.1821x; 1.0016x over previous
#include <cuda_runtime.h>
#include <cuda_fp16.h>
#include <math.h>
#include <stdint.h>

#define BB 64
#define SQ 320
#define NCV 256
#define DM 256
#define HIDN 1024
#define NHEADS 8
#define NDEPTH 6
#define WSQ 1089

// ---------------- device scratch ----------------
__device__ float g_x[(size_t)BB * SQ * DM];
__device__ float g_ln[(size_t)BB * SQ * DM];
__device__ float g_hcv[(size_t)BB * NCV * DM];

__device__ __half g_lnh[(size_t)BB * SQ * DM];
__device__ __half g_qkvh[(size_t)BB * SQ * 3 * DM];
__device__ __half g_ath[(size_t)BB * SQ * DM];
__device__ __half g_h1h[(size_t)BB * SQ * HIDN];
__device__ __half g_cth[(size_t)BB * NCV * 2 * DM];

#define WOFF_QKV   0u
#define WOFF_WO    1179648u
#define WOFF_W1    1572864u
#define WOFF_W2    3145728u
#define WOFF_PW    4718592u
#define WOFF_GW    4915200u
#define WPOOL_N    5046272u
__device__ __half g_wh[WPOOL_N];

// ---------------- helpers ----------------
__device__ __forceinline__ float pos2d_val(int yy, int xx, int d) {
    int dd = d & 127;
    int i = dd >> 1;
    float freq = expf((float)(2 * i) * (-0.07195578415606394f));
    float coord = (d < 128) ? (float)yy : (float)xx;
    float ang = coord * freq;
    return (d & 1) ? cosf(ang) : sinf(ang);
}

__device__ __forceinline__ float gelu_exact(float v) {
    return 0.5f * v * (1.0f + erff(v * 0.70710678118654752f));
}

__device__ __forceinline__ uint32_t smem_u32(const void* p) {
    uint32_t a;
    asm("{ .reg .u64 t; cvta.to.shared.u64 t, %1; cvt.u32.u64 %0, t; }" : "=r"(a) : "l"(p));
    return a;
}

__device__ __forceinline__ void cp16(uint32_t dst, const void* src) {
    asm volatile("cp.async.cg.shared.global [%0], [%1], 16;" :: "r"(dst), "l"(src));
}

__device__ __forceinline__ void ldsm4(uint32_t* r, uint32_t addr) {
    asm volatile("ldmatrix.sync.aligned.m8n8.x4.shared.b16 {%0,%1,%2,%3}, [%4];"
                 : "=r"(r[0]), "=r"(r[1]), "=r"(r[2]), "=r"(r[3]) : "r"(addr));
}

__device__ __forceinline__ void ldsm4t(uint32_t* r, uint32_t addr) {
    asm volatile("ldmatrix.sync.aligned.m8n8.x4.trans.shared.b16 {%0,%1,%2,%3}, [%4];"
                 : "=r"(r[0]), "=r"(r[1]), "=r"(r[2]), "=r"(r[3]) : "r"(addr));
}

__device__ __forceinline__ void mma16816(float* c, const uint32_t* a, const uint32_t* b) {
    asm volatile(
        "mma.sync.aligned.m16n8k16.row.col.f32.f16.f16.f32 "
        "{%0,%1,%2,%3}, {%4,%5,%6,%7}, {%8,%9}, {%0,%1,%2,%3};\n"
        : "+f"(c[0]), "+f"(c[1]), "+f"(c[2]), "+f"(c[3])
        : "r"(a[0]), "r"(a[1]), "r"(a[2]), "r"(a[3]), "r"(b[0]), "r"(b[1]));
}

// ---------------- ALL weights fp32 -> fp16, one launch ----------------
__global__ void __launch_bounds__(256) wcvt_all_k(
    const float* __restrict__ s0, const float* __restrict__ s1,
    const float* __restrict__ s2, const float* __restrict__ s3,
    const float* __restrict__ s4, const float* __restrict__ s5,
    __half* __restrict__ h) {
    int i = blockIdx.x * 256 + threadIdx.x;
    const float* src;
    int base;
    if (i < 393216) {
        if (i < 294912) { src = s0; base = 0; }
        else            { src = s1; base = 294912; }
    } else if (i < 1179648) {
        if (i < 786432) { src = s2; base = 393216; }
        else            { src = s3; base = 786432; }
    } else {
        if (i < 1228800) { src = s4; base = 1179648; }
        else             { src = s5; base = 1228800; }
    }
    float4 v = ((const float4*)src)[i - base];
    __half2* hp = (__half2*)(h + (size_t)i * 4);
    hp[0] = __floats2half2_rn(v.x, v.y);
    hp[1] = __floats2half2_rn(v.z, v.w);
}

// ---------------- copy h_map->out + embed + entry LN ----------------
#define COPY_BLKS 8712
__global__ void __launch_bounds__(256) copyembed_k(const float* __restrict__ h_map,
                                                   float* __restrict__ out,
                                                   const int* __restrict__ idx,
                                                   float* __restrict__ hcv,
                                                   __half* __restrict__ cth,
                                                   float* __restrict__ x,
                                                   __half* __restrict__ lnh,
                                                   const float* __restrict__ gam,
                                                   const float* __restrict__ bet) {
    int warp = threadIdx.x >> 5;
    int lane = threadIdx.x & 31;
    if (blockIdx.x < COPY_BLKS) {
        int row = blockIdx.x * 8 + warp;
        const float4* s = (const float4*)(h_map + (size_t)row * DM) + lane;
        float4* d = (float4*)(out + (size_t)row * DM) + lane;
        d[0] = s[0];
        d[32] = s[32];
        return;
    }
    int tok = (blockIdx.x - COPY_BLKS) * 8 + warp;
    int b = tok >> 8, n = tok & 255;
    int p = idx[n];
    int yy = p / 33, xx = p % 33;
    const float* hp = h_map + ((size_t)b * WSQ + p) * DM;
    float v[8];
    float sum = 0.f, sq = 0.f;
#pragma unroll
    for (int i = 0; i < 8; i++) {
        int d = lane + 32 * i;
        float h = hp[d];
        hcv[((size_t)tok) * DM + d] = h;
        cth[((size_t)tok) * 512 + d] = __float2half_rn(h);
        float xv = h + pos2d_val(yy, xx, d);
        v[i] = xv;
        x[((size_t)(b * SQ + n)) * DM + d] = xv;
        sum += xv;
        sq += xv * xv;
    }
#pragma unroll
    for (int off = 16; off; off >>= 1) {
        sum += __shfl_xor_sync(0xffffffffu, sum, off);
        sq  += __shfl_xor_sync(0xffffffffu, sq, off);
    }
    float mu = sum * (1.0f / 256.0f);
    float var = sq * (1.0f / 256.0f) - mu * mu;
    float inv = rsqrtf(var + 1e-5f);
#pragma unroll
    for (int i = 0; i < 8; i++) {
        int d = lane + 32 * i;
        lnh[((size_t)(b * SQ + n)) * DM + d] =
            __float2half_rn((v[i] - mu) * inv * gam[d] + bet[d]);
    }
}

// ================= fused flash attention (fixed-offset softmax) =================
#define ATT_RS 80u
#define ATT_TEN (320u * ATT_RS)
#define ATT_SMEM (3u * ATT_TEN)

__global__ void __launch_bounds__(320) attn_fa_k(const __half* __restrict__ qkvh,
                                                 __half* __restrict__ oh) {
    extern __shared__ char sm[];
    const uint32_t smb = smem_u32(sm);
    const int b = blockIdx.x >> 3;
    const int h = blockIdx.x & 7;
    const int tid = threadIdx.x;
    const int l = tid & 31;
    const int w = tid >> 5;

#pragma unroll
    for (int j = 0; j < 12; j++) {
        int c = j * 320 + tid;
        int tz = c / 1280;
        int rem = c - tz * 1280;
        int r = rem >> 2;
        int ch = rem & 3;
        const __half* src = qkvh + (size_t)(b * SQ + r) * 768 + tz * 256 + h * 32 + ch * 8;
        cp16(smb + (uint32_t)tz * ATT_TEN + (uint32_t)r * ATT_RS + (uint32_t)ch * 16u, src);
    }
    asm volatile("cp.async.commit_group;" ::: "memory");
    asm volatile("cp.async.wait_group 0;" ::: "memory");
    __syncthreads();

    const uint32_t smQ = smb, smK = smb + ATT_TEN, smV = smb + 2 * ATT_TEN;
    const int q0 = w * 32;

    uint32_t aq[2][2][4];
#pragma unroll
    for (int mf = 0; mf < 2; mf++)
#pragma unroll
        for (int kc = 0; kc < 2; kc++) {
            uint32_t addr = smQ +
                (uint32_t)(q0 + mf * 16 + (l & 7) + ((l >> 3) & 1) * 8) * ATT_RS +
                (uint32_t)(kc * 2 + (l >> 4)) * 16u;
            ldsm4(aq[mf][kc], addr);
        }

    float lrow[2][2] = {{0.f, 0.f}, {0.f, 0.f}};
    float acc_o[2][4][4];
#pragma unroll
    for (int mf = 0; mf < 2; mf++)
#pragma unroll
        for (int db = 0; db < 4; db++)
#pragma unroll
            for (int q = 0; q < 4; q++) acc_o[mf][db][q] = 0.f;

    for (int ck = 0; ck < 320; ck += 64) {
        float s[2][8][4];
#pragma unroll
        for (int mf = 0; mf < 2; mf++)
#pragma unroll
            for (int nb = 0; nb < 8; nb++)
#pragma unroll
                for (int q = 0; q < 4; q++) s[mf][nb][q] = 0.f;

#pragma unroll
        for (int g = 0; g < 4; g++) {
#pragma unroll
            for (int ks = 0; ks < 2; ks++) {
                uint32_t bk[4];
                uint32_t addr = smK +
                    (uint32_t)(ck + g * 16 + ((l >> 4) << 3) + (l & 7)) * ATT_RS +
                    (uint32_t)(ks * 2 + ((l >> 3) & 1)) * 16u;
                ldsm4(bk, addr);
#pragma unroll
                for (int mf = 0; mf < 2; mf++) {
                    mma16816(s[mf][2 * g],     aq[mf][ks], bk);
                    mma16816(s[mf][2 * g + 1], aq[mf][ks], bk + 2);
                }
            }
        }

        uint32_t ap[2][4][4];
#pragma unroll
        for (int mf = 0; mf < 2; mf++) {
            float ls0 = 0.f, ls1 = 0.f;
#pragma unroll
            for (int nb = 0; nb < 8; nb++) {
                float p0 = __expf(s[mf][nb][0] - 4.0f);
                float p1 = __expf(s[mf][nb][1] - 4.0f);
                float p2 = __expf(s[mf][nb][2] - 4.0f);
                float p3 = __expf(s[mf][nb][3] - 4.0f);
                s[mf][nb][0] = p0; s[mf][nb][1] = p1;
                s[mf][nb][2] = p2; s[mf][nb][3] = p3;
                ls0 += p0 + p1;
                ls1 += p2 + p3;
            }
            ls0 += __shfl_xor_sync(0xffffffffu, ls0, 1);
            ls0 += __shfl_xor_sync(0xffffffffu, ls0, 2);
            ls1 += __shfl_xor_sync(0xffffffffu, ls1, 1);
            ls1 += __shfl_xor_sync(0xffffffffu, ls1, 2);
            lrow[mf][0] += ls0;
            lrow[mf][1] += ls1;
#pragma unroll
            for (int g = 0; g < 4; g++) {
                __half2 h0 = __floats2half2_rn(s[mf][2 * g][0],     s[mf][2 * g][1]);
                __half2 h1 = __floats2half2_rn(s[mf][2 * g][2],     s[mf][2 * g][3]);
                __half2 h2 = __floats2half2_rn(s[mf][2 * g + 1][0], s[mf][2 * g + 1][1]);
                __half2 h3 = __floats2half2_rn(s[mf][2 * g + 1][2], s[mf][2 * g + 1][3]);
                ap[mf][g][0] = *(uint32_t*)&h0;
                ap[mf][g][1] = *(uint32_t*)&h1;
                ap[mf][g][2] = *(uint32_t*)&h2;
                ap[mf][g][3] = *(uint32_t*)&h3;
            }
        }

#pragma unroll
        for (int g = 0; g < 4; g++) {
#pragma unroll
            for (int dd = 0; dd < 2; dd++) {
                uint32_t bv[4];
                uint32_t addr = smV +
                    (uint32_t)(ck + g * 16 + ((l >> 3) & 1) * 8 + (l & 7)) * ATT_RS +
                    (uint32_t)(dd * 2 + (l >> 4)) * 16u;
                ldsm4t(bv, addr);
#pragma unroll
                for (int mf = 0; mf < 2; mf++) {
                    mma16816(acc_o[mf][dd * 2],     ap[mf][g], bv);
                    mma16816(acc_o[mf][dd * 2 + 1], ap[mf][g], bv + 2);
                }
            }
        }
    }

#pragma unroll
    for (int mf = 0; mf < 2; mf++) {
#pragma unroll
        for (int hh = 0; hh < 2; hh++) {
            float inv = 1.f / lrow[mf][hh];
            int tok = q0 + mf * 16 + (l >> 2) + hh * 8;
            __half* op = oh + (size_t)(b * SQ + tok) * DM + h * 32 + 2 * (l & 3);
#pragma unroll
            for (int db = 0; db < 4; db++) {
                __half2 r = __floats2half2_rn(acc_o[mf][db][hh * 2] * inv,
                                              acc_o[mf][db][hh * 2 + 1] * inv);
                *(__half2*)(op + db * 8) = r;
            }
        }
    }
}

// ================= HMMA fp16 pipelined GEMM (128x128, 2 CTA/SM) =================
enum { EPL_GELU = 2, EPL_GATE = 4, EPL_QKVH = 5 };

#define STG_B 32768u
#define GSMEM_BYTES (3u * STG_B)

template <int MODE>
__device__ __forceinline__ void epi_store2(
    float* __restrict__ out, __half* __restrict__ outh,
    int N, int row, int col, float vx, float vy,
    const float* __restrict__ bias, const float* __restrict__ res,
    const float* __restrict__ extra, const int* __restrict__ idx) {
    float2 bb = *(const float2*)(bias + col);
    vx += bb.x;
    vy += bb.y;
    if (MODE == EPL_GELU) {
        *(__half2*)&outh[(size_t)row * N + col] =
            __floats2half2_rn(gelu_exact(vx), gelu_exact(vy));
    } else if (MODE == EPL_QKVH) {
        float sc = (col < 256) ? 0.17677669529663687f : 1.0f;
        *(__half2*)&outh[(size_t)row * N + col] = __floats2half2_rn(vx * sc, vy * sc);
    } else {  // EPL_GATE
        int b = row >> 8, n = row & 255;
        int p = idx[n];
        float2 hc = *(const float2*)&res[(size_t)row * DM + col];
        float2 hn = *(const float2*)&extra[((size_t)(b * SQ + n)) * DM + col];
        float g0 = 1.f / (1.f + expf(-vx));
        float g1 = 1.f / (1.f + expf(-vy));
        float2 r;
        r.x = hc.x + g0 * (hn.x - hc.x);
        r.y = hc.y + g1 * (hn.y - hc.y);
        *(float2*)&out[((size_t)b * WSQ + p) * DM + col] = r;
    }
}

template <int MODE>
__global__ void __launch_bounds__(256, 2) mma_gemm_k(
    const __half* __restrict__ Ah, const __half* __restrict__ Bh,
    const float* __restrict__ bias, float* __restrict__ out,
    __half* __restrict__ outh,
    int M, int N, int K,
    const float* __restrict__ res, const float* __restrict__ extra,
    const int* __restrict__ idx) {
    extern __shared__ char sm[];
    const uint32_t smb = smem_u32(sm);
    const int tid = threadIdx.x;
    const int lane = tid & 31;
    const int w = tid >> 5;
    const int wm = w >> 1;
    const int wn = w & 1;
    const int m0 = blockIdx.y * 128;
    const int n0 = blockIdx.x * 128;

    float acc[2][8][4];
#pragma unroll
    for (int i = 0; i < 2; i++)
#pragma unroll
        for (int j = 0; j < 8; j++)
#pragma unroll
            for (int q = 0; q < 4; q++) acc[i][j][q] = 0.f;

    const int nkt = K >> 6;

    const uint32_t crow0 = (uint32_t)(tid >> 3);
    const uint32_t ck8i = (uint32_t)(tid & 7);
    const uint32_t coff0 = crow0 * 128u + ((ck8i ^ (crow0 & 7)) << 4);
    const uint32_t asrc0 = (uint32_t)(m0 + (int)crow0) * (uint32_t)K + ck8i * 8u;
    const uint32_t bsrc0 = (uint32_t)(n0 + (int)crow0) * (uint32_t)K + ck8i * 8u;
    const uint32_t kst = 32u * (uint32_t)K;

#define ISSUE_STAGE(kt)                                                        \
    do {                                                                       \
        const uint32_t kk0 = (uint32_t)(kt) << 6;                              \
        const uint32_t sb = smb + (uint32_t)((kt) % 3) * STG_B;                \
        _Pragma("unroll") for (uint32_t j = 0; j < 4; j++) {                   \
            cp16(sb + coff0 + 4096u * j,           Ah + asrc0 + kk0 + kst * j);\
            cp16(sb + 16384u + coff0 + 4096u * j,  Bh + bsrc0 + kk0 + kst * j);\
        }                                                                      \
        asm volatile("cp.async.commit_group;" ::: "memory");                   \
    } while (0)

    ISSUE_STAGE(0);
    ISSUE_STAGE(1);

    const uint32_t rowAb[2] = {
        (uint32_t)(wm * 32 + 0  + (lane & 7) + ((lane >> 3) & 1) * 8) * 128u,
        (uint32_t)(wm * 32 + 16 + (lane & 7) + ((lane >> 3) & 1) * 8) * 128u};
    const int a_k8add = lane >> 4;
    uint32_t rowBb[4];
#pragma unroll
    for (int nfp = 0; nfp < 4; nfp++)
        rowBb[nfp] = (uint32_t)(wn * 64 + nfp * 16 + ((lane >> 4) << 3) + (lane & 7)) * 128u;
    const int b_k8add = (lane >> 3) & 1;
    const uint32_t swz = (uint32_t)(lane & 7);

    for (int kt = 0; kt < nkt; kt++) {
        if (kt + 1 < nkt) {
            asm volatile("cp.async.wait_group 1;" ::: "memory");
        } else {
            asm volatile("cp.async.wait_group 0;" ::: "memory");
        }
        __syncthreads();
        if (kt + 2 < nkt) ISSUE_STAGE(kt + 2);

        const uint32_t sb = smb + (uint32_t)(kt % 3) * STG_B;

        // hoist A fragments
        uint32_t ahh[4][2][4];
#pragma unroll
        for (int ks = 0; ks < 4; ks++)
#pragma unroll
            for (int mf = 0; mf < 2; mf++) {
                uint32_t off = rowAb[mf] +
                    ((((uint32_t)(ks * 2 + a_k8add)) ^ swz) << 4);
                ldsm4(ahh[ks][mf], sb + off);
            }

        // software-pipelined B fragments over flattened (ks,nfp)
        uint32_t bh[2][4];
        {
            uint32_t off0 = rowBb[0] + ((((uint32_t)b_k8add) ^ swz) << 4);
            ldsm4(bh[0], sb + 16384u + off0);
        }
#pragma unroll
        for (int it = 0; it < 16; it++) {
            const int ks = it >> 2, nfp = it & 3;
            if (it + 1 < 16) {
                const int ksn = (it + 1) >> 2, nfpn = (it + 1) & 3;
                uint32_t offn = rowBb[nfpn] +
                    ((((uint32_t)(ksn * 2 + b_k8add)) ^ swz) << 4);
                ldsm4(bh[(it + 1) & 1], sb + 16384u + offn);
            }
            uint32_t* bc = bh[it & 1];
            mma16816(acc[0][2 * nfp],     ahh[ks][0], bc);
            mma16816(acc[0][2 * nfp + 1], ahh[ks][0], bc + 2);
            mma16816(acc[1][2 * nfp],     ahh[ks][1], bc);
            mma16816(acc[1][2 * nfp + 1], ahh[ks][1], bc + 2);
        }
    }
#undef ISSUE_STAGE

#pragma unroll
    for (int mf = 0; mf < 2; mf++) {
        int row = m0 + wm * 32 + mf * 16 + (lane >> 2);
#pragma unroll
        for (int nf = 0; nf < 8; nf++) {
            int col = n0 + wn * 64 + nf * 8 + (lane & 3) * 2;
            epi_store2<MODE>(out, outh, N, row, col,
                             acc[mf][nf][0], acc[mf][nf][1], bias, res, extra, idx);
            epi_store2<MODE>(out, outh, N, row + 8, col,
                             acc[mf][nf][2], acc[mf][nf][3], bias, res, extra, idx);
        }
    }
}

// ======== fused GEMM(32x256) + bias + residual + LayerNorm ========
#define G32_A(st)  ((uint32_t)(st) * 4096u)
#define G32_B(st)  (8192u + (uint32_t)(st) * 32768u)
#define G32_GB     73728u
#define G32_ST     75776u
#define GSMEM32    77824u

template <bool FINAL>
__global__ void __launch_bounds__(256, 2) gemm32_resln_k(
    const __half* __restrict__ Ah, const __half* __restrict__ Bh,
    const float* __restrict__ bias,
    const float* res, float* xout, __half* __restrict__ lnh_out,
    int K, const float* __restrict__ gam, const float* __restrict__ bet) {
    extern __shared__ char sm[];
    const uint32_t smb = smem_u32(sm);
    const int tid = threadIdx.x;
    const int lane = tid & 31;
    const int w = tid >> 5;
    const int m0 = blockIdx.y * 32;

    float* gbuf = (float*)(sm + G32_GB);
    float2* stats = (float2*)(sm + G32_ST);
    gbuf[tid] = gam[tid];
    gbuf[256 + tid] = bet[tid];

    float acc[2][4][4];
#pragma unroll
    for (int i = 0; i < 2; i++)
#pragma unroll
        for (int j = 0; j < 4; j++)
#pragma unroll
            for (int q = 0; q < 4; q++) acc[i][j][q] = 0.f;

    const int nkt = K >> 6;

    const uint32_t crow0 = (uint32_t)(tid >> 3);
    const uint32_t ck8i = (uint32_t)(tid & 7);
    const uint32_t coff0 = crow0 * 128u + ((ck8i ^ (crow0 & 7)) << 4);
    const uint32_t asrc0 = (uint32_t)(m0 + (int)crow0) * (uint32_t)K + ck8i * 8u;
    const uint32_t bsrc0 = crow0 * (uint32_t)K + ck8i * 8u;
    const uint32_t kst = 32u * (uint32_t)K;

#define ISSUE32(kt)                                                            \
    do {                                                                       \
        const uint32_t kk0 = (uint32_t)(kt) << 6;                              \
        cp16(smb + G32_A((kt) & 1) + coff0, Ah + asrc0 + kk0);                 \
        const uint32_t sb = smb + G32_B((kt) & 1);                             \
        _Pragma("unroll") for (uint32_t j = 0; j < 8; j++)                     \
            cp16(sb + coff0 + 4096u * j, Bh + bsrc0 + kk0 + kst * j);          \
        asm volatile("cp.async.commit_group;" ::: "memory");                   \
    } while (0)

    ISSUE32(0);
    ISSUE32(1);

    const uint32_t rowAb[2] = {
        (uint32_t)(0  + (lane & 7) + ((lane >> 3) & 1) * 8) * 128u,
        (uint32_t)(16 + (lane & 7) + ((lane >> 3) & 1) * 8) * 128u};
    const int a_k8add = lane >> 4;
    uint32_t rowBb[2];
#pragma unroll
    for (int nfp = 0; nfp < 2; nfp++)
        rowBb[nfp] = (uint32_t)(w * 32 + nfp * 16 + ((lane >> 4) << 3) + (lane & 7)) * 128u;
    const int b_k8add = (lane >> 3) & 1;
    const uint32_t swz = (uint32_t)(lane & 7);

    for (int kt = 0; kt < nkt; kt++) {
        if (kt + 1 < nkt) {
            asm volatile("cp.async.wait_group 1;" ::: "memory");
        } else {
            asm volatile("cp.async.wait_group 0;" ::: "memory");
        }
        __syncthreads();

        const uint32_t sa = smb + G32_A(kt & 1);
        const uint32_t sb = smb + G32_B(kt & 1);

        uint32_t ahh[4][2][4];
#pragma unroll
        for (int ks = 0; ks < 4; ks++)
#pragma unroll
            for (int mf = 0; mf < 2; mf++) {
                uint32_t off = rowAb[mf] +
                    ((((uint32_t)(ks * 2 + a_k8add)) ^ swz) << 4);
                ldsm4(ahh[ks][mf], sa + off);
            }

        uint32_t bh[2][4];
        {
            uint32_t off0 = rowBb[0] + ((((uint32_t)b_k8add) ^ swz) << 4);
            ldsm4(bh[0], sb + off0);
        }
#pragma unroll
        for (int it = 0; it < 8; it++) {
            const int ks = it >> 1, nfp = it & 1;
            if (it + 1 < 8) {
                const int ksn = (it + 1) >> 1, nfpn = (it + 1) & 1;
                uint32_t offn = rowBb[nfpn] +
                    ((((uint32_t)(ksn * 2 + b_k8add)) ^ swz) << 4);
                ldsm4(bh[(it + 1) & 1], sb + offn);
            }
            uint32_t* bc = bh[it & 1];
            mma16816(acc[0][2 * nfp],     ahh[ks][0], bc);
            mma16816(acc[0][2 * nfp + 1], ahh[ks][0], bc + 2);
            mma16816(acc[1][2 * nfp],     ahh[ks][1], bc);
            mma16816(acc[1][2 * nfp + 1], ahh[ks][1], bc + 2);
        }
        __syncthreads();
        if (kt + 2 < nkt) ISSUE32(kt + 2);
    }
#undef ISSUE32

#pragma unroll
    for (int mf = 0; mf < 2; mf++) {
        const int lra = mf * 16 + (lane >> 2);
        const int r1 = m0 + lra;
        const int r2 = r1 + 8;
        float s1 = 0.f, q1 = 0.f, s2 = 0.f, q2 = 0.f;
#pragma unroll
        for (int nf = 0; nf < 4; nf++) {
            const int col = w * 32 + nf * 8 + (lane & 3) * 2;
            float2 bb = *(const float2*)&bias[col];
            float2 e1 = *(const float2*)&res[(size_t)r1 * DM + col];
            float2 e2 = *(const float2*)&res[(size_t)r2 * DM + col];
            acc[mf][nf][0] += bb.x + e1.x;
            acc[mf][nf][1] += bb.y + e1.y;
            acc[mf][nf][2] += bb.x + e2.x;
            acc[mf][nf][3] += bb.y + e2.y;
            s1 += acc[mf][nf][0] + acc[mf][nf][1];
            q1 += acc[mf][nf][0] * acc[mf][nf][0] + acc[mf][nf][1] * acc[mf][nf][1];
            s2 += acc[mf][nf][2] + acc[mf][nf][3];
            q2 += acc[mf][nf][2] * acc[mf][nf][2] + acc[mf][nf][3] * acc[mf][nf][3];
        }
        s1 += __shfl_xor_sync(0xffffffffu, s1, 1); q1 += __shfl_xor_sync(0xffffffffu, q1, 1);
        s1 += __shfl_xor_sync(0xffffffffu, s1, 2); q1 += __shfl_xor_sync(0xffffffffu, q1, 2);
        s2 += __shfl_xor_sync(0xffffffffu, s2, 1); q2 += __shfl_xor_sync(0xffffffffu, q2, 1);
        s2 += __shfl_xor_sync(0xffffffffu, s2, 2); q2 += __shfl_xor_sync(0xffffffffu, q2, 2);
        if ((lane & 3) == 0) {
            stats[lra * 8 + w] = make_float2(s1, q1);
            stats[(lra + 8) * 8 + w] = make_float2(s2, q2);
        }
    }
    __syncthreads();

#pragma unroll
    for (int mf = 0; mf < 2; mf++) {
        const int lra = mf * 16 + (lane >> 2);
        const int r1 = m0 + lra, r2 = r1 + 8;
        float su1 = 0.f, qu1 = 0.f, su2 = 0.f, qu2 = 0.f;
#pragma unroll
        for (int j = 0; j < 8; j++) {
            float2 p = stats[lra * 8 + j];
            su1 += p.x; qu1 += p.y;
            float2 r = stats[(lra + 8) * 8 + j];
            su2 += r.x; qu2 += r.y;
        }
        float mu1 = su1 * (1.0f / 256.0f);
        float iv1 = rsqrtf(qu1 * (1.0f / 256.0f) - mu1 * mu1 + 1e-5f);
        float mu2 = su2 * (1.0f / 256.0f);
        float iv2 = rsqrtf(qu2 * (1.0f / 256.0f) - mu2 * mu2 + 1e-5f);

        int b1 = 0, n1 = 0, b2 = 0, n2 = 0;
        if (FINAL) { b1 = r1 / SQ; n1 = r1 - b1 * SQ; b2 = r2 / SQ; n2 = r2 - b2 * SQ; }

#pragma unroll
        for (int nf = 0; nf < 4; nf++) {
            const int col = w * 32 + nf * 8 + (lane & 3) * 2;
            float g0 = gbuf[col], g1 = gbuf[col + 1];
            float be0 = gbuf[256 + col], be1 = gbuf[256 + col + 1];
            float l10 = (acc[mf][nf][0] - mu1) * iv1 * g0 + be0;
            float l11 = (acc[mf][nf][1] - mu1) * iv1 * g1 + be1;
            float l20 = (acc[mf][nf][2] - mu2) * iv2 * g0 + be0;
            float l21 = (acc[mf][nf][3] - mu2) * iv2 * g1 + be1;
            if (!FINAL) {
                *(float2*)&xout[(size_t)r1 * DM + col] =
                    make_float2(acc[mf][nf][0], acc[mf][nf][1]);
                *(float2*)&xout[(size_t)r2 * DM + col] =
                    make_float2(acc[mf][nf][2], acc[mf][nf][3]);
                *(__half2*)&lnh_out[(size_t)r1 * DM + col] = __floats2half2_rn(l10, l11);
                *(__half2*)&lnh_out[(size_t)r2 * DM + col] = __floats2half2_rn(l20, l21);
            } else {
                *(float2*)&xout[(size_t)r1 * DM + col] = make_float2(l10, l11);
                *(float2*)&xout[(size_t)r2 * DM + col] = make_float2(l20, l21);
                if (n1 < NCV)
                    *(__half2*)&lnh_out[((size_t)(b1 * NCV + n1)) * 512 + 256 + col] =
                        __floats2half2_rn(l10, l11);
                if (n2 < NCV)
                    *(__half2*)&lnh_out[((size_t)(b2 * NCV + n2)) * 512 + 256 + col] =
                        __floats2half2_rn(l20, l21);
            }
        }
    }
}

// ======== patch GEMM: on-the-fly im2col A + bias + pos + entry LN ========
#define PATCH_B_OFF 16384u
#define PATCH_GB_OFF 81920u
#define PATCH_ST_OFF 83968u
#define PATCH_SMEM 86016u

__global__ void __launch_bounds__(256, 2) patchgemm_k(
    const float* __restrict__ frame, const __half* __restrict__ Bh,
    const float* __restrict__ bias,
    float* __restrict__ xout, __half* __restrict__ lnh_out,
    const float* __restrict__ gam, const float* __restrict__ bet) {
    extern __shared__ char sm[];
    const uint32_t smb = smem_u32(sm);
    const int tid = threadIdx.x;
    const int lane = tid & 31;
    const int w = tid >> 5;
    const int wm = w >> 2;
    const int wn = w & 3;
    const int b = blockIdx.y;
    const int nkt = 12;

    float* gbuf = (float*)(sm + PATCH_GB_OFF);
    float2* stats = (float2*)(sm + PATCH_ST_OFF);
    gbuf[tid] = gam[tid];
    gbuf[256 + tid] = bet[tid];

    float acc[2][8][4];
#pragma unroll
    for (int i = 0; i < 2; i++)
#pragma unroll
        for (int j = 0; j < 8; j++)
#pragma unroll
            for (int q = 0; q < 4; q++) acc[i][j][q] = 0.f;

    uint32_t acoff[2];
    int at[2], ack8[2];
#pragma unroll
    for (int j = 0; j < 2; j++) {
        int c = tid + 256 * j;
        at[j] = c >> 3;
        ack8[j] = c & 7;
        acoff[j] = (uint32_t)at[j] * 128u + (uint32_t)((ack8[j] ^ (at[j] & 7)) << 4);
    }
    uint32_t bcoff[8], bsrc[8];
#pragma unroll
    for (int j = 0; j < 8; j++) {
        int c = tid + 256 * j;
        int crow = c >> 3, ck8 = c & 7;
        bcoff[j] = (uint32_t)crow * 128u + (uint32_t)((ck8 ^ (crow & 7)) << 4);
        bsrc[j] = (uint32_t)crow * 768u + (uint32_t)(ck8 * 8);
    }

    float areg[2][8];
#define LOAD_A(kt)                                                             \
    do {                                                                       \
        _Pragma("unroll") for (int j = 0; j < 2; j++) {                        \
            int k0 = ((kt) * 8 + ack8[j]) * 8;                                 \
            int cch = k0 >> 8, rem = k0 & 255;                                 \
            int rr = rem >> 4, qq = rem & 15;                                  \
            const float* fp = frame +                                          \
                (((size_t)(b * 3 + cch) * 128 + (at[j] >> 3) * 16 + rr) * 128  \
                 + (at[j] & 7) * 16 + qq);                                     \
            float4 v0 = *(const float4*)fp;                                    \
            float4 v1 = *(const float4*)(fp + 4);                              \
            areg[j][0] = v0.x; areg[j][1] = v0.y; areg[j][2] = v0.z;           \
            areg[j][3] = v0.w; areg[j][4] = v1.x; areg[j][5] = v1.y;           \
            areg[j][6] = v1.z; areg[j][7] = v1.w;                              \
        }                                                                      \
    } while (0)

#define STS_A(kt)                                                              \
    do {                                                                       \
        const uint32_t sa = (uint32_t)((kt) & 1) * 8192u;                      \
        _Pragma("unroll") for (int j = 0; j < 2; j++) {                        \
            __half2 h0 = __floats2half2_rn(areg[j][0], areg[j][1]);            \
            __half2 h1 = __floats2half2_rn(areg[j][2], areg[j][3]);            \
            __half2 h2 = __floats2half2_rn(areg[j][4], areg[j][5]);            \
            __half2 h3 = __floats2half2_rn(areg[j][6], areg[j][7]);            \
            uint4 pk = make_uint4(*(uint32_t*)&h0, *(uint32_t*)&h1,            \
                                  *(uint32_t*)&h2, *(uint32_t*)&h3);           \
            *(uint4*)(sm + sa + acoff[j]) = pk;                                \
        }                                                                      \
    } while (0)

#define ISSUE_B(kt)                                                            \
    do {                                                                       \
        const uint32_t kk0 = (uint32_t)(kt) << 6;                              \
        const uint32_t sb = smb + PATCH_B_OFF + (uint32_t)((kt) & 1) * 32768u; \
        _Pragma("unroll") for (int j = 0; j < 8; j++)                          \
            cp16(sb + bcoff[j], Bh + bsrc[j] + kk0);                           \
        asm volatile("cp.async.commit_group;" ::: "memory");                   \
    } while (0)

    LOAD_A(0);
    ISSUE_B(0);
    ISSUE_B(1);
    STS_A(0);

    const uint32_t rowAb[2] = {
        (uint32_t)(wm * 32 + 0  + (lane & 7) + ((lane >> 3) & 1) * 8) * 128u,
        (uint32_t)(wm * 32 + 16 + (lane & 7) + ((lane >> 3) & 1) * 8) * 128u};
    const int a_k8add = lane >> 4;
    uint32_t rowBb[4];
#pragma unroll
    for (int nfp = 0; nfp < 4; nfp++)
        rowBb[nfp] = (uint32_t)(wn * 64 + nfp * 16 + ((lane >> 4) << 3) + (lane & 7)) * 128u;
    const int b_k8add = (lane >> 3) & 1;
    const uint32_t swz = (uint32_t)(lane & 7);

    for (int kt = 0; kt < nkt; kt++) {
        if (kt + 1 < nkt) {
            asm volatile("cp.async.wait_group 1;" ::: "memory");
        } else {
            asm volatile("cp.async.wait_group 0;" ::: "memory");
        }
        __syncthreads();

        if (kt + 1 < nkt) LOAD_A(kt + 1);

        const uint32_t sa = smb + (uint32_t)(kt & 1) * 8192u;
        const uint32_t sb = smb + PATCH_B_OFF + (uint32_t)(kt & 1) * 32768u;
#pragma unroll
        for (int ks = 0; ks < 4; ks++) {
            uint32_t ah[2][4];
#pragma unroll
            for (int mf = 0; mf < 2; mf++) {
                uint32_t off = rowAb[mf] +
                    ((((uint32_t)(ks * 2 + a_k8add)) ^ swz) << 4);
                ldsm4(ah[mf], sa + off);
            }
#pragma unroll
            for (int nfp = 0; nfp < 4; nfp++) {
                uint32_t off = rowBb[nfp] +
                    ((((uint32_t)(ks * 2 + b_k8add)) ^ swz) << 4);
                uint32_t bh[4];
                ldsm4(bh, sb + off);
#pragma unroll
                for (int mf = 0; mf < 2; mf++) {
                    mma16816(acc[mf][2 * nfp],     ah[mf], bh);
                    mma16816(acc[mf][2 * nfp + 1], ah[mf], bh + 2);
                }
            }
        }
        __syncthreads();
        if (kt + 1 < nkt) STS_A(kt + 1);
        if (kt + 2 < nkt) ISSUE_B(kt + 2);
    }
#undef LOAD_A
#undef STS_A
#undef ISSUE_B

#pragma unroll
    for (int mf = 0; mf < 2; mf++) {
        const int lra = wm * 32 + mf * 16 + (lane >> 2);
        const int t1 = lra, t2 = lra + 8;
        float s1 = 0.f, q1 = 0.f, s2 = 0.f, q2 = 0.f;
#pragma unroll
        for (int nf = 0; nf < 8; nf++) {
            const int col = wn * 64 + nf * 8 + (lane & 3) * 2;
            float2 bb = *(const float2*)&bias[col];
            acc[mf][nf][0] += bb.x + pos2d_val(t1 >> 3, t1 & 7, col);
            acc[mf][nf][1] += bb.y + pos2d_val(t1 >> 3, t1 & 7, col + 1);
            acc[mf][nf][2] += bb.x + pos2d_val(t2 >> 3, t2 & 7, col);
            acc[mf][nf][3] += bb.y + pos2d_val(t2 >> 3, t2 & 7, col + 1);
            s1 += acc[mf][nf][0] + acc[mf][nf][1];
            q1 += acc[mf][nf][0] * acc[mf][nf][0] + acc[mf][nf][1] * acc[mf][nf][1];
            s2 += acc[mf][nf][2] + acc[mf][nf][3];
            q2 += acc[mf][nf][2] * acc[mf][nf][2] + acc[mf][nf][3] * acc[mf][nf][3];
        }
        s1 += __shfl_xor_sync(0xffffffffu, s1, 1); q1 += __shfl_xor_sync(0xffffffffu, q1, 1);
        s1 += __shfl_xor_sync(0xffffffffu, s1, 2); q1 += __shfl_xor_sync(0xffffffffu, q1, 2);
        s2 += __shfl_xor_sync(0xffffffffu, s2, 1); q2 += __shfl_xor_sync(0xffffffffu, q2, 1);
        s2 += __shfl_xor_sync(0xffffffffu, s2, 2); q2 += __shfl_xor_sync(0xffffffffu, q2, 2);
        if ((lane & 3) == 0) {
            stats[lra * 4 + wn] = make_float2(s1, q1);
            stats[(lra + 8) * 4 + wn] = make_float2(s2, q2);
        }
    }
    __syncthreads();

#pragma unroll
    for (int mf = 0; mf < 2; mf++) {
        const int lra = wm * 32 + mf * 16 + (lane >> 2);
        const int t1 = lra, t2 = lra + 8;
        const int r1 = b * SQ + NCV + t1;
        const int r2 = b * SQ + NCV + t2;
        float2 a0 = stats[lra * 4 + 0], a1 = stats[lra * 4 + 1];
        float2 a2 = stats[lra * 4 + 2], a3 = stats[lra * 4 + 3];
        float mu1 = (a0.x + a1.x + a2.x + a3.x) * (1.0f / 256.0f);
        float iv1 = rsqrtf((a0.y + a1.y + a2.y + a3.y) * (1.0f / 256.0f) - mu1 * mu1 + 1e-5f);
        float2 c0 = stats[(lra + 8) * 4 + 0], c1 = stats[(lra + 8) * 4 + 1];
        float2 c2 = stats[(lra + 8) * 4 + 2], c3 = stats[(lra + 8) * 4 + 3];
        float mu2 = (c0.x + c1.x + c2.x + c3.x) * (1.0f / 256.0f);
        float iv2 = rsqrtf((c0.y + c1.y + c2.y + c3.y) * (1.0f / 256.0f) - mu2 * mu2 + 1e-5f);

#pragma unroll
        for (int nf = 0; nf < 8; nf++) {
            const int col = wn * 64 + nf * 8 + (lane & 3) * 2;
            float g0 = gbuf[col], g1 = gbuf[col + 1];
            float be0 = gbuf[256 + col], be1 = gbuf[256 + col + 1];
            *(float2*)&xout[(size_t)r1 * DM + col] =
                make_float2(acc[mf][nf][0], acc[mf][nf][1]);
            *(float2*)&xout[(size_t)r2 * DM + col] =
                make_float2(acc[mf][nf][2], acc[mf][nf][3]);
            *(__half2*)&lnh_out[(size_t)r1 * DM + col] = __floats2half2_rn(
                (acc[mf][nf][0] - mu1) * iv1 * g0 + be0,
                (acc[mf][nf][1] - mu1) * iv1 * g1 + be1);
            *(__half2*)&lnh_out[(size_t)r2 * DM + col] = __floats2half2_rn(
                (acc[mf][nf][2] - mu2) * iv2 * g0 + be0,
                (acc[mf][nf][3] - mu2) * iv2 * g1 + be1);
        }
    }
}

// ---------------- host launcher ----------------
extern "C" void kernel_launch(void* const* d_in, const int* in_sizes, int n_in,
                              void* d_out, int out_size) {
    const float* h_map   = (const float*)d_in[0];
    const float* frame   = (const float*)d_in[1];
    const int*   idx     = (const int*)  d_in[2];
    const float* Wqkv    = (const float*)d_in[3];
    const float* bqkv    = (const float*)d_in[4];
    const float* Wo      = (const float*)d_in[5];
    const float* bo      = (const float*)d_in[6];
    const float* ln1g    = (const float*)d_in[7];
    const float* ln1b    = (const float*)d_in[8];
    const float* W1      = (const float*)d_in[9];
    const float* b1      = (const float*)d_in[10];
    const float* W2      = (const float*)d_in[11];
    const float* b2      = (const float*)d_in[12];
    const float* ln2g    = (const float*)d_in[13];
    const float* ln2b    = (const float*)d_in[14];
    const float* nfg     = (const float*)d_in[15];
    const float* nfb     = (const float*)d_in[16];
    const float* patch_w = (const float*)d_in[17];
    const float* patch_b = (const float*)d_in[18];
    const float* gate_w  = (const float*)d_in[19];
    const float* gate_b  = (const float*)d_in[20];
    float* out = (float*)d_out;

    float *x, *ln, *hcv;
    __half *lnh, *qkvh, *ath, *h1h, *cth, *wh;
    cudaGetSymbolAddress((void**)&x, g_x);
    cudaGetSymbolAddress((void**)&ln, g_ln);
    cudaGetSymbolAddress((void**)&hcv, g_hcv);
    cudaGetSymbolAddress((void**)&lnh, g_lnh);
    cudaGetSymbolAddress((void**)&qkvh, g_qkvh);
    cudaGetSymbolAddress((void**)&ath, g_ath);
    cudaGetSymbolAddress((void**)&h1h, g_h1h);
    cudaGetSymbolAddress((void**)&cth, g_cth);
    cudaGetSymbolAddress((void**)&wh, g_wh);

    cudaFuncSetAttribute(mma_gemm_k<EPL_GELU>,   cudaFuncAttributeMaxDynamicSharedMemorySize, GSMEM_BYTES);
    cudaFuncSetAttribute(mma_gemm_k<EPL_GATE>,   cudaFuncAttributeMaxDynamicSharedMemorySize, GSMEM_BYTES);
    cudaFuncSetAttribute(mma_gemm_k<EPL_QKVH>,   cudaFuncAttributeMaxDynamicSharedMemorySize, GSMEM_BYTES);
    cudaFuncSetAttribute(gemm32_resln_k<false>,  cudaFuncAttributeMaxDynamicSharedMemorySize, GSMEM32);
    cudaFuncSetAttribute(gemm32_resln_k<true>,   cudaFuncAttributeMaxDynamicSharedMemorySize, GSMEM32);
    cudaFuncSetAttribute(patchgemm_k, cudaFuncAttributeMaxDynamicSharedMemorySize, PATCH_SMEM);
    cudaFuncSetAttribute(attn_fa_k, cudaFuncAttributeMaxDynamicSharedMemorySize, ATT_SMEM);

    wcvt_all_k<<<1261568 / 256, 256>>>(Wqkv, Wo, W1, W2, patch_w, gate_w, wh);
    copyembed_k<<<COPY_BLKS + 2048, 256>>>(h_map, out, idx, hcv, cth, x, lnh, ln1g, ln1b);
    patchgemm_k<<<dim3(1, 64), 256, PATCH_SMEM>>>(
        frame, wh + WOFF_PW, patch_b, x, lnh, ln1g, ln1b);

    const int NTOK = BB * SQ;  // 20480
    for (int l = 0; l < NDEPTH; l++) {
        mma_gemm_k<EPL_QKVH><<<dim3(6, 160), 256, GSMEM_BYTES>>>(
            lnh, wh + WOFF_QKV + (size_t)l * 196608,
            bqkv + l * 768, nullptr, qkvh,
            NTOK, 768, 256, nullptr, nullptr, nullptr);
        attn_fa_k<<<BB * NHEADS, 320, ATT_SMEM>>>(qkvh, ath);
        gemm32_resln_k<false><<<dim3(1, NTOK / 32), 256, GSMEM32>>>(
            ath, wh + WOFF_WO + (size_t)l * 65536, bo + l * 256,
            x, x, lnh, 256, ln2g + l * 256, ln2b + l * 256);
        mma_gemm_k<EPL_GELU><<<dim3(8, 160), 256, GSMEM_BYTES>>>(
            lnh, wh + WOFF_W1 + (size_t)l * 262144,
            b1 + l * 1024, nullptr, h1h,
            NTOK, 1024, 256, nullptr, nullptr, nullptr);
        if (l + 1 < NDEPTH) {
            gemm32_resln_k<false><<<dim3(1, NTOK / 32), 256, GSMEM32>>>(
                h1h, wh + WOFF_W2 + (size_t)l * 262144, b2 + l * 256,
                x, x, lnh, 1024, ln1g + (l + 1) * 256, ln1b + (l + 1) * 256);
        } else {
            gemm32_resln_k<true><<<dim3(1, NTOK / 32), 256, GSMEM32>>>(
                h1h, wh + WOFF_W2 + (size_t)l * 262144, b2 + l * 256,
                x, ln, cth, 1024, nfg, nfb);
        }
    }

    mma_gemm_k<EPL_GATE><<<dim3(2, 128), 256, GSMEM_BYTES>>>(
        cth, wh + WOFF_GW, gate_b, out, nullptr,
        16384, 256, 512, hcv, ln, idx);
}